// round 1
// baseline (speedup 1.0000x reference)
#include <cuda_runtime.h>
#include <math.h>

// Problem constants
#define AN 50000
#define PN 100000
#define DIN 128
#define HD 256
#define CN 40
#define EN 300000

// ---------------------------------------------------------------------------
// Scratch (static __device__ arrays: allocation-free per harness rules)
// ---------------------------------------------------------------------------
__device__ float g_ha[(size_t)AN * HD];    // author hidden state
__device__ float g_hp[(size_t)PN * HD];    // paper hidden state
__device__ float g_agg[(size_t)PN * HD];   // aggregation buffer (reused)
__device__ float g_ta[(size_t)AN * HD];    // author conv output / proj hidden
__device__ float g_tp[(size_t)PN * HD];    // paper conv output / proj hidden
__device__ float g_ws01[HD * HD];          // combined W_self[l,0]+W_self[l,1]
__device__ float g_b01[HD];                // combined bias
__device__ int   g_deg[3 * PN];
__device__ int   g_off[3 * (PN + 1)];
__device__ int   g_cur[3 * PN];
__device__ int   g_perm[3 * EN];

// ---------------------------------------------------------------------------
// Utility
// ---------------------------------------------------------------------------
__device__ __forceinline__ float warp_sum(float v) {
#pragma unroll
    for (int o = 16; o; o >>= 1) v += __shfl_xor_sync(0xffffffffu, v, o);
    return v;
}
__device__ __forceinline__ float warp_max(float v) {
#pragma unroll
    for (int o = 16; o; o >>= 1) v = fmaxf(v, __shfl_xor_sync(0xffffffffu, v, o));
    return v;
}

// ---------------------------------------------------------------------------
// CSR construction kernels (edges are launch-invariant; built once per launch)
// ---------------------------------------------------------------------------
__global__ void k_zero_int(int* __restrict__ p, int n) {
    int i = blockIdx.x * blockDim.x + threadIdx.x;
    if (i < n) p[i] = 0;
}

__global__ void k_hist(const int* __restrict__ dst, int* __restrict__ deg, int n) {
    int i = blockIdx.x * blockDim.x + threadIdx.x;
    if (i < n) atomicAdd(&deg[dst[i]], 1);
}

// single-block exclusive scan: 1024 threads, chunked serial + Hillis-Steele
__global__ void k_scan(const int* __restrict__ deg, int* __restrict__ off, int n) {
    __shared__ int part[1024];
    int tid = threadIdx.x;
    int chunk = (n + 1023) >> 10;
    int s = tid * chunk;
    int e = min(s + chunk, n);
    int sum = 0;
    for (int i = s; i < e; ++i) sum += deg[i];
    part[tid] = sum;
    __syncthreads();
#pragma unroll
    for (int d = 1; d < 1024; d <<= 1) {
        int v = (tid >= d) ? part[tid - d] : 0;
        __syncthreads();
        part[tid] += v;
        __syncthreads();
    }
    int run = (tid == 0) ? 0 : part[tid - 1];
    for (int i = s; i < e; ++i) { off[i] = run; run += deg[i]; }
    if (tid == 0) off[n] = part[1023];
}

__global__ void k_copy_int(const int* __restrict__ a, int* __restrict__ b, int n) {
    int i = blockIdx.x * blockDim.x + threadIdx.x;
    if (i < n) b[i] = a[i];
}

__global__ void k_fill(const int* __restrict__ src, const int* __restrict__ dst,
                       int* __restrict__ cur, int* __restrict__ perm, int n) {
    int i = blockIdx.x * blockDim.x + threadIdx.x;
    if (i < n) {
        int slot = atomicAdd(&cur[dst[i]], 1);
        perm[slot] = src[i];
    }
}

// ---------------------------------------------------------------------------
// Mean aggregation: one warp per destination row, gather over CSR bucket.
// Each edge reads a full contiguous 1KB feature row (coalesced float4s).
// ---------------------------------------------------------------------------
__global__ void k_agg(const float* __restrict__ h, const int* __restrict__ off,
                      const int* __restrict__ perm, float* __restrict__ out, int ndst) {
    int w = (blockIdx.x * blockDim.x + threadIdx.x) >> 5;
    int lane = threadIdx.x & 31;
    if (w >= ndst) return;
    int s = off[w], e = off[w + 1];
    float4 a0 = make_float4(0.f, 0.f, 0.f, 0.f);
    float4 a1 = make_float4(0.f, 0.f, 0.f, 0.f);
    for (int i = s; i < e; ++i) {
        const float4* r = (const float4*)(h + (size_t)perm[i] * HD);
        float4 v0 = __ldg(&r[lane]);
        float4 v1 = __ldg(&r[lane + 32]);
        a0.x += v0.x; a0.y += v0.y; a0.z += v0.z; a0.w += v0.w;
        a1.x += v1.x; a1.y += v1.y; a1.z += v1.z; a1.w += v1.w;
    }
    float inv = (e > s) ? 1.f / (float)(e - s) : 0.f;
    a0.x *= inv; a0.y *= inv; a0.z *= inv; a0.w *= inv;
    a1.x *= inv; a1.y *= inv; a1.z *= inv; a1.w *= inv;
    float4* o = (float4*)(out + (size_t)w * HD);
    o[lane] = a0;
    o[lane + 32] = a1;
}

// ---------------------------------------------------------------------------
// SGEMM: C[M,N] = A[M,K] @ B[K,N] (+bias) (+=C if accum) (relu optional)
// 128x64 tile, BK=16, 256 threads, 8x4 per thread. K % 16 == 0, N % 4 == 0.
// ---------------------------------------------------------------------------
#define BM 128
#define BN 64
#define BK 16
#define TM 8
#define TN 4

__global__ __launch_bounds__(256) void k_sgemm(
    const float* __restrict__ A, const float* __restrict__ B,
    const float* __restrict__ bias, float* __restrict__ C,
    int M, int N, int K, int accum, int relu) {
    __shared__ float As[BK][BM];  // transposed A tile
    __shared__ float Bs[BK][BN];

    const int tid = threadIdx.x;
    const int tx = tid & 15;   // N direction
    const int ty = tid >> 4;   // M direction
    const int bm = blockIdx.y * BM;
    const int bn = blockIdx.x * BN;

    float acc[TM][TN];
#pragma unroll
    for (int i = 0; i < TM; ++i)
#pragma unroll
        for (int j = 0; j < TN; ++j) acc[i][j] = 0.f;

    const int ar = tid >> 2;           // A tile row   (0..63, +64 second half)
    const int ac = (tid & 3) << 2;     // A tile col4  (0,4,8,12)
    const int br = tid >> 4;           // B tile row   (0..15)
    const int bc = (tid & 15) << 2;    // B tile col4  (0..60)

    for (int k0 = 0; k0 < K; k0 += BK) {
#pragma unroll
        for (int h = 0; h < 2; ++h) {
            int r = ar + h * 64;
            int gr = bm + r;
            float4 v = make_float4(0.f, 0.f, 0.f, 0.f);
            if (gr < M) v = *(const float4*)(A + (size_t)gr * K + k0 + ac);
            As[ac + 0][r] = v.x;
            As[ac + 1][r] = v.y;
            As[ac + 2][r] = v.z;
            As[ac + 3][r] = v.w;
        }
        {
            int gc = bn + bc;
            float4 v = make_float4(0.f, 0.f, 0.f, 0.f);
            if (gc < N) v = *(const float4*)(B + (size_t)(k0 + br) * N + gc);
            *(float4*)&Bs[br][bc] = v;
        }
        __syncthreads();
#pragma unroll
        for (int kk = 0; kk < BK; ++kk) {
            float aF[TM], bF[TN];
#pragma unroll
            for (int i = 0; i < TM; ++i) aF[i] = As[kk][ty * TM + i];
#pragma unroll
            for (int j = 0; j < TN; ++j) bF[j] = Bs[kk][tx * TN + j];
#pragma unroll
            for (int i = 0; i < TM; ++i)
#pragma unroll
                for (int j = 0; j < TN; ++j)
                    acc[i][j] = fmaf(aF[i], bF[j], acc[i][j]);
        }
        __syncthreads();
    }

    const int col = bn + tx * TN;
    if (col < N) {  // N % 4 == 0, so full float4 in-bounds when col < N
        float4 bv = make_float4(0.f, 0.f, 0.f, 0.f);
        if (bias) bv = *(const float4*)(bias + col);
#pragma unroll
        for (int i = 0; i < TM; ++i) {
            int row = bm + ty * TM + i;
            if (row >= M) continue;
            float* cp = C + (size_t)row * N + col;
            float4 v = make_float4(acc[i][0] + bv.x, acc[i][1] + bv.y,
                                   acc[i][2] + bv.z, acc[i][3] + bv.w);
            if (accum) {
                float4 o = *(const float4*)cp;
                v.x += o.x; v.y += o.y; v.z += o.z; v.w += o.w;
            }
            if (relu) {
                v.x = fmaxf(v.x, 0.f); v.y = fmaxf(v.y, 0.f);
                v.z = fmaxf(v.z, 0.f); v.w = fmaxf(v.w, 0.f);
            }
            *(float4*)cp = v;
        }
    }
}

// ---------------------------------------------------------------------------
// Fused relu + residual + LayerNorm, in-place into h. One warp per row (H=256).
// ---------------------------------------------------------------------------
__global__ void k_ln(const float* __restrict__ t, float* __restrict__ h,
                     const float* __restrict__ g, const float* __restrict__ b,
                     int rows) {
    int w = (blockIdx.x * blockDim.x + threadIdx.x) >> 5;
    int lane = threadIdx.x & 31;
    if (w >= rows) return;
    const float4* t4 = (const float4*)(t + (size_t)w * HD);
    float4* h4 = (float4*)(h + (size_t)w * HD);
    float4 x0 = t4[lane], x1 = t4[lane + 32];
    float4 p0 = h4[lane], p1 = h4[lane + 32];
    float u[8];
    u[0] = fmaxf(x0.x, 0.f) + p0.x; u[1] = fmaxf(x0.y, 0.f) + p0.y;
    u[2] = fmaxf(x0.z, 0.f) + p0.z; u[3] = fmaxf(x0.w, 0.f) + p0.w;
    u[4] = fmaxf(x1.x, 0.f) + p1.x; u[5] = fmaxf(x1.y, 0.f) + p1.y;
    u[6] = fmaxf(x1.z, 0.f) + p1.z; u[7] = fmaxf(x1.w, 0.f) + p1.w;
    float s = 0.f;
#pragma unroll
    for (int i = 0; i < 8; ++i) s += u[i];
    s = warp_sum(s);
    float mu = s * (1.f / HD);
    float v = 0.f;
#pragma unroll
    for (int i = 0; i < 8; ++i) { float d = u[i] - mu; v += d * d; }
    v = warp_sum(v);
    float rstd = rsqrtf(v * (1.f / HD) + 1e-5f);
    const float4* g4 = (const float4*)g;
    const float4* b4 = (const float4*)b;
    float4 ga = g4[lane], gb = g4[lane + 32];
    float4 ba = b4[lane], bb = b4[lane + 32];
    float4 o0, o1;
    o0.x = (u[0] - mu) * rstd * ga.x + ba.x;
    o0.y = (u[1] - mu) * rstd * ga.y + ba.y;
    o0.z = (u[2] - mu) * rstd * ga.z + ba.z;
    o0.w = (u[3] - mu) * rstd * ga.w + ba.w;
    o1.x = (u[4] - mu) * rstd * gb.x + bb.x;
    o1.y = (u[5] - mu) * rstd * gb.y + bb.y;
    o1.z = (u[6] - mu) * rstd * gb.z + bb.z;
    o1.w = (u[7] - mu) * rstd * gb.w + bb.w;
    h4[lane] = o0;
    h4[lane + 32] = o1;
}

// ---------------------------------------------------------------------------
// log_softmax over CN=40 classes, in-place, one warp per row
// ---------------------------------------------------------------------------
__global__ void k_lsm(float* __restrict__ x, int rows) {
    int w = (blockIdx.x * blockDim.x + threadIdx.x) >> 5;
    int lane = threadIdx.x & 31;
    if (w >= rows) return;
    float* r = x + (size_t)w * CN;
    float v0 = r[lane];                       // lane < 32 < 40 always valid
    bool has1 = (lane + 32) < CN;
    float v1 = has1 ? r[lane + 32] : -3.4e38f;
    float m = warp_max(fmaxf(v0, v1));
    float s = expf(v0 - m) + (has1 ? expf(v1 - m) : 0.f);
    s = warp_sum(s);
    float lse = m + logf(s);
    r[lane] = v0 - lse;
    if (has1) r[lane + 32] = v1 - lse;
}

// ---------------------------------------------------------------------------
// combine W_self[l,0] + W_self[l,1] and biases (saves one 100k GEMM per layer)
// ---------------------------------------------------------------------------
__global__ void k_combine(const float* __restrict__ w0, const float* __restrict__ w1,
                          float* __restrict__ wo, const float* __restrict__ b0,
                          const float* __restrict__ b1, float* __restrict__ bo) {
    int i = blockIdx.x * blockDim.x + threadIdx.x;
    if (i < HD * HD) wo[i] = w0[i] + w1[i];
    if (i < HD) bo[i] = b0[i] + b1[i];
}

// ---------------------------------------------------------------------------
// Host launcher
// ---------------------------------------------------------------------------
static inline void gemm(const float* A, const float* B, const float* bias,
                        float* C, int M, int N, int K, int accum, int relu) {
    dim3 grid((N + BN - 1) / BN, (M + BM - 1) / BM);
    k_sgemm<<<grid, 256>>>(A, B, bias, C, M, N, K, accum, relu);
}

extern "C" void kernel_launch(void* const* d_in, const int* in_sizes, int n_in,
                              void* d_out, int out_size) {
    const float* x_author     = (const float*)d_in[0];
    const float* x_paper      = (const float*)d_in[1];
    const int*   e0_src       = (const int*)d_in[2];
    const int*   e0_dst       = (const int*)d_in[3];
    const int*   e1_src       = (const int*)d_in[4];
    const int*   e1_dst       = (const int*)d_in[5];
    const int*   e2_src       = (const int*)d_in[6];
    const int*   e2_dst       = (const int*)d_in[7];
    const float* emb_W_author = (const float*)d_in[8];
    const float* emb_b_author = (const float*)d_in[9];
    const float* emb_W_paper  = (const float*)d_in[10];
    const float* emb_b_paper  = (const float*)d_in[11];
    const float* W_self       = (const float*)d_in[12];
    const float* W_neigh      = (const float*)d_in[13];
    const float* b_conv       = (const float*)d_in[14];
    const float* ln_g_author  = (const float*)d_in[15];
    const float* ln_b_author  = (const float*)d_in[16];
    const float* ln_g_paper   = (const float*)d_in[17];
    const float* ln_b_paper   = (const float*)d_in[18];
    const float* pW1_author   = (const float*)d_in[19];
    const float* pb1_author   = (const float*)d_in[20];
    const float* pW2_author   = (const float*)d_in[21];
    const float* pb2_author   = (const float*)d_in[22];
    const float* pW1_paper    = (const float*)d_in[23];
    const float* pb1_paper    = (const float*)d_in[24];
    const float* pW2_paper    = (const float*)d_in[25];
    const float* pb2_paper    = (const float*)d_in[26];

    float *p_ha, *p_hp, *p_agg, *p_ta, *p_tp, *p_ws01, *p_b01;
    int *p_deg, *p_off, *p_cur, *p_perm;
    cudaGetSymbolAddress((void**)&p_ha, g_ha);
    cudaGetSymbolAddress((void**)&p_hp, g_hp);
    cudaGetSymbolAddress((void**)&p_agg, g_agg);
    cudaGetSymbolAddress((void**)&p_ta, g_ta);
    cudaGetSymbolAddress((void**)&p_tp, g_tp);
    cudaGetSymbolAddress((void**)&p_ws01, g_ws01);
    cudaGetSymbolAddress((void**)&p_b01, g_b01);
    cudaGetSymbolAddress((void**)&p_deg, g_deg);
    cudaGetSymbolAddress((void**)&p_off, g_off);
    cudaGetSymbolAddress((void**)&p_cur, g_cur);
    cudaGetSymbolAddress((void**)&p_perm, g_perm);

    // ---- CSR build for the 3 edge types (reused across both layers) ----
    const int* srcs[3] = {e0_src, e1_src, e2_src};
    const int* dsts[3] = {e0_dst, e1_dst, e2_dst};
    const int ndsts[3] = {PN, PN, AN};
    const int EB = (EN + 255) / 256;
    for (int t = 0; t < 3; ++t) {
        int* deg = p_deg + t * PN;
        int* off = p_off + t * (PN + 1);
        int* cur = p_cur + t * PN;
        int* perm = p_perm + t * EN;
        int nd = ndsts[t];
        int NB = (nd + 255) / 256;
        k_zero_int<<<NB, 256>>>(deg, nd);
        k_hist<<<EB, 256>>>(dsts[t], deg, EN);
        k_scan<<<1, 1024>>>(deg, off, nd);
        k_copy_int<<<NB, 256>>>(off, cur, nd);
        k_fill<<<EB, 256>>>(srcs[t], dsts[t], cur, perm, EN);
    }

    // ---- input embeddings ----
    gemm(x_author, emb_W_author, emb_b_author, p_ha, AN, HD, DIN, 0, 0);
    gemm(x_paper, emb_W_paper, emb_b_paper, p_hp, PN, HD, DIN, 0, 0);

    // ---- 2 SAGE layers ----
    const int AGG_BLK = 128;  // 4 warps -> 4 dst rows per block
    for (int l = 0; l < 2; ++l) {
        const float* Ws = W_self + (size_t)l * 3 * HD * HD;
        const float* Wn = W_neigh + (size_t)l * 3 * HD * HD;
        const float* bc = b_conv + (size_t)l * 3 * HD;

        k_combine<<<(HD * HD + 255) / 256, 256>>>(Ws, Ws + HD * HD, p_ws01,
                                                  bc, bc + HD, p_b01);

        // paper output: hp@(Ws0+Ws1) + agg0@Wn0 + agg1@Wn1 + (b0+b1)
        gemm(p_hp, p_ws01, p_b01, p_tp, PN, HD, HD, 0, 0);
        k_agg<<<(PN * 32 + AGG_BLK - 1) / AGG_BLK, AGG_BLK>>>(
            p_ha, p_off + 0 * (PN + 1), p_perm + 0 * EN, p_agg, PN);
        gemm(p_agg, Wn, nullptr, p_tp, PN, HD, HD, 1, 0);
        k_agg<<<(PN * 32 + AGG_BLK - 1) / AGG_BLK, AGG_BLK>>>(
            p_hp, p_off + 1 * (PN + 1), p_perm + 1 * EN, p_agg, PN);
        gemm(p_agg, Wn + HD * HD, nullptr, p_tp, PN, HD, HD, 1, 0);

        // author output: ha@Ws2 + agg2@Wn2 + b2
        gemm(p_ha, Ws + 2 * HD * HD, bc + 2 * HD, p_ta, AN, HD, HD, 0, 0);
        k_agg<<<(AN * 32 + AGG_BLK - 1) / AGG_BLK, AGG_BLK>>>(
            p_hp, p_off + 2 * (PN + 1), p_perm + 2 * EN, p_agg, AN);
        gemm(p_agg, Wn + 2 * HD * HD, nullptr, p_ta, AN, HD, HD, 1, 0);

        // fused relu + residual + LayerNorm (in-place into h)
        k_ln<<<(AN * 32 + 127) / 128, 128>>>(p_ta, p_ha, ln_g_author, ln_b_author, AN);
        k_ln<<<(PN * 32 + 127) / 128, 128>>>(p_tp, p_hp, ln_g_paper, ln_b_paper, PN);
    }

    // ---- output heads ----
    float* out = (float*)d_out;
    // author: relu(ha@pW1+b1)@pW2+b2 -> log_softmax, rows of 40
    gemm(p_ha, pW1_author, pb1_author, p_ta, AN, HD, HD, 0, 1);
    gemm(p_ta, pW2_author, pb2_author, out, AN, CN, HD, 0, 0);
    k_lsm<<<(AN * 32 + 127) / 128, 128>>>(out, AN);
    // paper: relu(hp@pW1+b1)@pW2+b2, rows of 256
    gemm(p_hp, pW1_paper, pb1_paper, p_tp, PN, HD, HD, 0, 1);
    gemm(p_tp, pW2_paper, pb2_paper, out + (size_t)AN * CN, PN, HD, HD, 0, 0);
}

// round 2
// speedup vs baseline: 1.0003x; 1.0003x over previous
#include <cuda_runtime.h>
#include <math.h>

// Problem constants
#define AN 50000
#define PN 100000
#define DIN 128
#define HD 256
#define CN 40
#define EN 300000

// ---------------------------------------------------------------------------
// Scratch (static __device__ arrays: allocation-free per harness rules)
// ---------------------------------------------------------------------------
__device__ float g_ha[(size_t)AN * HD];    // author hidden state
__device__ float g_hp[(size_t)PN * HD];    // paper hidden state
__device__ float g_agg[(size_t)PN * HD];   // aggregation buffer (reused)
__device__ float g_ta[(size_t)AN * HD];    // author conv output / proj hidden
__device__ float g_tp[(size_t)PN * HD];    // paper conv output / proj hidden
__device__ float g_ws01[HD * HD];          // combined W_self[l,0]+W_self[l,1]
__device__ float g_b01[HD];                // combined bias
__device__ int   g_deg[3 * PN];
__device__ int   g_off[3 * (PN + 1)];
__device__ int   g_cur[3 * PN];
__device__ int   g_perm[3 * EN];

// ---------------------------------------------------------------------------
// Utility
// ---------------------------------------------------------------------------
__device__ __forceinline__ float warp_sum(float v) {
#pragma unroll
    for (int o = 16; o; o >>= 1) v += __shfl_xor_sync(0xffffffffu, v, o);
    return v;
}
__device__ __forceinline__ float warp_max(float v) {
#pragma unroll
    for (int o = 16; o; o >>= 1) v = fmaxf(v, __shfl_xor_sync(0xffffffffu, v, o));
    return v;
}

// ---------------------------------------------------------------------------
// CSR construction kernels (edges are launch-invariant; built once per launch)
// ---------------------------------------------------------------------------
__global__ void k_zero_int(int* __restrict__ p, int n) {
    int i = blockIdx.x * blockDim.x + threadIdx.x;
    if (i < n) p[i] = 0;
}

__global__ void k_hist(const int* __restrict__ dst, int* __restrict__ deg, int n) {
    int i = blockIdx.x * blockDim.x + threadIdx.x;
    if (i < n) atomicAdd(&deg[dst[i]], 1);
}

// single-block exclusive scan: 1024 threads, chunked serial + Hillis-Steele
__global__ void k_scan(const int* __restrict__ deg, int* __restrict__ off, int n) {
    __shared__ int part[1024];
    int tid = threadIdx.x;
    int chunk = (n + 1023) >> 10;
    int s = tid * chunk;
    int e = min(s + chunk, n);
    int sum = 0;
    for (int i = s; i < e; ++i) sum += deg[i];
    part[tid] = sum;
    __syncthreads();
#pragma unroll
    for (int d = 1; d < 1024; d <<= 1) {
        int v = (tid >= d) ? part[tid - d] : 0;
        __syncthreads();
        part[tid] += v;
        __syncthreads();
    }
    int run = (tid == 0) ? 0 : part[tid - 1];
    for (int i = s; i < e; ++i) { off[i] = run; run += deg[i]; }
    if (tid == 0) off[n] = part[1023];
}

__global__ void k_copy_int(const int* __restrict__ a, int* __restrict__ b, int n) {
    int i = blockIdx.x * blockDim.x + threadIdx.x;
    if (i < n) b[i] = a[i];
}

__global__ void k_fill(const int* __restrict__ src, const int* __restrict__ dst,
                       int* __restrict__ cur, int* __restrict__ perm, int n) {
    int i = blockIdx.x * blockDim.x + threadIdx.x;
    if (i < n) {
        int slot = atomicAdd(&cur[dst[i]], 1);
        perm[slot] = src[i];
    }
}

// ---------------------------------------------------------------------------
// Mean aggregation: one warp per destination row, gather over CSR bucket.
// Each edge reads a full contiguous 1KB feature row (coalesced float4s).
// ---------------------------------------------------------------------------
__global__ void k_agg(const float* __restrict__ h, const int* __restrict__ off,
                      const int* __restrict__ perm, float* __restrict__ out, int ndst) {
    int w = (blockIdx.x * blockDim.x + threadIdx.x) >> 5;
    int lane = threadIdx.x & 31;
    if (w >= ndst) return;
    int s = off[w], e = off[w + 1];
    float4 a0 = make_float4(0.f, 0.f, 0.f, 0.f);
    float4 a1 = make_float4(0.f, 0.f, 0.f, 0.f);
    for (int i = s; i < e; ++i) {
        const float4* r = (const float4*)(h + (size_t)perm[i] * HD);
        float4 v0 = __ldg(&r[lane]);
        float4 v1 = __ldg(&r[lane + 32]);
        a0.x += v0.x; a0.y += v0.y; a0.z += v0.z; a0.w += v0.w;
        a1.x += v1.x; a1.y += v1.y; a1.z += v1.z; a1.w += v1.w;
    }
    float inv = (e > s) ? 1.f / (float)(e - s) : 0.f;
    a0.x *= inv; a0.y *= inv; a0.z *= inv; a0.w *= inv;
    a1.x *= inv; a1.y *= inv; a1.z *= inv; a1.w *= inv;
    float4* o = (float4*)(out + (size_t)w * HD);
    o[lane] = a0;
    o[lane + 32] = a1;
}

// ---------------------------------------------------------------------------
// SGEMM: C[M,N] = A[M,K] @ B[K,N] (+bias) (+=C if accum) (relu optional)
// 128x64 tile, BK=16, 256 threads, 8x4 per thread. K % 16 == 0, N % 4 == 0.
// ---------------------------------------------------------------------------
#define BM 128
#define BN 64
#define BK 16
#define TM 8
#define TN 4

__global__ __launch_bounds__(256) void k_sgemm(
    const float* __restrict__ A, const float* __restrict__ B,
    const float* __restrict__ bias, float* __restrict__ C,
    int M, int N, int K, int accum, int relu) {
    __shared__ float As[BK][BM];  // transposed A tile
    __shared__ float Bs[BK][BN];

    const int tid = threadIdx.x;
    const int tx = tid & 15;   // N direction
    const int ty = tid >> 4;   // M direction
    const int bm = blockIdx.y * BM;
    const int bn = blockIdx.x * BN;

    float acc[TM][TN];
#pragma unroll
    for (int i = 0; i < TM; ++i)
#pragma unroll
        for (int j = 0; j < TN; ++j) acc[i][j] = 0.f;

    const int ar = tid >> 2;           // A tile row   (0..63, +64 second half)
    const int ac = (tid & 3) << 2;     // A tile col4  (0,4,8,12)
    const int br = tid >> 4;           // B tile row   (0..15)
    const int bc = (tid & 15) << 2;    // B tile col4  (0..60)

    for (int k0 = 0; k0 < K; k0 += BK) {
#pragma unroll
        for (int h = 0; h < 2; ++h) {
            int r = ar + h * 64;
            int gr = bm + r;
            float4 v = make_float4(0.f, 0.f, 0.f, 0.f);
            if (gr < M) v = *(const float4*)(A + (size_t)gr * K + k0 + ac);
            As[ac + 0][r] = v.x;
            As[ac + 1][r] = v.y;
            As[ac + 2][r] = v.z;
            As[ac + 3][r] = v.w;
        }
        {
            int gc = bn + bc;
            float4 v = make_float4(0.f, 0.f, 0.f, 0.f);
            if (gc < N) v = *(const float4*)(B + (size_t)(k0 + br) * N + gc);
            *(float4*)&Bs[br][bc] = v;
        }
        __syncthreads();
#pragma unroll
        for (int kk = 0; kk < BK; ++kk) {
            float aF[TM], bF[TN];
#pragma unroll
            for (int i = 0; i < TM; ++i) aF[i] = As[kk][ty * TM + i];
#pragma unroll
            for (int j = 0; j < TN; ++j) bF[j] = Bs[kk][tx * TN + j];
#pragma unroll
            for (int i = 0; i < TM; ++i)
#pragma unroll
                for (int j = 0; j < TN; ++j)
                    acc[i][j] = fmaf(aF[i], bF[j], acc[i][j]);
        }
        __syncthreads();
    }

    const int col = bn + tx * TN;
    if (col < N) {  // N % 4 == 0, so full float4 in-bounds when col < N
        float4 bv = make_float4(0.f, 0.f, 0.f, 0.f);
        if (bias) bv = *(const float4*)(bias + col);
#pragma unroll
        for (int i = 0; i < TM; ++i) {
            int row = bm + ty * TM + i;
            if (row >= M) continue;
            float* cp = C + (size_t)row * N + col;
            float4 v = make_float4(acc[i][0] + bv.x, acc[i][1] + bv.y,
                                   acc[i][2] + bv.z, acc[i][3] + bv.w);
            if (accum) {
                float4 o = *(const float4*)cp;
                v.x += o.x; v.y += o.y; v.z += o.z; v.w += o.w;
            }
            if (relu) {
                v.x = fmaxf(v.x, 0.f); v.y = fmaxf(v.y, 0.f);
                v.z = fmaxf(v.z, 0.f); v.w = fmaxf(v.w, 0.f);
            }
            *(float4*)cp = v;
        }
    }
}

// ---------------------------------------------------------------------------
// Fused relu + residual + LayerNorm, in-place into h. One warp per row (H=256).
// ---------------------------------------------------------------------------
__global__ void k_ln(const float* __restrict__ t, float* __restrict__ h,
                     const float* __restrict__ g, const float* __restrict__ b,
                     int rows) {
    int w = (blockIdx.x * blockDim.x + threadIdx.x) >> 5;
    int lane = threadIdx.x & 31;
    if (w >= rows) return;
    const float4* t4 = (const float4*)(t + (size_t)w * HD);
    float4* h4 = (float4*)(h + (size_t)w * HD);
    float4 x0 = t4[lane], x1 = t4[lane + 32];
    float4 p0 = h4[lane], p1 = h4[lane + 32];
    float u[8];
    u[0] = fmaxf(x0.x, 0.f) + p0.x; u[1] = fmaxf(x0.y, 0.f) + p0.y;
    u[2] = fmaxf(x0.z, 0.f) + p0.z; u[3] = fmaxf(x0.w, 0.f) + p0.w;
    u[4] = fmaxf(x1.x, 0.f) + p1.x; u[5] = fmaxf(x1.y, 0.f) + p1.y;
    u[6] = fmaxf(x1.z, 0.f) + p1.z; u[7] = fmaxf(x1.w, 0.f) + p1.w;
    float s = 0.f;
#pragma unroll
    for (int i = 0; i < 8; ++i) s += u[i];
    s = warp_sum(s);
    float mu = s * (1.f / HD);
    float v = 0.f;
#pragma unroll
    for (int i = 0; i < 8; ++i) { float d = u[i] - mu; v += d * d; }
    v = warp_sum(v);
    float rstd = rsqrtf(v * (1.f / HD) + 1e-5f);
    const float4* g4 = (const float4*)g;
    const float4* b4 = (const float4*)b;
    float4 ga = g4[lane], gb = g4[lane + 32];
    float4 ba = b4[lane], bb = b4[lane + 32];
    float4 o0, o1;
    o0.x = (u[0] - mu) * rstd * ga.x + ba.x;
    o0.y = (u[1] - mu) * rstd * ga.y + ba.y;
    o0.z = (u[2] - mu) * rstd * ga.z + ba.z;
    o0.w = (u[3] - mu) * rstd * ga.w + ba.w;
    o1.x = (u[4] - mu) * rstd * gb.x + bb.x;
    o1.y = (u[5] - mu) * rstd * gb.y + bb.y;
    o1.z = (u[6] - mu) * rstd * gb.z + bb.z;
    o1.w = (u[7] - mu) * rstd * gb.w + bb.w;
    h4[lane] = o0;
    h4[lane + 32] = o1;
}

// ---------------------------------------------------------------------------
// log_softmax over CN=40 classes, in-place, one warp per row
// ---------------------------------------------------------------------------
__global__ void k_lsm(float* __restrict__ x, int rows) {
    int w = (blockIdx.x * blockDim.x + threadIdx.x) >> 5;
    int lane = threadIdx.x & 31;
    if (w >= rows) return;
    float* r = x + (size_t)w * CN;
    float v0 = r[lane];                       // lane < 32 < 40 always valid
    bool has1 = (lane + 32) < CN;
    float v1 = has1 ? r[lane + 32] : -3.4e38f;
    float m = warp_max(fmaxf(v0, v1));
    float s = expf(v0 - m) + (has1 ? expf(v1 - m) : 0.f);
    s = warp_sum(s);
    float lse = m + logf(s);
    r[lane] = v0 - lse;
    if (has1) r[lane + 32] = v1 - lse;
}

// ---------------------------------------------------------------------------
// combine W_self[l,0] + W_self[l,1] and biases (saves one 100k GEMM per layer)
// ---------------------------------------------------------------------------
__global__ void k_combine(const float* __restrict__ w0, const float* __restrict__ w1,
                          float* __restrict__ wo, const float* __restrict__ b0,
                          const float* __restrict__ b1, float* __restrict__ bo) {
    int i = blockIdx.x * blockDim.x + threadIdx.x;
    if (i < HD * HD) wo[i] = w0[i] + w1[i];
    if (i < HD) bo[i] = b0[i] + b1[i];
}

// ---------------------------------------------------------------------------
// Host launcher
// ---------------------------------------------------------------------------
static inline void gemm(const float* A, const float* B, const float* bias,
                        float* C, int M, int N, int K, int accum, int relu) {
    dim3 grid((N + BN - 1) / BN, (M + BM - 1) / BM);
    k_sgemm<<<grid, 256>>>(A, B, bias, C, M, N, K, accum, relu);
}

extern "C" void kernel_launch(void* const* d_in, const int* in_sizes, int n_in,
                              void* d_out, int out_size) {
    const float* x_author     = (const float*)d_in[0];
    const float* x_paper      = (const float*)d_in[1];
    const int*   e0_src       = (const int*)d_in[2];
    const int*   e0_dst       = (const int*)d_in[3];
    const int*   e1_src       = (const int*)d_in[4];
    const int*   e1_dst       = (const int*)d_in[5];
    const int*   e2_src       = (const int*)d_in[6];
    const int*   e2_dst       = (const int*)d_in[7];
    const float* emb_W_author = (const float*)d_in[8];
    const float* emb_b_author = (const float*)d_in[9];
    const float* emb_W_paper  = (const float*)d_in[10];
    const float* emb_b_paper  = (const float*)d_in[11];
    const float* W_self       = (const float*)d_in[12];
    const float* W_neigh      = (const float*)d_in[13];
    const float* b_conv       = (const float*)d_in[14];
    const float* ln_g_author  = (const float*)d_in[15];
    const float* ln_b_author  = (const float*)d_in[16];
    const float* ln_g_paper   = (const float*)d_in[17];
    const float* ln_b_paper   = (const float*)d_in[18];
    const float* pW1_author   = (const float*)d_in[19];
    const float* pb1_author   = (const float*)d_in[20];
    const float* pW2_author   = (const float*)d_in[21];
    const float* pb2_author   = (const float*)d_in[22];
    const float* pW1_paper    = (const float*)d_in[23];
    const float* pb1_paper    = (const float*)d_in[24];
    const float* pW2_paper    = (const float*)d_in[25];
    const float* pb2_paper    = (const float*)d_in[26];

    float *p_ha, *p_hp, *p_agg, *p_ta, *p_tp, *p_ws01, *p_b01;
    int *p_deg, *p_off, *p_cur, *p_perm;
    cudaGetSymbolAddress((void**)&p_ha, g_ha);
    cudaGetSymbolAddress((void**)&p_hp, g_hp);
    cudaGetSymbolAddress((void**)&p_agg, g_agg);
    cudaGetSymbolAddress((void**)&p_ta, g_ta);
    cudaGetSymbolAddress((void**)&p_tp, g_tp);
    cudaGetSymbolAddress((void**)&p_ws01, g_ws01);
    cudaGetSymbolAddress((void**)&p_b01, g_b01);
    cudaGetSymbolAddress((void**)&p_deg, g_deg);
    cudaGetSymbolAddress((void**)&p_off, g_off);
    cudaGetSymbolAddress((void**)&p_cur, g_cur);
    cudaGetSymbolAddress((void**)&p_perm, g_perm);

    // ---- CSR build for the 3 edge types (reused across both layers) ----
    const int* srcs[3] = {e0_src, e1_src, e2_src};
    const int* dsts[3] = {e0_dst, e1_dst, e2_dst};
    const int ndsts[3] = {PN, PN, AN};
    const int EB = (EN + 255) / 256;
    for (int t = 0; t < 3; ++t) {
        int* deg = p_deg + t * PN;
        int* off = p_off + t * (PN + 1);
        int* cur = p_cur + t * PN;
        int* perm = p_perm + t * EN;
        int nd = ndsts[t];
        int NB = (nd + 255) / 256;
        k_zero_int<<<NB, 256>>>(deg, nd);
        k_hist<<<EB, 256>>>(dsts[t], deg, EN);
        k_scan<<<1, 1024>>>(deg, off, nd);
        k_copy_int<<<NB, 256>>>(off, cur, nd);
        k_fill<<<EB, 256>>>(srcs[t], dsts[t], cur, perm, EN);
    }

    // ---- input embeddings ----
    gemm(x_author, emb_W_author, emb_b_author, p_ha, AN, HD, DIN, 0, 0);
    gemm(x_paper, emb_W_paper, emb_b_paper, p_hp, PN, HD, DIN, 0, 0);

    // ---- 2 SAGE layers ----
    const int AGG_BLK = 128;  // 4 warps -> 4 dst rows per block
    for (int l = 0; l < 2; ++l) {
        const float* Ws = W_self + (size_t)l * 3 * HD * HD;
        const float* Wn = W_neigh + (size_t)l * 3 * HD * HD;
        const float* bc = b_conv + (size_t)l * 3 * HD;

        k_combine<<<(HD * HD + 255) / 256, 256>>>(Ws, Ws + HD * HD, p_ws01,
                                                  bc, bc + HD, p_b01);

        // paper output: hp@(Ws0+Ws1) + agg0@Wn0 + agg1@Wn1 + (b0+b1)
        gemm(p_hp, p_ws01, p_b01, p_tp, PN, HD, HD, 0, 0);
        k_agg<<<(PN * 32 + AGG_BLK - 1) / AGG_BLK, AGG_BLK>>>(
            p_ha, p_off + 0 * (PN + 1), p_perm + 0 * EN, p_agg, PN);
        gemm(p_agg, Wn, nullptr, p_tp, PN, HD, HD, 1, 0);
        k_agg<<<(PN * 32 + AGG_BLK - 1) / AGG_BLK, AGG_BLK>>>(
            p_hp, p_off + 1 * (PN + 1), p_perm + 1 * EN, p_agg, PN);
        gemm(p_agg, Wn + HD * HD, nullptr, p_tp, PN, HD, HD, 1, 0);

        // author output: ha@Ws2 + agg2@Wn2 + b2
        gemm(p_ha, Ws + 2 * HD * HD, bc + 2 * HD, p_ta, AN, HD, HD, 0, 0);
        k_agg<<<(AN * 32 + AGG_BLK - 1) / AGG_BLK, AGG_BLK>>>(
            p_hp, p_off + 2 * (PN + 1), p_perm + 2 * EN, p_agg, AN);
        gemm(p_agg, Wn + 2 * HD * HD, nullptr, p_ta, AN, HD, HD, 1, 0);

        // fused relu + residual + LayerNorm (in-place into h)
        k_ln<<<(AN * 32 + 127) / 128, 128>>>(p_ta, p_ha, ln_g_author, ln_b_author, AN);
        k_ln<<<(PN * 32 + 127) / 128, 128>>>(p_tp, p_hp, ln_g_paper, ln_b_paper, PN);
    }

    // ---- output heads ----
    float* out = (float*)d_out;
    // author: relu(ha@pW1+b1)@pW2+b2 -> log_softmax, rows of 40
    gemm(p_ha, pW1_author, pb1_author, p_ta, AN, HD, HD, 0, 1);
    gemm(p_ta, pW2_author, pb2_author, out, AN, CN, HD, 0, 0);
    k_lsm<<<(AN * 32 + 127) / 128, 128>>>(out, AN);
    // paper: relu(hp@pW1+b1)@pW2+b2, rows of 256
    gemm(p_hp, pW1_paper, pb1_paper, p_tp, PN, HD, HD, 0, 1);
    gemm(p_tp, pW2_paper, pb2_paper, out + (size_t)AN * CN, PN, HD, HD, 0, 0);
}

// round 4
// speedup vs baseline: 1.3748x; 1.3745x over previous
#include <cuda_runtime.h>
#include <cuda_bf16.h>
#include <math.h>

#define AN 50000
#define PN 100000
#define DIN 128
#define HD 256
#define CN 40
#define EN 300000

__device__ float g_ha[(size_t)AN * HD];
__device__ float g_hp[(size_t)PN * HD];
__device__ float g_agg[(size_t)PN * HD];
__device__ float g_ta[(size_t)AN * HD];
__device__ float g_tp[(size_t)PN * HD];
__device__ float g_ws01[HD * HD];
__device__ float g_b01[HD];
__device__ int   g_deg[3 * PN];
__device__ int   g_off[3 * (PN + 1)];
__device__ int   g_cur[3 * PN];
__device__ int   g_perm[3 * EN];

// ---------------- helpers ----------------
__device__ __forceinline__ unsigned smem_u32(const void* p) {
    unsigned a;
    asm("{ .reg .u64 t; cvta.to.shared.u64 t, %1; cvt.u32.u64 %0, t; }" : "=r"(a) : "l"(p));
    return a;
}
__device__ __forceinline__ void cp16(unsigned dst, const void* src, int n) {
    asm volatile("cp.async.cg.shared.global [%0], [%1], 16, %2;" :: "r"(dst), "l"(src), "r"(n));
}
#define CP_COMMIT() asm volatile("cp.async.commit_group;" ::: "memory")
#define CP_WAIT0()  asm volatile("cp.async.wait_group 0;" ::: "memory")
#define CP_WAIT1()  asm volatile("cp.async.wait_group 1;" ::: "memory")

__device__ __forceinline__ void bsplit(float x, float y, unsigned& h, unsigned& l) {
    __nv_bfloat162 hb = __floats2bfloat162_rn(x, y);
    float rx = x - __bfloat162float(hb.x);
    float ry = y - __bfloat162float(hb.y);
    __nv_bfloat162 lb = __floats2bfloat162_rn(rx, ry);
    h = *(unsigned*)&hb;
    l = *(unsigned*)&lb;
}

#define MMA16816(c, a, b) \
    asm volatile("mma.sync.aligned.m16n8k16.row.col.f32.bf16.bf16.f32 " \
        "{%0,%1,%2,%3},{%4,%5,%6,%7},{%8,%9},{%0,%1,%2,%3};" \
        : "+f"((c)[0]), "+f"((c)[1]), "+f"((c)[2]), "+f"((c)[3]) \
        : "r"((a)[0]), "r"((a)[1]), "r"((a)[2]), "r"((a)[3]), "r"((b)[0]), "r"((b)[1]))

__device__ __forceinline__ float warp_sum(float v) {
#pragma unroll
    for (int o = 16; o; o >>= 1) v += __shfl_xor_sync(0xffffffffu, v, o);
    return v;
}
__device__ __forceinline__ float warp_max(float v) {
#pragma unroll
    for (int o = 16; o; o >>= 1) v = fmaxf(v, __shfl_xor_sync(0xffffffffu, v, o));
    return v;
}

// ---------------- CSR build ----------------
__global__ void k_zero_int(int* __restrict__ p, int n) {
    int i = blockIdx.x * blockDim.x + threadIdx.x;
    if (i < n) p[i] = 0;
}
__global__ void k_hist(const int* __restrict__ dst, int* __restrict__ deg, int n) {
    int i = blockIdx.x * blockDim.x + threadIdx.x;
    if (i < n) atomicAdd(&deg[dst[i]], 1);
}
__global__ void k_scan(const int* __restrict__ deg, int* __restrict__ off, int n) {
    __shared__ int part[1024];
    int tid = threadIdx.x;
    int chunk = (n + 1023) >> 10;
    int s = tid * chunk, e = min(s + chunk, n);
    int sum = 0;
    for (int i = s; i < e; ++i) sum += deg[i];
    part[tid] = sum;
    __syncthreads();
#pragma unroll
    for (int d = 1; d < 1024; d <<= 1) {
        int v = (tid >= d) ? part[tid - d] : 0;
        __syncthreads();
        part[tid] += v;
        __syncthreads();
    }
    int run = (tid == 0) ? 0 : part[tid - 1];
    for (int i = s; i < e; ++i) { off[i] = run; run += deg[i]; }
    if (tid == 0) off[n] = part[1023];
}
__global__ void k_copy_int(const int* __restrict__ a, int* __restrict__ b, int n) {
    int i = blockIdx.x * blockDim.x + threadIdx.x;
    if (i < n) b[i] = a[i];
}
__global__ void k_fill(const int* __restrict__ src, const int* __restrict__ dst,
                       int* __restrict__ cur, int* __restrict__ perm, int n) {
    int i = blockIdx.x * blockDim.x + threadIdx.x;
    if (i < n) { int slot = atomicAdd(&cur[dst[i]], 1); perm[slot] = src[i]; }
}

// ---------------- mean aggregation ----------------
__global__ void k_agg(const float* __restrict__ h, const int* __restrict__ off,
                      const int* __restrict__ perm, float* __restrict__ out, int ndst) {
    int w = (blockIdx.x * blockDim.x + threadIdx.x) >> 5;
    int lane = threadIdx.x & 31;
    if (w >= ndst) return;
    int s = off[w], e = off[w + 1];
    float4 a0 = make_float4(0.f, 0.f, 0.f, 0.f);
    float4 a1 = make_float4(0.f, 0.f, 0.f, 0.f);
    for (int i = s; i < e; ++i) {
        const float4* r = (const float4*)(h + (size_t)perm[i] * HD);
        float4 v0 = __ldg(&r[lane]);
        float4 v1 = __ldg(&r[lane + 32]);
        a0.x += v0.x; a0.y += v0.y; a0.z += v0.z; a0.w += v0.w;
        a1.x += v1.x; a1.y += v1.y; a1.z += v1.z; a1.w += v1.w;
    }
    float inv = (e > s) ? 1.f / (float)(e - s) : 0.f;
    a0.x *= inv; a0.y *= inv; a0.z *= inv; a0.w *= inv;
    a1.x *= inv; a1.y *= inv; a1.z *= inv; a1.w *= inv;
    float4* o = (float4*)(out + (size_t)w * HD);
    o[lane] = a0;
    o[lane + 32] = a1;
}

// ---------------- HMMA bf16 3-split GEMM (mma.sync, arch-neutral PTX) ------
// C[M,N] = A[M,K]@B[K,N] (+bias)(+=C)(relu). Requires N%128==0, K%32==0.
// CTA tile 128x128, BK=32, 8 warps (2M x 4N), warp tile 64x32, fp32 acc.
#define ASTR 36   // A smem row stride (floats), 144B: keeps cp.async 16B align
#define BSTR 132  // B smem row stride (floats), 528B
#define BUFW (128 * ASTR + 32 * BSTR)  // words per double-buffer stage

__global__ __launch_bounds__(256) void k_hgemm(
    const float* __restrict__ A, const float* __restrict__ B,
    const float* __restrict__ bias, float* __restrict__ C,
    int M, int N, int K, int accum, int relu) {
    extern __shared__ float smf[];
    const int tid = threadIdx.x;
    const int lane = tid & 31;
    const int warp = tid >> 5;
    const int g = lane >> 2;      // 0..7
    const int t = lane & 3;       // 0..3
    const int wm = warp & 1;      // 2 warps along M
    const int wn = warp >> 1;     // 4 warps along N
    const int bm = blockIdx.y * 128;
    const int bn = blockIdx.x * 128;
    const unsigned sbase = smem_u32(smf);

    float acc[4][4][4];
#pragma unroll
    for (int i = 0; i < 4; ++i)
#pragma unroll
        for (int j = 0; j < 4; ++j)
#pragma unroll
            for (int q = 0; q < 4; ++q) acc[i][j][q] = 0.f;

    const int NIT = K >> 5;

    // --- async tile loader: tile it -> buffer (it&1) ---
    auto issue = [&](int it) {
        int buf = it & 1;
        int k0 = it << 5;
        unsigned abase = sbase + buf * (BUFW * 4);
        unsigned bbase = abase + 128 * ASTR * 4;
#pragma unroll
        for (int r = 0; r < 4; ++r) {  // A: 128 rows x 8 16B-chunks
            int c = tid + r * 256;
            int row = c >> 3, c16 = c & 7;
            int grow = bm + row;
            const float* src = A + (size_t)(grow < M ? grow : 0) * K + k0 + c16 * 4;
            cp16(abase + row * (ASTR * 4) + c16 * 16, src, grow < M ? 16 : 0);
        }
#pragma unroll
        for (int r = 0; r < 4; ++r) {  // B: 32 rows x 32 16B-chunks
            int c = tid + r * 256;
            int row = c >> 5, col = c & 31;
            const float* src = B + (size_t)(k0 + row) * N + bn + col * 4;
            cp16(bbase + row * (BSTR * 4) + col * 16, src, 16);
        }
        CP_COMMIT();
    };

    issue(0);
    for (int it = 0; it < NIT; ++it) {
        if (it + 1 < NIT) { issue(it + 1); CP_WAIT1(); }
        else              { CP_WAIT0(); }
        __syncthreads();

        const float* as = smf + (it & 1) * BUFW;
        const float* bs = as + 128 * ASTR;
#pragma unroll
        for (int kk = 0; kk < 2; ++kk) {  // two k16 halves of BK=32
            unsigned ah[4][4], al[4][4];
#pragma unroll
            for (int i = 0; i < 4; ++i) {
                const float* ap = as + (wm * 64 + i * 16 + g) * ASTR + kk * 16 + 2 * t;
                float2 v00 = *(const float2*)(ap);
                float2 v10 = *(const float2*)(ap + 8 * ASTR);
                float2 v01 = *(const float2*)(ap + 8);
                float2 v11 = *(const float2*)(ap + 8 * ASTR + 8);
                bsplit(v00.x, v00.y, ah[i][0], al[i][0]);
                bsplit(v10.x, v10.y, ah[i][1], al[i][1]);
                bsplit(v01.x, v01.y, ah[i][2], al[i][2]);
                bsplit(v11.x, v11.y, ah[i][3], al[i][3]);
            }
            unsigned bh[4][2], bl[4][2];
#pragma unroll
            for (int j = 0; j < 4; ++j) {
                const float* bp = bs + (kk * 16 + 2 * t) * BSTR + wn * 32 + j * 8 + g;
                float b0 = bp[0],         b1 = bp[BSTR];
                float b2 = bp[8 * BSTR],  b3 = bp[9 * BSTR];
                bsplit(b0, b1, bh[j][0], bl[j][0]);
                bsplit(b2, b3, bh[j][1], bl[j][1]);
            }
#pragma unroll
            for (int i = 0; i < 4; ++i)
#pragma unroll
                for (int j = 0; j < 4; ++j) {
                    MMA16816(acc[i][j], ah[i], bh[j]);
                    MMA16816(acc[i][j], ah[i], bl[j]);
                    MMA16816(acc[i][j], al[i], bh[j]);
                }
        }
        __syncthreads();
    }

    // --- epilogue ---
#pragma unroll
    for (int i = 0; i < 4; ++i) {
        int r0 = bm + wm * 64 + i * 16 + g;
#pragma unroll
        for (int j = 0; j < 4; ++j) {
            int cn = bn + wn * 32 + j * 8 + 2 * t;
            float2 bv = make_float2(0.f, 0.f);
            if (bias) bv = *(const float2*)(bias + cn);
#pragma unroll
            for (int h = 0; h < 2; ++h) {
                int row = r0 + h * 8;
                if (row >= M) continue;
                float* cp = C + (size_t)row * N + cn;
                float2 v = make_float2(acc[i][j][h * 2 + 0] + bv.x,
                                       acc[i][j][h * 2 + 1] + bv.y);
                if (accum) {
                    float2 o = *(const float2*)cp;
                    v.x += o.x; v.y += o.y;
                }
                if (relu) { v.x = fmaxf(v.x, 0.f); v.y = fmaxf(v.y, 0.f); }
                *(float2*)cp = v;
            }
        }
    }
}

// ---------------- fp32 SGEMM fallback (N=40 head) ----------------
#define BM 128
#define BN 64
#define BK 16
#define TM 8
#define TN 4
__global__ __launch_bounds__(256) void k_sgemm(
    const float* __restrict__ A, const float* __restrict__ B,
    const float* __restrict__ bias, float* __restrict__ C,
    int M, int N, int K, int accum, int relu) {
    __shared__ float As[BK][BM];
    __shared__ float Bs[BK][BN];
    const int tid = threadIdx.x;
    const int tx = tid & 15, ty = tid >> 4;
    const int bm = blockIdx.y * BM, bn = blockIdx.x * BN;
    float acc[TM][TN];
#pragma unroll
    for (int i = 0; i < TM; ++i)
#pragma unroll
        for (int j = 0; j < TN; ++j) acc[i][j] = 0.f;
    const int ar = tid >> 2, ac = (tid & 3) << 2;
    const int br = tid >> 4, bc = (tid & 15) << 2;
    for (int k0 = 0; k0 < K; k0 += BK) {
#pragma unroll
        for (int h = 0; h < 2; ++h) {
            int r = ar + h * 64, gr = bm + r;
            float4 v = make_float4(0.f, 0.f, 0.f, 0.f);
            if (gr < M) v = *(const float4*)(A + (size_t)gr * K + k0 + ac);
            As[ac + 0][r] = v.x; As[ac + 1][r] = v.y;
            As[ac + 2][r] = v.z; As[ac + 3][r] = v.w;
        }
        {
            int gc = bn + bc;
            float4 v = make_float4(0.f, 0.f, 0.f, 0.f);
            if (gc < N) v = *(const float4*)(B + (size_t)(k0 + br) * N + gc);
            *(float4*)&Bs[br][bc] = v;
        }
        __syncthreads();
#pragma unroll
        for (int kk = 0; kk < BK; ++kk) {
            float aF[TM], bF[TN];
#pragma unroll
            for (int i = 0; i < TM; ++i) aF[i] = As[kk][ty * TM + i];
#pragma unroll
            for (int j = 0; j < TN; ++j) bF[j] = Bs[kk][tx * TN + j];
#pragma unroll
            for (int i = 0; i < TM; ++i)
#pragma unroll
                for (int j = 0; j < TN; ++j) acc[i][j] = fmaf(aF[i], bF[j], acc[i][j]);
        }
        __syncthreads();
    }
    const int col = bn + tx * TN;
    if (col < N) {
        float4 bv = make_float4(0.f, 0.f, 0.f, 0.f);
        if (bias) bv = *(const float4*)(bias + col);
#pragma unroll
        for (int i = 0; i < TM; ++i) {
            int row = bm + ty * TM + i;
            if (row >= M) continue;
            float* cp = C + (size_t)row * N + col;
            float4 v = make_float4(acc[i][0] + bv.x, acc[i][1] + bv.y,
                                   acc[i][2] + bv.z, acc[i][3] + bv.w);
            if (accum) {
                float4 o = *(const float4*)cp;
                v.x += o.x; v.y += o.y; v.z += o.z; v.w += o.w;
            }
            if (relu) {
                v.x = fmaxf(v.x, 0.f); v.y = fmaxf(v.y, 0.f);
                v.z = fmaxf(v.z, 0.f); v.w = fmaxf(v.w, 0.f);
            }
            *(float4*)cp = v;
        }
    }
}

// ---------------- fused relu+residual+LayerNorm ----------------
__global__ void k_ln(const float* __restrict__ t, float* __restrict__ h,
                     const float* __restrict__ g, const float* __restrict__ b, int rows) {
    int w = (blockIdx.x * blockDim.x + threadIdx.x) >> 5;
    int lane = threadIdx.x & 31;
    if (w >= rows) return;
    const float4* t4 = (const float4*)(t + (size_t)w * HD);
    float4* h4 = (float4*)(h + (size_t)w * HD);
    float4 x0 = t4[lane], x1 = t4[lane + 32];
    float4 p0 = h4[lane], p1 = h4[lane + 32];
    float u[8];
    u[0] = fmaxf(x0.x, 0.f) + p0.x; u[1] = fmaxf(x0.y, 0.f) + p0.y;
    u[2] = fmaxf(x0.z, 0.f) + p0.z; u[3] = fmaxf(x0.w, 0.f) + p0.w;
    u[4] = fmaxf(x1.x, 0.f) + p1.x; u[5] = fmaxf(x1.y, 0.f) + p1.y;
    u[6] = fmaxf(x1.z, 0.f) + p1.z; u[7] = fmaxf(x1.w, 0.f) + p1.w;
    float s = 0.f;
#pragma unroll
    for (int i = 0; i < 8; ++i) s += u[i];
    s = warp_sum(s);
    float mu = s * (1.f / HD);
    float v = 0.f;
#pragma unroll
    for (int i = 0; i < 8; ++i) { float d = u[i] - mu; v += d * d; }
    v = warp_sum(v);
    float rstd = rsqrtf(v * (1.f / HD) + 1e-5f);
    const float4* g4 = (const float4*)g;
    const float4* b4 = (const float4*)b;
    float4 ga = g4[lane], gb = g4[lane + 32];
    float4 ba = b4[lane], bb = b4[lane + 32];
    float4 o0, o1;
    o0.x = (u[0] - mu) * rstd * ga.x + ba.x; o0.y = (u[1] - mu) * rstd * ga.y + ba.y;
    o0.z = (u[2] - mu) * rstd * ga.z + ba.z; o0.w = (u[3] - mu) * rstd * ga.w + ba.w;
    o1.x = (u[4] - mu) * rstd * gb.x + bb.x; o1.y = (u[5] - mu) * rstd * gb.y + bb.y;
    o1.z = (u[6] - mu) * rstd * gb.z + bb.z; o1.w = (u[7] - mu) * rstd * gb.w + bb.w;
    h4[lane] = o0;
    h4[lane + 32] = o1;
}

__global__ void k_lsm(float* __restrict__ x, int rows) {
    int w = (blockIdx.x * blockDim.x + threadIdx.x) >> 5;
    int lane = threadIdx.x & 31;
    if (w >= rows) return;
    float* r = x + (size_t)w * CN;
    float v0 = r[lane];
    bool has1 = (lane + 32) < CN;
    float v1 = has1 ? r[lane + 32] : -3.4e38f;
    float m = warp_max(fmaxf(v0, v1));
    float s = expf(v0 - m) + (has1 ? expf(v1 - m) : 0.f);
    s = warp_sum(s);
    float lse = m + logf(s);
    r[lane] = v0 - lse;
    if (has1) r[lane + 32] = v1 - lse;
}

__global__ void k_combine(const float* __restrict__ w0, const float* __restrict__ w1,
                          float* __restrict__ wo, const float* __restrict__ b0,
                          const float* __restrict__ b1, float* __restrict__ bo) {
    int i = blockIdx.x * blockDim.x + threadIdx.x;
    if (i < HD * HD) wo[i] = w0[i] + w1[i];
    if (i < HD) bo[i] = b0[i] + b1[i];
}

// ---------------- host ----------------
static inline void gemm(const float* A, const float* B, const float* bias,
                        float* C, int M, int N, int K, int accum, int relu) {
    if ((N & 127) == 0 && (K & 31) == 0) {
        dim3 grid(N >> 7, (M + 127) >> 7);
        k_hgemm<<<grid, 256, 2 * BUFW * 4>>>(A, B, bias, C, M, N, K, accum, relu);
    } else {
        dim3 grid((N + BN - 1) / BN, (M + BM - 1) / BM);
        k_sgemm<<<grid, 256>>>(A, B, bias, C, M, N, K, accum, relu);
    }
}

extern "C" void kernel_launch(void* const* d_in, const int* in_sizes, int n_in,
                              void* d_out, int out_size) {
    const float* x_author     = (const float*)d_in[0];
    const float* x_paper      = (const float*)d_in[1];
    const int*   e0_src       = (const int*)d_in[2];
    const int*   e0_dst       = (const int*)d_in[3];
    const int*   e1_src       = (const int*)d_in[4];
    const int*   e1_dst       = (const int*)d_in[5];
    const int*   e2_src       = (const int*)d_in[6];
    const int*   e2_dst       = (const int*)d_in[7];
    const float* emb_W_author = (const float*)d_in[8];
    const float* emb_b_author = (const float*)d_in[9];
    const float* emb_W_paper  = (const float*)d_in[10];
    const float* emb_b_paper  = (const float*)d_in[11];
    const float* W_self       = (const float*)d_in[12];
    const float* W_neigh      = (const float*)d_in[13];
    const float* b_conv       = (const float*)d_in[14];
    const float* ln_g_author  = (const float*)d_in[15];
    const float* ln_b_author  = (const float*)d_in[16];
    const float* ln_g_paper   = (const float*)d_in[17];
    const float* ln_b_paper   = (const float*)d_in[18];
    const float* pW1_author   = (const float*)d_in[19];
    const float* pb1_author   = (const float*)d_in[20];
    const float* pW2_author   = (const float*)d_in[21];
    const float* pb2_author   = (const float*)d_in[22];
    const float* pW1_paper    = (const float*)d_in[23];
    const float* pb1_paper    = (const float*)d_in[24];
    const float* pW2_paper    = (const float*)d_in[25];
    const float* pb2_paper    = (const float*)d_in[26];

    cudaFuncSetAttribute(k_hgemm, cudaFuncAttributeMaxDynamicSharedMemorySize, 2 * BUFW * 4);

    float *p_ha, *p_hp, *p_agg, *p_ta, *p_tp, *p_ws01, *p_b01;
    int *p_deg, *p_off, *p_cur, *p_perm;
    cudaGetSymbolAddress((void**)&p_ha, g_ha);
    cudaGetSymbolAddress((void**)&p_hp, g_hp);
    cudaGetSymbolAddress((void**)&p_agg, g_agg);
    cudaGetSymbolAddress((void**)&p_ta, g_ta);
    cudaGetSymbolAddress((void**)&p_tp, g_tp);
    cudaGetSymbolAddress((void**)&p_ws01, g_ws01);
    cudaGetSymbolAddress((void**)&p_b01, g_b01);
    cudaGetSymbolAddress((void**)&p_deg, g_deg);
    cudaGetSymbolAddress((void**)&p_off, g_off);
    cudaGetSymbolAddress((void**)&p_cur, g_cur);
    cudaGetSymbolAddress((void**)&p_perm, g_perm);

    const int* srcs[3] = {e0_src, e1_src, e2_src};
    const int* dsts[3] = {e0_dst, e1_dst, e2_dst};
    const int ndsts[3] = {PN, PN, AN};
    const int EB = (EN + 255) / 256;
    for (int t = 0; t < 3; ++t) {
        int* deg = p_deg + t * PN;
        int* off = p_off + t * (PN + 1);
        int* cur = p_cur + t * PN;
        int* perm = p_perm + t * EN;
        int nd = ndsts[t];
        int NB = (nd + 255) / 256;
        k_zero_int<<<NB, 256>>>(deg, nd);
        k_hist<<<EB, 256>>>(dsts[t], deg, EN);
        k_scan<<<1, 1024>>>(deg, off, nd);
        k_copy_int<<<NB, 256>>>(off, cur, nd);
        k_fill<<<EB, 256>>>(srcs[t], dsts[t], cur, perm, EN);
    }

    gemm(x_author, emb_W_author, emb_b_author, p_ha, AN, HD, DIN, 0, 0);
    gemm(x_paper, emb_W_paper, emb_b_paper, p_hp, PN, HD, DIN, 0, 0);

    const int AGG_BLK = 128;
    for (int l = 0; l < 2; ++l) {
        const float* Ws = W_self + (size_t)l * 3 * HD * HD;
        const float* Wn = W_neigh + (size_t)l * 3 * HD * HD;
        const float* bc = b_conv + (size_t)l * 3 * HD;

        k_combine<<<(HD * HD + 255) / 256, 256>>>(Ws, Ws + HD * HD, p_ws01, bc, bc + HD, p_b01);

        gemm(p_hp, p_ws01, p_b01, p_tp, PN, HD, HD, 0, 0);
        k_agg<<<(PN * 32 + AGG_BLK - 1) / AGG_BLK, AGG_BLK>>>(
            p_ha, p_off + 0 * (PN + 1), p_perm + 0 * EN, p_agg, PN);
        gemm(p_agg, Wn, nullptr, p_tp, PN, HD, HD, 1, 0);
        k_agg<<<(PN * 32 + AGG_BLK - 1) / AGG_BLK, AGG_BLK>>>(
            p_hp, p_off + 1 * (PN + 1), p_perm + 1 * EN, p_agg, PN);
        gemm(p_agg, Wn + HD * HD, nullptr, p_tp, PN, HD, HD, 1, 0);

        gemm(p_ha, Ws + 2 * HD * HD, bc + 2 * HD, p_ta, AN, HD, HD, 0, 0);
        k_agg<<<(AN * 32 + AGG_BLK - 1) / AGG_BLK, AGG_BLK>>>(
            p_hp, p_off + 2 * (PN + 1), p_perm + 2 * EN, p_agg, AN);
        gemm(p_agg, Wn + 2 * HD * HD, nullptr, p_ta, AN, HD, HD, 1, 0);

        k_ln<<<(AN * 32 + 127) / 128, 128>>>(p_ta, p_ha, ln_g_author, ln_b_author, AN);
        k_ln<<<(PN * 32 + 127) / 128, 128>>>(p_tp, p_hp, ln_g_paper, ln_b_paper, PN);
    }

    float* out = (float*)d_out;
    gemm(p_ha, pW1_author, pb1_author, p_ta, AN, HD, HD, 0, 1);
    gemm(p_ta, pW2_author, pb2_author, out, AN, CN, HD, 0, 0);
    k_lsm<<<(AN * 32 + 127) / 128, 128>>>(out, AN);
    gemm(p_hp, pW1_paper, pb1_paper, p_tp, PN, HD, HD, 0, 1);
    gemm(p_tp, pW2_paper, pb2_paper, out + (size_t)AN * CN, PN, HD, HD, 0, 0);
}

// round 5
// speedup vs baseline: 1.5972x; 1.1617x over previous
#include <cuda_runtime.h>
#include <cuda_bf16.h>
#include <math.h>

#define AN 50000
#define PN 100000
#define DIN 128
#define HD 256
#define CN 40
#define EN 300000

__device__ float g_ha[(size_t)AN * HD];
__device__ float g_hp[(size_t)PN * HD];
__device__ float g_agg[(size_t)PN * HD];
__device__ float g_ta[(size_t)AN * HD];
__device__ float g_tp[(size_t)PN * HD];
__device__ float g_ws01[HD * HD];
__device__ float g_b01[HD];
__device__ int   g_deg[3 * PN];
__device__ int   g_off[3 * (PN + 1)];
__device__ int   g_cur[3 * PN];
__device__ int   g_perm[3 * EN];

// ---------------- helpers ----------------
__device__ __forceinline__ unsigned smem_u32(const void* p) {
    unsigned a;
    asm("{ .reg .u64 t; cvta.to.shared.u64 t, %1; cvt.u32.u64 %0, t; }" : "=r"(a) : "l"(p));
    return a;
}
__device__ __forceinline__ void bsplit(float x, float y, unsigned& h, unsigned& l) {
    __nv_bfloat162 hb = __floats2bfloat162_rn(x, y);
    float rx = x - __bfloat162float(hb.x);
    float ry = y - __bfloat162float(hb.y);
    __nv_bfloat162 lb = __floats2bfloat162_rn(rx, ry);
    h = *(unsigned*)&hb;
    l = *(unsigned*)&lb;
}
#define MMA16816(c, a, b) \
    asm volatile("mma.sync.aligned.m16n8k16.row.col.f32.bf16.bf16.f32 " \
        "{%0,%1,%2,%3},{%4,%5,%6,%7},{%8,%9},{%0,%1,%2,%3};" \
        : "+f"((c)[0]), "+f"((c)[1]), "+f"((c)[2]), "+f"((c)[3]) \
        : "r"((a)[0]), "r"((a)[1]), "r"((a)[2]), "r"((a)[3]), "r"((b)[0]), "r"((b)[1]))
#define LDSM4(r, addr) \
    asm volatile("ldmatrix.sync.aligned.m8n8.x4.shared.b16 {%0,%1,%2,%3},[%4];" \
        : "=r"((r)[0]), "=r"((r)[1]), "=r"((r)[2]), "=r"((r)[3]) : "r"(addr))
#define LDSM4T(r, addr) \
    asm volatile("ldmatrix.sync.aligned.m8n8.x4.trans.shared.b16 {%0,%1,%2,%3},[%4];" \
        : "=r"((r)[0]), "=r"((r)[1]), "=r"((r)[2]), "=r"((r)[3]) : "r"(addr))

__device__ __forceinline__ float warp_sum(float v) {
#pragma unroll
    for (int o = 16; o; o >>= 1) v += __shfl_xor_sync(0xffffffffu, v, o);
    return v;
}
__device__ __forceinline__ float warp_max(float v) {
#pragma unroll
    for (int o = 16; o; o >>= 1) v = fmaxf(v, __shfl_xor_sync(0xffffffffu, v, o));
    return v;
}

// ---------------- CSR build ----------------
__global__ void k_zero_int(int* __restrict__ p, int n) {
    int i = blockIdx.x * blockDim.x + threadIdx.x;
    if (i < n) p[i] = 0;
}
__global__ void k_hist(const int* __restrict__ dst, int* __restrict__ deg, int n) {
    int i = blockIdx.x * blockDim.x + threadIdx.x;
    if (i < n) atomicAdd(&deg[dst[i]], 1);
}
__global__ void k_scan(const int* __restrict__ deg, int* __restrict__ off, int n) {
    __shared__ int part[1024];
    int tid = threadIdx.x;
    int chunk = (n + 1023) >> 10;
    int s = tid * chunk, e = min(s + chunk, n);
    int sum = 0;
    for (int i = s; i < e; ++i) sum += deg[i];
    part[tid] = sum;
    __syncthreads();
#pragma unroll
    for (int d = 1; d < 1024; d <<= 1) {
        int v = (tid >= d) ? part[tid - d] : 0;
        __syncthreads();
        part[tid] += v;
        __syncthreads();
    }
    int run = (tid == 0) ? 0 : part[tid - 1];
    for (int i = s; i < e; ++i) { off[i] = run; run += deg[i]; }
    if (tid == 0) off[n] = part[1023];
}
__global__ void k_copy_int(const int* __restrict__ a, int* __restrict__ b, int n) {
    int i = blockIdx.x * blockDim.x + threadIdx.x;
    if (i < n) b[i] = a[i];
}
__global__ void k_fill(const int* __restrict__ src, const int* __restrict__ dst,
                       int* __restrict__ cur, int* __restrict__ perm, int n) {
    int i = blockIdx.x * blockDim.x + threadIdx.x;
    if (i < n) { int slot = atomicAdd(&cur[dst[i]], 1); perm[slot] = src[i]; }
}

// ---------------- mean aggregation ----------------
__global__ void k_agg(const float* __restrict__ h, const int* __restrict__ off,
                      const int* __restrict__ perm, float* __restrict__ out, int ndst) {
    int w = (blockIdx.x * blockDim.x + threadIdx.x) >> 5;
    int lane = threadIdx.x & 31;
    if (w >= ndst) return;
    int s = off[w], e = off[w + 1];
    float4 a0 = make_float4(0.f, 0.f, 0.f, 0.f);
    float4 a1 = make_float4(0.f, 0.f, 0.f, 0.f);
    for (int i = s; i < e; ++i) {
        const float4* r = (const float4*)(h + (size_t)perm[i] * HD);
        float4 v0 = __ldg(&r[lane]);
        float4 v1 = __ldg(&r[lane + 32]);
        a0.x += v0.x; a0.y += v0.y; a0.z += v0.z; a0.w += v0.w;
        a1.x += v1.x; a1.y += v1.y; a1.z += v1.z; a1.w += v1.w;
    }
    float inv = (e > s) ? 1.f / (float)(e - s) : 0.f;
    a0.x *= inv; a0.y *= inv; a0.z *= inv; a0.w *= inv;
    a1.x *= inv; a1.y *= inv; a1.z *= inv; a1.w *= inv;
    float4* o = (float4*)(out + (size_t)w * HD);
    o[lane] = a0;
    o[lane + 32] = a1;
}

// ---------------- HMMA bf16 3-split GEMM, convert-at-STS + ldmatrix --------
// C[M,N] = A[M,K]@B[K,N] (+bias)(+=C)(relu). Requires N%128==0, K%32==0.
// CTA 128x128, BK=32, 8 warps (2M x 4N), warp tile 64x32, fp32 acc.
#define A_ST 80           // A smem row stride bytes (40 bf16; 5x16B, 5 coprime 8)
#define B_ST 272          // B smem row stride bytes (136 bf16; 17x16B)
#define OFF_AL 10240      // 128*80
#define OFF_BH 20480
#define OFF_BL 29184      // 20480 + 32*272
#define STAGE 37888       // 29184 + 32*272

__global__ __launch_bounds__(256, 1) void k_hgemm(
    const float* __restrict__ A, const float* __restrict__ B,
    const float* __restrict__ bias, float* __restrict__ C,
    int M, int N, int K, int accum, int relu) {
    extern __shared__ char smc[];
    const int tid = threadIdx.x;
    const int lane = tid & 31;
    const int warp = tid >> 5;
    const int g = lane >> 2;
    const int t = lane & 3;
    const int wm = warp & 1;
    const int wn = warp >> 1;
    const int bm = blockIdx.y * 128;
    const int bn = blockIdx.x * 128;
    const unsigned sbase = smem_u32(smc);

    float acc[4][4][4];
#pragma unroll
    for (int i = 0; i < 4; ++i)
#pragma unroll
        for (int j = 0; j < 4; ++j)
#pragma unroll
            for (int q = 0; q < 4; ++q) acc[i][j][q] = 0.f;

    const int NIT = K >> 5;

    int arow[4], ac4[4], brow[4], bc4[4];
#pragma unroll
    for (int r = 0; r < 4; ++r) {
        int c = tid + r * 256;
        arow[r] = c >> 3; ac4[r] = c & 7;
        brow[r] = c >> 5; bc4[r] = c & 31;
    }

    float4 Ar[4], Br[4];
#pragma unroll
    for (int r = 0; r < 4; ++r) {
        int grow = bm + arow[r];
        Ar[r] = *(const float4*)(A + (size_t)(grow < M ? grow : 0) * K + ac4[r] * 4);
        Br[r] = *(const float4*)(B + (size_t)brow[r] * N + bn + bc4[r] * 4);
    }

    for (int it = 0; it < NIT; ++it) {
        const unsigned sa = sbase + (it & 1) * STAGE;
        // STS current tile: fp32 regs -> bf16 hi/lo smem
#pragma unroll
        for (int r = 0; r < 4; ++r) {
            unsigned h0, l0, h1, l1;
            bsplit(Ar[r].x, Ar[r].y, h0, l0);
            bsplit(Ar[r].z, Ar[r].w, h1, l1);
            unsigned off = sa + arow[r] * A_ST + ac4[r] * 8;
            asm volatile("st.shared.v2.b32 [%0], {%1,%2};" :: "r"(off), "r"(h0), "r"(h1));
            asm volatile("st.shared.v2.b32 [%0], {%1,%2};" :: "r"(off + OFF_AL), "r"(l0), "r"(l1));
            bsplit(Br[r].x, Br[r].y, h0, l0);
            bsplit(Br[r].z, Br[r].w, h1, l1);
            unsigned boff = sa + OFF_BH + brow[r] * B_ST + bc4[r] * 8;
            asm volatile("st.shared.v2.b32 [%0], {%1,%2};" :: "r"(boff), "r"(h0), "r"(h1));
            asm volatile("st.shared.v2.b32 [%0], {%1,%2};" :: "r"(boff + (OFF_BL - OFF_BH)), "r"(l0), "r"(l1));
        }
        if (it + 1 < NIT) {  // prefetch next tile
            int k0 = (it + 1) << 5;
#pragma unroll
            for (int r = 0; r < 4; ++r) {
                int grow = bm + arow[r];
                Ar[r] = *(const float4*)(A + (size_t)(grow < M ? grow : 0) * K + k0 + ac4[r] * 4);
                Br[r] = *(const float4*)(B + (size_t)(k0 + brow[r]) * N + bn + bc4[r] * 4);
            }
        }
        __syncthreads();

#pragma unroll
        for (int kk = 0; kk < 2; ++kk) {
            unsigned ah[4][4], al[4][4], bh[2][4], bl[2][4];
            unsigned abase = sa + (wm * 64 + (lane & 15)) * A_ST + kk * 32 + ((lane >> 4) << 4);
#pragma unroll
            for (int i = 0; i < 4; ++i) {
                LDSM4(ah[i], abase + i * (16 * A_ST));
                LDSM4(al[i], abase + i * (16 * A_ST) + OFF_AL);
            }
            unsigned bbase = sa + OFF_BH + (kk * 16 + (lane & 15)) * B_ST +
                             (wn * 32 + ((lane >> 4) << 3)) * 2;
#pragma unroll
            for (int p = 0; p < 2; ++p) {
                LDSM4T(bh[p], bbase + p * 32);
                LDSM4T(bl[p], bbase + p * 32 + (OFF_BL - OFF_BH));
            }
#pragma unroll
            for (int i = 0; i < 4; ++i)
#pragma unroll
                for (int j = 0; j < 4; ++j) {
                    unsigned* bhj = &bh[j >> 1][(j & 1) * 2];
                    unsigned* blj = &bl[j >> 1][(j & 1) * 2];
                    MMA16816(acc[i][j], ah[i], bhj);
                    MMA16816(acc[i][j], ah[i], blj);
                    MMA16816(acc[i][j], al[i], bhj);
                }
        }
        __syncthreads();
    }

#pragma unroll
    for (int i = 0; i < 4; ++i) {
        int r0 = bm + wm * 64 + i * 16 + g;
#pragma unroll
        for (int j = 0; j < 4; ++j) {
            int cn = bn + wn * 32 + j * 8 + 2 * t;
            float2 bv = make_float2(0.f, 0.f);
            if (bias) bv = *(const float2*)(bias + cn);
#pragma unroll
            for (int h = 0; h < 2; ++h) {
                int row = r0 + h * 8;
                if (row >= M) continue;
                float* cp = C + (size_t)row * N + cn;
                float2 v = make_float2(acc[i][j][h * 2 + 0] + bv.x,
                                       acc[i][j][h * 2 + 1] + bv.y);
                if (accum) {
                    float2 o = *(const float2*)cp;
                    v.x += o.x; v.y += o.y;
                }
                if (relu) { v.x = fmaxf(v.x, 0.f); v.y = fmaxf(v.y, 0.f); }
                *(float2*)cp = v;
            }
        }
    }
}

// ---------------- fp32 SGEMM fallback (N=40 head) ----------------
#define BM 128
#define BN 64
#define BK 16
#define TM 8
#define TN 4
__global__ __launch_bounds__(256) void k_sgemm(
    const float* __restrict__ A, const float* __restrict__ B,
    const float* __restrict__ bias, float* __restrict__ C,
    int M, int N, int K, int accum, int relu) {
    __shared__ float As[BK][BM];
    __shared__ float Bs[BK][BN];
    const int tid = threadIdx.x;
    const int tx = tid & 15, ty = tid >> 4;
    const int bm = blockIdx.y * BM, bn = blockIdx.x * BN;
    float acc[TM][TN];
#pragma unroll
    for (int i = 0; i < TM; ++i)
#pragma unroll
        for (int j = 0; j < TN; ++j) acc[i][j] = 0.f;
    const int ar = tid >> 2, ac = (tid & 3) << 2;
    const int br = tid >> 4, bc = (tid & 15) << 2;
    for (int k0 = 0; k0 < K; k0 += BK) {
#pragma unroll
        for (int h = 0; h < 2; ++h) {
            int r = ar + h * 64, gr = bm + r;
            float4 v = make_float4(0.f, 0.f, 0.f, 0.f);
            if (gr < M) v = *(const float4*)(A + (size_t)gr * K + k0 + ac);
            As[ac + 0][r] = v.x; As[ac + 1][r] = v.y;
            As[ac + 2][r] = v.z; As[ac + 3][r] = v.w;
        }
        {
            int gc = bn + bc;
            float4 v = make_float4(0.f, 0.f, 0.f, 0.f);
            if (gc < N) v = *(const float4*)(B + (size_t)(k0 + br) * N + gc);
            *(float4*)&Bs[br][bc] = v;
        }
        __syncthreads();
#pragma unroll
        for (int kk = 0; kk < BK; ++kk) {
            float aF[TM], bF[TN];
#pragma unroll
            for (int i = 0; i < TM; ++i) aF[i] = As[kk][ty * TM + i];
#pragma unroll
            for (int j = 0; j < TN; ++j) bF[j] = Bs[kk][tx * TN + j];
#pragma unroll
            for (int i = 0; i < TM; ++i)
#pragma unroll
                for (int j = 0; j < TN; ++j) acc[i][j] = fmaf(aF[i], bF[j], acc[i][j]);
        }
        __syncthreads();
    }
    const int col = bn + tx * TN;
    if (col < N) {
        float4 bv = make_float4(0.f, 0.f, 0.f, 0.f);
        if (bias) bv = *(const float4*)(bias + col);
#pragma unroll
        for (int i = 0; i < TM; ++i) {
            int row = bm + ty * TM + i;
            if (row >= M) continue;
            float* cp = C + (size_t)row * N + col;
            float4 v = make_float4(acc[i][0] + bv.x, acc[i][1] + bv.y,
                                   acc[i][2] + bv.z, acc[i][3] + bv.w);
            if (accum) {
                float4 o = *(const float4*)cp;
                v.x += o.x; v.y += o.y; v.z += o.z; v.w += o.w;
            }
            if (relu) {
                v.x = fmaxf(v.x, 0.f); v.y = fmaxf(v.y, 0.f);
                v.z = fmaxf(v.z, 0.f); v.w = fmaxf(v.w, 0.f);
            }
            *(float4*)cp = v;
        }
    }
}

// ---------------- fused relu+residual+LayerNorm ----------------
__global__ void k_ln(const float* __restrict__ t, float* __restrict__ h,
                     const float* __restrict__ g, const float* __restrict__ b, int rows) {
    int w = (blockIdx.x * blockDim.x + threadIdx.x) >> 5;
    int lane = threadIdx.x & 31;
    if (w >= rows) return;
    const float4* t4 = (const float4*)(t + (size_t)w * HD);
    float4* h4 = (float4*)(h + (size_t)w * HD);
    float4 x0 = t4[lane], x1 = t4[lane + 32];
    float4 p0 = h4[lane], p1 = h4[lane + 32];
    float u[8];
    u[0] = fmaxf(x0.x, 0.f) + p0.x; u[1] = fmaxf(x0.y, 0.f) + p0.y;
    u[2] = fmaxf(x0.z, 0.f) + p0.z; u[3] = fmaxf(x0.w, 0.f) + p0.w;
    u[4] = fmaxf(x1.x, 0.f) + p1.x; u[5] = fmaxf(x1.y, 0.f) + p1.y;
    u[6] = fmaxf(x1.z, 0.f) + p1.z; u[7] = fmaxf(x1.w, 0.f) + p1.w;
    float s = 0.f;
#pragma unroll
    for (int i = 0; i < 8; ++i) s += u[i];
    s = warp_sum(s);
    float mu = s * (1.f / HD);
    float v = 0.f;
#pragma unroll
    for (int i = 0; i < 8; ++i) { float d = u[i] - mu; v += d * d; }
    v = warp_sum(v);
    float rstd = rsqrtf(v * (1.f / HD) + 1e-5f);
    const float4* g4 = (const float4*)g;
    const float4* b4 = (const float4*)b;
    float4 ga = g4[lane], gb = g4[lane + 32];
    float4 ba = b4[lane], bb = b4[lane + 32];
    float4 o0, o1;
    o0.x = (u[0] - mu) * rstd * ga.x + ba.x; o0.y = (u[1] - mu) * rstd * ga.y + ba.y;
    o0.z = (u[2] - mu) * rstd * ga.z + ba.z; o0.w = (u[3] - mu) * rstd * ga.w + ba.w;
    o1.x = (u[4] - mu) * rstd * gb.x + bb.x; o1.y = (u[5] - mu) * rstd * gb.y + bb.y;
    o1.z = (u[6] - mu) * rstd * gb.z + bb.z; o1.w = (u[7] - mu) * rstd * gb.w + bb.w;
    h4[lane] = o0;
    h4[lane + 32] = o1;
}

__global__ void k_lsm(float* __restrict__ x, int rows) {
    int w = (blockIdx.x * blockDim.x + threadIdx.x) >> 5;
    int lane = threadIdx.x & 31;
    if (w >= rows) return;
    float* r = x + (size_t)w * CN;
    float v0 = r[lane];
    bool has1 = (lane + 32) < CN;
    float v1 = has1 ? r[lane + 32] : -3.4e38f;
    float m = warp_max(fmaxf(v0, v1));
    float s = expf(v0 - m) + (has1 ? expf(v1 - m) : 0.f);
    s = warp_sum(s);
    float lse = m + logf(s);
    r[lane] = v0 - lse;
    if (has1) r[lane + 32] = v1 - lse;
}

__global__ void k_combine(const float* __restrict__ w0, const float* __restrict__ w1,
                          float* __restrict__ wo, const float* __restrict__ b0,
                          const float* __restrict__ b1, float* __restrict__ bo) {
    int i = blockIdx.x * blockDim.x + threadIdx.x;
    if (i < HD * HD) wo[i] = w0[i] + w1[i];
    if (i < HD) bo[i] = b0[i] + b1[i];
}

// ---------------- host ----------------
static inline void gemm(const float* A, const float* B, const float* bias,
                        float* C, int M, int N, int K, int accum, int relu) {
    if ((N & 127) == 0 && (K & 31) == 0) {
        dim3 grid(N >> 7, (M + 127) >> 7);
        k_hgemm<<<grid, 256, 2 * STAGE>>>(A, B, bias, C, M, N, K, accum, relu);
    } else {
        dim3 grid((N + BN - 1) / BN, (M + BM - 1) / BM);
        k_sgemm<<<grid, 256>>>(A, B, bias, C, M, N, K, accum, relu);
    }
}

extern "C" void kernel_launch(void* const* d_in, const int* in_sizes, int n_in,
                              void* d_out, int out_size) {
    const float* x_author     = (const float*)d_in[0];
    const float* x_paper      = (const float*)d_in[1];
    const int*   e0_src       = (const int*)d_in[2];
    const int*   e0_dst       = (const int*)d_in[3];
    const int*   e1_src       = (const int*)d_in[4];
    const int*   e1_dst       = (const int*)d_in[5];
    const int*   e2_src       = (const int*)d_in[6];
    const int*   e2_dst       = (const int*)d_in[7];
    const float* emb_W_author = (const float*)d_in[8];
    const float* emb_b_author = (const float*)d_in[9];
    const float* emb_W_paper  = (const float*)d_in[10];
    const float* emb_b_paper  = (const float*)d_in[11];
    const float* W_self       = (const float*)d_in[12];
    const float* W_neigh      = (const float*)d_in[13];
    const float* b_conv       = (const float*)d_in[14];
    const float* ln_g_author  = (const float*)d_in[15];
    const float* ln_b_author  = (const float*)d_in[16];
    const float* ln_g_paper   = (const float*)d_in[17];
    const float* ln_b_paper   = (const float*)d_in[18];
    const float* pW1_author   = (const float*)d_in[19];
    const float* pb1_author   = (const float*)d_in[20];
    const float* pW2_author   = (const float*)d_in[21];
    const float* pb2_author   = (const float*)d_in[22];
    const float* pW1_paper    = (const float*)d_in[23];
    const float* pb1_paper    = (const float*)d_in[24];
    const float* pW2_paper    = (const float*)d_in[25];
    const float* pb2_paper    = (const float*)d_in[26];

    cudaFuncSetAttribute(k_hgemm, cudaFuncAttributeMaxDynamicSharedMemorySize, 2 * STAGE);

    float *p_ha, *p_hp, *p_agg, *p_ta, *p_tp, *p_ws01, *p_b01;
    int *p_deg, *p_off, *p_cur, *p_perm;
    cudaGetSymbolAddress((void**)&p_ha, g_ha);
    cudaGetSymbolAddress((void**)&p_hp, g_hp);
    cudaGetSymbolAddress((void**)&p_agg, g_agg);
    cudaGetSymbolAddress((void**)&p_ta, g_ta);
    cudaGetSymbolAddress((void**)&p_tp, g_tp);
    cudaGetSymbolAddress((void**)&p_ws01, g_ws01);
    cudaGetSymbolAddress((void**)&p_b01, g_b01);
    cudaGetSymbolAddress((void**)&p_deg, g_deg);
    cudaGetSymbolAddress((void**)&p_off, g_off);
    cudaGetSymbolAddress((void**)&p_cur, g_cur);
    cudaGetSymbolAddress((void**)&p_perm, g_perm);

    const int* srcs[3] = {e0_src, e1_src, e2_src};
    const int* dsts[3] = {e0_dst, e1_dst, e2_dst};
    const int ndsts[3] = {PN, PN, AN};
    const int EB = (EN + 255) / 256;
    for (int t = 0; t < 3; ++t) {
        int* deg = p_deg + t * PN;
        int* off = p_off + t * (PN + 1);
        int* cur = p_cur + t * PN;
        int* perm = p_perm + t * EN;
        int nd = ndsts[t];
        int NB = (nd + 255) / 256;
        k_zero_int<<<NB, 256>>>(deg, nd);
        k_hist<<<EB, 256>>>(dsts[t], deg, EN);
        k_scan<<<1, 1024>>>(deg, off, nd);
        k_copy_int<<<NB, 256>>>(off, cur, nd);
        k_fill<<<EB, 256>>>(srcs[t], dsts[t], cur, perm, EN);
    }

    gemm(x_author, emb_W_author, emb_b_author, p_ha, AN, HD, DIN, 0, 0);
    gemm(x_paper, emb_W_paper, emb_b_paper, p_hp, PN, HD, DIN, 0, 0);

    const int AGG_BLK = 128;
    for (int l = 0; l < 2; ++l) {
        const float* Ws = W_self + (size_t)l * 3 * HD * HD;
        const float* Wn = W_neigh + (size_t)l * 3 * HD * HD;
        const float* bc = b_conv + (size_t)l * 3 * HD;

        k_combine<<<(HD * HD + 255) / 256, 256>>>(Ws, Ws + HD * HD, p_ws01, bc, bc + HD, p_b01);

        gemm(p_hp, p_ws01, p_b01, p_tp, PN, HD, HD, 0, 0);
        k_agg<<<(PN * 32 + AGG_BLK - 1) / AGG_BLK, AGG_BLK>>>(
            p_ha, p_off + 0 * (PN + 1), p_perm + 0 * EN, p_agg, PN);
        gemm(p_agg, Wn, nullptr, p_tp, PN, HD, HD, 1, 0);
        k_agg<<<(PN * 32 + AGG_BLK - 1) / AGG_BLK, AGG_BLK>>>(
            p_hp, p_off + 1 * (PN + 1), p_perm + 1 * EN, p_agg, PN);
        gemm(p_agg, Wn + HD * HD, nullptr, p_tp, PN, HD, HD, 1, 0);

        gemm(p_ha, Ws + 2 * HD * HD, bc + 2 * HD, p_ta, AN, HD, HD, 0, 0);
        k_agg<<<(AN * 32 + AGG_BLK - 1) / AGG_BLK, AGG_BLK>>>(
            p_hp, p_off + 2 * (PN + 1), p_perm + 2 * EN, p_agg, AN);
        gemm(p_agg, Wn + 2 * HD * HD, nullptr, p_ta, AN, HD, HD, 1, 0);

        k_ln<<<(AN * 32 + 127) / 128, 128>>>(p_ta, p_ha, ln_g_author, ln_b_author, AN);
        k_ln<<<(PN * 32 + 127) / 128, 128>>>(p_tp, p_hp, ln_g_paper, ln_b_paper, PN);
    }

    float* out = (float*)d_out;
    gemm(p_ha, pW1_author, pb1_author, p_ta, AN, HD, HD, 0, 1);
    gemm(p_ta, pW2_author, pb2_author, out, AN, CN, HD, 0, 0);
    k_lsm<<<(AN * 32 + 127) / 128, 128>>>(out, AN);
    gemm(p_hp, pW1_paper, pb1_paper, p_tp, PN, HD, HD, 0, 1);
    gemm(p_tp, pW2_paper, pb2_paper, out + (size_t)AN * CN, PN, HD, HD, 0, 0);
}

// round 6
// speedup vs baseline: 1.7180x; 1.0756x over previous
#include <cuda_runtime.h>
#include <cuda_bf16.h>
#include <math.h>

#define AN 50000
#define PN 100000
#define DIN 128
#define HD 256
#define CN 40
#define EN 300000

typedef unsigned short ushortx;

// fp32 state
__device__ float g_ha[(size_t)AN * HD];
__device__ float g_hp[(size_t)PN * HD];
__device__ float g_ta[(size_t)AN * HD];
__device__ float g_tp[(size_t)PN * HD];
__device__ float g_b01[2 * HD];
// bf16 hi/lo operand buffers
__device__ ushortx g_xah[(size_t)AN * DIN], g_xal[(size_t)AN * DIN];
__device__ ushortx g_xph[(size_t)PN * DIN], g_xpl[(size_t)PN * DIN];
__device__ ushortx g_hah[(size_t)AN * HD],  g_hal[(size_t)AN * HD];
__device__ ushortx g_hph[(size_t)PN * HD],  g_hpl[(size_t)PN * HD];
__device__ ushortx g_ag0h[(size_t)PN * HD], g_ag0l[(size_t)PN * HD];
__device__ ushortx g_ag1h[(size_t)PN * HD], g_ag1l[(size_t)PN * HD];
// split weights, stacked segments
#define WOFF_EMBA 0
#define WOFF_EMBP (WOFF_EMBA + 128 * 256)
#define WOFF_WP0  (WOFF_EMBP + 128 * 256)
#define WOFF_WA0  (WOFF_WP0 + 768 * 256)
#define WOFF_WP1  (WOFF_WA0 + 512 * 256)
#define WOFF_WA1  (WOFF_WP1 + 768 * 256)
#define WOFF_P1A  (WOFF_WA1 + 512 * 256)
#define WOFF_P1P  (WOFF_P1A + 256 * 256)
#define WOFF_P2P  (WOFF_P1P + 256 * 256)
#define WTOT      (WOFF_P2P + 256 * 256)
__device__ ushortx g_wh[WTOT], g_wl[WTOT];
// CSR
__device__ int g_deg[3 * PN];
__device__ int g_off[3 * (PN + 1)];
__device__ int g_cur[3 * PN];
__device__ int g_perm[3 * EN];

// ---------------- helpers ----------------
__device__ __forceinline__ unsigned smem_u32(const void* p) {
    unsigned a;
    asm("{ .reg .u64 t; cvta.to.shared.u64 t, %1; cvt.u32.u64 %0, t; }" : "=r"(a) : "l"(p));
    return a;
}
__device__ __forceinline__ void cp16(unsigned dst, const void* src, int n) {
    asm volatile("cp.async.cg.shared.global [%0], [%1], 16, %2;" :: "r"(dst), "l"(src), "r"(n));
}
#define CP_COMMIT() asm volatile("cp.async.commit_group;" ::: "memory")
#define CP_WAIT1()  asm volatile("cp.async.wait_group 1;" ::: "memory")

__device__ __forceinline__ void bsplit(float x, float y, unsigned& h, unsigned& l) {
    __nv_bfloat162 hb = __floats2bfloat162_rn(x, y);
    float rx = x - __bfloat162float(hb.x);
    float ry = y - __bfloat162float(hb.y);
    __nv_bfloat162 lb = __floats2bfloat162_rn(rx, ry);
    h = *(unsigned*)&hb;
    l = *(unsigned*)&lb;
}
#define MMA16816(c, a, b) \
    asm volatile("mma.sync.aligned.m16n8k16.row.col.f32.bf16.bf16.f32 " \
        "{%0,%1,%2,%3},{%4,%5,%6,%7},{%8,%9},{%0,%1,%2,%3};" \
        : "+f"((c)[0]), "+f"((c)[1]), "+f"((c)[2]), "+f"((c)[3]) \
        : "r"((a)[0]), "r"((a)[1]), "r"((a)[2]), "r"((a)[3]), "r"((b)[0]), "r"((b)[1]))
#define LDSM4(r, addr) \
    asm volatile("ldmatrix.sync.aligned.m8n8.x4.shared.b16 {%0,%1,%2,%3},[%4];" \
        : "=r"((r)[0]), "=r"((r)[1]), "=r"((r)[2]), "=r"((r)[3]) : "r"(addr))
#define LDSM4T(r, addr) \
    asm volatile("ldmatrix.sync.aligned.m8n8.x4.trans.shared.b16 {%0,%1,%2,%3},[%4];" \
        : "=r"((r)[0]), "=r"((r)[1]), "=r"((r)[2]), "=r"((r)[3]) : "r"(addr))

__device__ __forceinline__ float warp_sum(float v) {
#pragma unroll
    for (int o = 16; o; o >>= 1) v += __shfl_xor_sync(0xffffffffu, v, o);
    return v;
}
__device__ __forceinline__ float warp_max(float v) {
#pragma unroll
    for (int o = 16; o; o >>= 1) v = fmaxf(v, __shfl_xor_sync(0xffffffffu, v, o));
    return v;
}

// ---------------- prep: fp32 -> bf16 hi/lo split ----------------
__global__ void k_wsplit(const float* __restrict__ s, ushortx* __restrict__ dh,
                         ushortx* __restrict__ dl, int n) {
    int i = blockIdx.x * blockDim.x + threadIdx.x;
    if (i >= n) return;
    float v = s[i];
    __nv_bfloat16 h = __float2bfloat16(v);
    __nv_bfloat16 l = __float2bfloat16(v - __bfloat162float(h));
    dh[i] = *(ushortx*)&h;
    dl[i] = *(ushortx*)&l;
}
__global__ void k_wsplit_add(const float* __restrict__ a, const float* __restrict__ b,
                             ushortx* __restrict__ dh, ushortx* __restrict__ dl, int n) {
    int i = blockIdx.x * blockDim.x + threadIdx.x;
    if (i >= n) return;
    float v = a[i] + b[i];
    __nv_bfloat16 h = __float2bfloat16(v);
    __nv_bfloat16 l = __float2bfloat16(v - __bfloat162float(h));
    dh[i] = *(ushortx*)&h;
    dl[i] = *(ushortx*)&l;
}
__global__ void k_badd(const float* __restrict__ a, const float* __restrict__ b,
                       float* __restrict__ o, int n) {
    int i = blockIdx.x * blockDim.x + threadIdx.x;
    if (i < n) o[i] = a[i] + b[i];
}

// ---------------- CSR build ----------------
__global__ void k_zero_int(int* __restrict__ p, int n) {
    int i = blockIdx.x * blockDim.x + threadIdx.x;
    if (i < n) p[i] = 0;
}
__global__ void k_hist(const int* __restrict__ dst, int* __restrict__ deg, int n) {
    int i = blockIdx.x * blockDim.x + threadIdx.x;
    if (i < n) atomicAdd(&deg[dst[i]], 1);
}
__global__ void k_scan(const int* __restrict__ deg, int* __restrict__ off, int n) {
    __shared__ int part[1024];
    int tid = threadIdx.x;
    int chunk = (n + 1023) >> 10;
    int s = tid * chunk, e = min(s + chunk, n);
    int sum = 0;
    for (int i = s; i < e; ++i) sum += deg[i];
    part[tid] = sum;
    __syncthreads();
#pragma unroll
    for (int d = 1; d < 1024; d <<= 1) {
        int v = (tid >= d) ? part[tid - d] : 0;
        __syncthreads();
        part[tid] += v;
        __syncthreads();
    }
    int run = (tid == 0) ? 0 : part[tid - 1];
    for (int i = s; i < e; ++i) { off[i] = run; run += deg[i]; }
    if (tid == 0) off[n] = part[1023];
}
__global__ void k_copy_int(const int* __restrict__ a, int* __restrict__ b, int n) {
    int i = blockIdx.x * blockDim.x + threadIdx.x;
    if (i < n) b[i] = a[i];
}
__global__ void k_fill(const int* __restrict__ src, const int* __restrict__ dst,
                       int* __restrict__ cur, int* __restrict__ perm, int n) {
    int i = blockIdx.x * blockDim.x + threadIdx.x;
    if (i < n) { int slot = atomicAdd(&cur[dst[i]], 1); perm[slot] = src[i]; }
}

// ---------------- mean aggregation: fp32 gather -> bf16 hi/lo out ----------
__global__ void k_agg(const float* __restrict__ h, const int* __restrict__ off,
                      const int* __restrict__ perm, ushortx* __restrict__ oh,
                      ushortx* __restrict__ ol, int ndst) {
    int w = (blockIdx.x * blockDim.x + threadIdx.x) >> 5;
    int lane = threadIdx.x & 31;
    if (w >= ndst) return;
    int s = off[w], e = off[w + 1];
    float4 a0 = make_float4(0.f, 0.f, 0.f, 0.f);
    float4 a1 = make_float4(0.f, 0.f, 0.f, 0.f);
    for (int i = s; i < e; ++i) {
        const float4* r = (const float4*)(h + (size_t)perm[i] * HD);
        float4 v0 = __ldg(&r[lane]);
        float4 v1 = __ldg(&r[lane + 32]);
        a0.x += v0.x; a0.y += v0.y; a0.z += v0.z; a0.w += v0.w;
        a1.x += v1.x; a1.y += v1.y; a1.z += v1.z; a1.w += v1.w;
    }
    float inv = (e > s) ? 1.f / (float)(e - s) : 0.f;
    a0.x *= inv; a0.y *= inv; a0.z *= inv; a0.w *= inv;
    a1.x *= inv; a1.y *= inv; a1.z *= inv; a1.w *= inv;
    unsigned h0, l0, h1, l1;
    unsigned* ohu = (unsigned*)(oh + (size_t)w * HD);
    unsigned* olu = (unsigned*)(ol + (size_t)w * HD);
    bsplit(a0.x, a0.y, h0, l0); bsplit(a0.z, a0.w, h1, l1);
    ohu[lane * 2] = h0; ohu[lane * 2 + 1] = h1;
    olu[lane * 2] = l0; olu[lane * 2 + 1] = l1;
    bsplit(a1.x, a1.y, h0, l0); bsplit(a1.z, a1.w, h1, l1);
    ohu[64 + lane * 2] = h0; ohu[64 + lane * 2 + 1] = h1;
    olu[64 + lane * 2] = l0; olu[64 + lane * 2 + 1] = l1;
}

// ---------------- bf16-input HMMA 3-split GEMM, cp.async 3-stage ----------
// C = sum_seg A_seg[M,Kseg] @ B[Ktot,N]  (+bias)(relu). N%128==0, Kseg%32==0.
// A given as bf16 hi/lo pairs per segment; B as stacked split weights.
#define A_ST 80
#define B_ST 272
#define OFF_AL 10240
#define OFF_BH 20480
#define OFF_BL 29184
#define STAGE 37888
#define NSTAGE 3

__global__ __launch_bounds__(256, 1) void k_bgemm(
    const ushortx* __restrict__ ah0, const ushortx* __restrict__ al0,
    const ushortx* __restrict__ ah1, const ushortx* __restrict__ al1,
    const ushortx* __restrict__ ah2, const ushortx* __restrict__ al2,
    const ushortx* __restrict__ Bh, const ushortx* __restrict__ Bl,
    const float* __restrict__ bias, float* __restrict__ C,
    ushortx* __restrict__ Ch, ushortx* __restrict__ Cl,
    int M, int N, int Ktot, int Kseg, int relu) {
    extern __shared__ char smc[];
    const int tid = threadIdx.x;
    const int lane = tid & 31;
    const int warp = tid >> 5;
    const int g = lane >> 2;
    const int t = lane & 3;
    const int wm = warp & 1;
    const int wn = warp >> 1;
    const int bm = blockIdx.y * 128;
    const int bn = blockIdx.x * 128;
    const unsigned sbase = smem_u32(smc);
    const int NIT = Ktot >> 5;
    const int segC = Kseg >> 5;

    float acc[4][4][4];
#pragma unroll
    for (int i = 0; i < 4; ++i)
#pragma unroll
        for (int j = 0; j < 4; ++j)
#pragma unroll
            for (int q = 0; q < 4; ++q) acc[i][j][q] = 0.f;

    // per-thread chunk slots
    const int ca = tid * 2;            // A: 512 chunks of 16B per buf
    const int arow0 = ca >> 2, ac0 = ca & 3;
    const int arow1 = (ca + 1) >> 2, ac1 = (ca + 1) & 3;
    const int cb = tid * 2;            // B: 512 chunks
    const int brow0 = cb >> 4, bc0 = cb & 15;
    const int brow1 = (cb + 1) >> 4, bc1 = (cb + 1) & 15;

    auto issue = [&](int it) {
        int seg = it / segC;
        int kloc = (it - seg * segC) << 5;
        const ushortx* pah = (seg == 0) ? ah0 : ((seg == 1) ? ah1 : ah2);
        const ushortx* pal = (seg == 0) ? al0 : ((seg == 1) ? al1 : al2);
        unsigned sa = sbase + (it % NSTAGE) * STAGE;
        int gr0 = bm + arow0, gr1 = bm + arow1;
        int ok0 = gr0 < M ? 16 : 0, ok1 = gr1 < M ? 16 : 0;
        size_t off0 = (size_t)(gr0 < M ? gr0 : 0) * Kseg + kloc + ac0 * 8;
        size_t off1 = (size_t)(gr1 < M ? gr1 : 0) * Kseg + kloc + ac1 * 8;
        cp16(sa + arow0 * A_ST + ac0 * 16, pah + off0, ok0);
        cp16(sa + arow1 * A_ST + ac1 * 16, pah + off1, ok1);
        cp16(sa + OFF_AL + arow0 * A_ST + ac0 * 16, pal + off0, ok0);
        cp16(sa + OFF_AL + arow1 * A_ST + ac1 * 16, pal + off1, ok1);
        int kg = it << 5;
        size_t bo0 = (size_t)(kg + brow0) * N + bn + bc0 * 8;
        size_t bo1 = (size_t)(kg + brow1) * N + bn + bc1 * 8;
        cp16(sa + OFF_BH + brow0 * B_ST + bc0 * 16, Bh + bo0, 16);
        cp16(sa + OFF_BH + brow1 * B_ST + bc1 * 16, Bh + bo1, 16);
        cp16(sa + OFF_BL + brow0 * B_ST + bc0 * 16, Bl + bo0, 16);
        cp16(sa + OFF_BL + brow1 * B_ST + bc1 * 16, Bl + bo1, 16);
        CP_COMMIT();
    };

    issue(0);
    issue(1);
    for (int it = 0; it < NIT; ++it) {
        CP_WAIT1();            // stage it complete (2 groups always pending)
        __syncthreads();
        if (it + 2 < NIT) issue(it + 2);
        else CP_COMMIT();      // keep group arithmetic constant
        const unsigned sa = sbase + (it % NSTAGE) * STAGE;
#pragma unroll
        for (int kk = 0; kk < 2; ++kk) {
            unsigned ah[4][4], al[4][4], bh[2][4], bl[2][4];
            unsigned abase = sa + (wm * 64 + (lane & 15)) * A_ST + kk * 32 + ((lane >> 4) << 4);
#pragma unroll
            for (int i = 0; i < 4; ++i) {
                LDSM4(ah[i], abase + i * (16 * A_ST));
                LDSM4(al[i], abase + i * (16 * A_ST) + OFF_AL);
            }
            unsigned bbase = sa + OFF_BH + (kk * 16 + (lane & 15)) * B_ST +
                             (wn * 32 + ((lane >> 4) << 3)) * 2;
#pragma unroll
            for (int p = 0; p < 2; ++p) {
                LDSM4T(bh[p], bbase + p * 32);
                LDSM4T(bl[p], bbase + p * 32 + (OFF_BL - OFF_BH));
            }
#pragma unroll
            for (int i = 0; i < 4; ++i)
#pragma unroll
                for (int j = 0; j < 4; ++j) {
                    unsigned* bhj = &bh[j >> 1][(j & 1) * 2];
                    unsigned* blj = &bl[j >> 1][(j & 1) * 2];
                    MMA16816(acc[i][j], ah[i], bhj);
                    MMA16816(acc[i][j], ah[i], blj);
                    MMA16816(acc[i][j], al[i], bhj);
                }
        }
        __syncthreads();
    }

    // epilogue: bias, relu, fp32 store and/or bf16 split store
#pragma unroll
    for (int i = 0; i < 4; ++i) {
        int r0 = bm + wm * 64 + i * 16 + g;
#pragma unroll
        for (int j = 0; j < 4; ++j) {
            int cn = bn + wn * 32 + j * 8 + 2 * t;
            float2 bv = make_float2(0.f, 0.f);
            if (bias) bv = *(const float2*)(bias + cn);
#pragma unroll
            for (int h = 0; h < 2; ++h) {
                int row = r0 + h * 8;
                if (row >= M) continue;
                float vx = acc[i][j][h * 2 + 0] + bv.x;
                float vy = acc[i][j][h * 2 + 1] + bv.y;
                if (relu) { vx = fmaxf(vx, 0.f); vy = fmaxf(vy, 0.f); }
                size_t o = (size_t)row * N + cn;
                if (C) *(float2*)(C + o) = make_float2(vx, vy);
                if (Ch) {
                    unsigned hh, ll;
                    bsplit(vx, vy, hh, ll);
                    *(unsigned*)(Ch + o) = hh;
                    *(unsigned*)(Cl + o) = ll;
                }
            }
        }
    }
}

// ---------------- fp32 SGEMM (N=40 head only) ----------------
#define BM 128
#define BN 64
#define BK 16
#define TM 8
#define TN 4
__global__ __launch_bounds__(256) void k_sgemm(
    const float* __restrict__ A, const float* __restrict__ B,
    const float* __restrict__ bias, float* __restrict__ C,
    int M, int N, int K) {
    __shared__ float As[BK][BM];
    __shared__ float Bs[BK][BN];
    const int tid = threadIdx.x;
    const int tx = tid & 15, ty = tid >> 4;
    const int bm = blockIdx.y * BM, bn = blockIdx.x * BN;
    float acc[TM][TN];
#pragma unroll
    for (int i = 0; i < TM; ++i)
#pragma unroll
        for (int j = 0; j < TN; ++j) acc[i][j] = 0.f;
    const int ar = tid >> 2, ac = (tid & 3) << 2;
    const int br = tid >> 4, bc = (tid & 15) << 2;
    for (int k0 = 0; k0 < K; k0 += BK) {
#pragma unroll
        for (int h = 0; h < 2; ++h) {
            int r = ar + h * 64, gr = bm + r;
            float4 v = make_float4(0.f, 0.f, 0.f, 0.f);
            if (gr < M) v = *(const float4*)(A + (size_t)gr * K + k0 + ac);
            As[ac + 0][r] = v.x; As[ac + 1][r] = v.y;
            As[ac + 2][r] = v.z; As[ac + 3][r] = v.w;
        }
        {
            int gc = bn + bc;
            float4 v = make_float4(0.f, 0.f, 0.f, 0.f);
            if (gc < N) v = *(const float4*)(B + (size_t)(k0 + br) * N + gc);
            *(float4*)&Bs[br][bc] = v;
        }
        __syncthreads();
#pragma unroll
        for (int kk = 0; kk < BK; ++kk) {
            float aF[TM], bF[TN];
#pragma unroll
            for (int i = 0; i < TM; ++i) aF[i] = As[kk][ty * TM + i];
#pragma unroll
            for (int j = 0; j < TN; ++j) bF[j] = Bs[kk][tx * TN + j];
#pragma unroll
            for (int i = 0; i < TM; ++i)
#pragma unroll
                for (int j = 0; j < TN; ++j) acc[i][j] = fmaf(aF[i], bF[j], acc[i][j]);
        }
        __syncthreads();
    }
    const int col = bn + tx * TN;
    if (col < N) {
        float4 bv = make_float4(0.f, 0.f, 0.f, 0.f);
        if (bias) bv = *(const float4*)(bias + col);
#pragma unroll
        for (int i = 0; i < TM; ++i) {
            int row = bm + ty * TM + i;
            if (row >= M) continue;
            *(float4*)(C + (size_t)row * N + col) =
                make_float4(acc[i][0] + bv.x, acc[i][1] + bv.y,
                            acc[i][2] + bv.z, acc[i][3] + bv.w);
        }
    }
}

// ---------------- fused relu+residual+LayerNorm + split ----------------
__global__ void k_ln(const float* __restrict__ t, float* __restrict__ h,
                     ushortx* __restrict__ hh, ushortx* __restrict__ hl,
                     const float* __restrict__ g, const float* __restrict__ b, int rows) {
    int w = (blockIdx.x * blockDim.x + threadIdx.x) >> 5;
    int lane = threadIdx.x & 31;
    if (w >= rows) return;
    const float4* t4 = (const float4*)(t + (size_t)w * HD);
    float4* h4 = (float4*)(h + (size_t)w * HD);
    float4 x0 = t4[lane], x1 = t4[lane + 32];
    float4 p0 = h4[lane], p1 = h4[lane + 32];
    float u[8];
    u[0] = fmaxf(x0.x, 0.f) + p0.x; u[1] = fmaxf(x0.y, 0.f) + p0.y;
    u[2] = fmaxf(x0.z, 0.f) + p0.z; u[3] = fmaxf(x0.w, 0.f) + p0.w;
    u[4] = fmaxf(x1.x, 0.f) + p1.x; u[5] = fmaxf(x1.y, 0.f) + p1.y;
    u[6] = fmaxf(x1.z, 0.f) + p1.z; u[7] = fmaxf(x1.w, 0.f) + p1.w;
    float s = 0.f;
#pragma unroll
    for (int i = 0; i < 8; ++i) s += u[i];
    s = warp_sum(s);
    float mu = s * (1.f / HD);
    float v = 0.f;
#pragma unroll
    for (int i = 0; i < 8; ++i) { float d = u[i] - mu; v += d * d; }
    v = warp_sum(v);
    float rstd = rsqrtf(v * (1.f / HD) + 1e-5f);
    const float4* g4 = (const float4*)g;
    const float4* b4 = (const float4*)b;
    float4 ga = g4[lane], gb = g4[lane + 32];
    float4 ba = b4[lane], bb = b4[lane + 32];
    float o[8];
    o[0] = (u[0] - mu) * rstd * ga.x + ba.x; o[1] = (u[1] - mu) * rstd * ga.y + ba.y;
    o[2] = (u[2] - mu) * rstd * ga.z + ba.z; o[3] = (u[3] - mu) * rstd * ga.w + ba.w;
    o[4] = (u[4] - mu) * rstd * gb.x + bb.x; o[5] = (u[5] - mu) * rstd * gb.y + bb.y;
    o[6] = (u[6] - mu) * rstd * gb.z + bb.z; o[7] = (u[7] - mu) * rstd * gb.w + bb.w;
    h4[lane] = make_float4(o[0], o[1], o[2], o[3]);
    h4[lane + 32] = make_float4(o[4], o[5], o[6], o[7]);
    unsigned* hhu = (unsigned*)(hh + (size_t)w * HD);
    unsigned* hlu = (unsigned*)(hl + (size_t)w * HD);
    unsigned hv0, lv0, hv1, lv1;
    bsplit(o[0], o[1], hv0, lv0); bsplit(o[2], o[3], hv1, lv1);
    hhu[lane * 2] = hv0; hhu[lane * 2 + 1] = hv1;
    hlu[lane * 2] = lv0; hlu[lane * 2 + 1] = lv1;
    bsplit(o[4], o[5], hv0, lv0); bsplit(o[6], o[7], hv1, lv1);
    hhu[64 + lane * 2] = hv0; hhu[64 + lane * 2 + 1] = hv1;
    hlu[64 + lane * 2] = lv0; hlu[64 + lane * 2 + 1] = lv1;
}

__global__ void k_lsm(float* __restrict__ x, int rows) {
    int w = (blockIdx.x * blockDim.x + threadIdx.x) >> 5;
    int lane = threadIdx.x & 31;
    if (w >= rows) return;
    float* r = x + (size_t)w * CN;
    float v0 = r[lane];
    bool has1 = (lane + 32) < CN;
    float v1 = has1 ? r[lane + 32] : -3.4e38f;
    float m = warp_max(fmaxf(v0, v1));
    float s = expf(v0 - m) + (has1 ? expf(v1 - m) : 0.f);
    s = warp_sum(s);
    float lse = m + logf(s);
    r[lane] = v0 - lse;
    if (has1) r[lane + 32] = v1 - lse;
}

// ---------------- host ----------------
static inline void bgemm(const ushortx* ah0, const ushortx* al0,
                         const ushortx* ah1, const ushortx* al1,
                         const ushortx* ah2, const ushortx* al2,
                         const ushortx* Bh, const ushortx* Bl,
                         const float* bias, float* C, ushortx* Ch, ushortx* Cl,
                         int M, int N, int Ktot, int Kseg, int relu) {
    dim3 grid(N >> 7, (M + 127) >> 7);
    k_bgemm<<<grid, 256, NSTAGE * STAGE>>>(ah0, al0, ah1, al1, ah2, al2,
                                           Bh, Bl, bias, C, Ch, Cl,
                                           M, N, Ktot, Kseg, relu);
}

extern "C" void kernel_launch(void* const* d_in, const int* in_sizes, int n_in,
                              void* d_out, int out_size) {
    const float* x_author     = (const float*)d_in[0];
    const float* x_paper      = (const float*)d_in[1];
    const int*   e0_src       = (const int*)d_in[2];
    const int*   e0_dst       = (const int*)d_in[3];
    const int*   e1_src       = (const int*)d_in[4];
    const int*   e1_dst       = (const int*)d_in[5];
    const int*   e2_src       = (const int*)d_in[6];
    const int*   e2_dst       = (const int*)d_in[7];
    const float* emb_W_author = (const float*)d_in[8];
    const float* emb_b_author = (const float*)d_in[9];
    const float* emb_W_paper  = (const float*)d_in[10];
    const float* emb_b_paper  = (const float*)d_in[11];
    const float* W_self       = (const float*)d_in[12];
    const float* W_neigh      = (const float*)d_in[13];
    const float* b_conv       = (const float*)d_in[14];
    const float* ln_g_author  = (const float*)d_in[15];
    const float* ln_b_author  = (const float*)d_in[16];
    const float* ln_g_paper   = (const float*)d_in[17];
    const float* ln_b_paper   = (const float*)d_in[18];
    const float* pW1_author   = (const float*)d_in[19];
    const float* pb1_author   = (const float*)d_in[20];
    const float* pW2_author   = (const float*)d_in[21];
    const float* pb2_author   = (const float*)d_in[22];
    const float* pW1_paper    = (const float*)d_in[23];
    const float* pb1_paper    = (const float*)d_in[24];
    const float* pW2_paper    = (const float*)d_in[25];
    const float* pb2_paper    = (const float*)d_in[26];

    cudaFuncSetAttribute(k_bgemm, cudaFuncAttributeMaxDynamicSharedMemorySize, NSTAGE * STAGE);

    float *p_ha, *p_hp, *p_ta, *p_tp, *p_b01;
    ushortx *p_xah, *p_xal, *p_xph, *p_xpl, *p_hah, *p_hal, *p_hph, *p_hpl;
    ushortx *p_ag0h, *p_ag0l, *p_ag1h, *p_ag1l, *p_wh, *p_wl;
    int *p_deg, *p_off, *p_cur, *p_perm;
    cudaGetSymbolAddress((void**)&p_ha, g_ha);
    cudaGetSymbolAddress((void**)&p_hp, g_hp);
    cudaGetSymbolAddress((void**)&p_ta, g_ta);
    cudaGetSymbolAddress((void**)&p_tp, g_tp);
    cudaGetSymbolAddress((void**)&p_b01, g_b01);
    cudaGetSymbolAddress((void**)&p_xah, g_xah);
    cudaGetSymbolAddress((void**)&p_xal, g_xal);
    cudaGetSymbolAddress((void**)&p_xph, g_xph);
    cudaGetSymbolAddress((void**)&p_xpl, g_xpl);
    cudaGetSymbolAddress((void**)&p_hah, g_hah);
    cudaGetSymbolAddress((void**)&p_hal, g_hal);
    cudaGetSymbolAddress((void**)&p_hph, g_hph);
    cudaGetSymbolAddress((void**)&p_hpl, g_hpl);
    cudaGetSymbolAddress((void**)&p_ag0h, g_ag0h);
    cudaGetSymbolAddress((void**)&p_ag0l, g_ag0l);
    cudaGetSymbolAddress((void**)&p_ag1h, g_ag1h);
    cudaGetSymbolAddress((void**)&p_ag1l, g_ag1l);
    cudaGetSymbolAddress((void**)&p_wh, g_wh);
    cudaGetSymbolAddress((void**)&p_wl, g_wl);
    cudaGetSymbolAddress((void**)&p_deg, g_deg);
    cudaGetSymbolAddress((void**)&p_off, g_off);
    cudaGetSymbolAddress((void**)&p_cur, g_cur);
    cudaGetSymbolAddress((void**)&p_perm, g_perm);

    // ---- weight + input splits ----
    const int WB = 256;
    auto nb = [](int n) { return (n + 255) / 256; };
    k_wsplit<<<nb(128 * 256), WB>>>(emb_W_author, p_wh + WOFF_EMBA, p_wl + WOFF_EMBA, 128 * 256);
    k_wsplit<<<nb(128 * 256), WB>>>(emb_W_paper, p_wh + WOFF_EMBP, p_wl + WOFF_EMBP, 128 * 256);
    const int WPO[2] = {WOFF_WP0, WOFF_WP1};
    const int WAO[2] = {WOFF_WA0, WOFF_WA1};
    for (int l = 0; l < 2; ++l) {
        const float* Ws = W_self + (size_t)l * 3 * HD * HD;
        const float* Wn = W_neigh + (size_t)l * 3 * HD * HD;
        const float* bc = b_conv + (size_t)l * 3 * HD;
        k_wsplit_add<<<nb(HD * HD), WB>>>(Ws, Ws + HD * HD,
                                          p_wh + WPO[l], p_wl + WPO[l], HD * HD);
        k_wsplit<<<nb(HD * HD), WB>>>(Wn, p_wh + WPO[l] + HD * HD, p_wl + WPO[l] + HD * HD, HD * HD);
        k_wsplit<<<nb(HD * HD), WB>>>(Wn + HD * HD, p_wh + WPO[l] + 2 * HD * HD,
                                      p_wl + WPO[l] + 2 * HD * HD, HD * HD);
        k_wsplit<<<nb(HD * HD), WB>>>(Ws + 2 * HD * HD, p_wh + WAO[l], p_wl + WAO[l], HD * HD);
        k_wsplit<<<nb(HD * HD), WB>>>(Wn + 2 * HD * HD, p_wh + WAO[l] + HD * HD,
                                      p_wl + WAO[l] + HD * HD, HD * HD);
        k_badd<<<1, 256>>>(bc, bc + HD, p_b01 + l * HD, HD);
    }
    k_wsplit<<<nb(HD * HD), WB>>>(pW1_author, p_wh + WOFF_P1A, p_wl + WOFF_P1A, HD * HD);
    k_wsplit<<<nb(HD * HD), WB>>>(pW1_paper, p_wh + WOFF_P1P, p_wl + WOFF_P1P, HD * HD);
    k_wsplit<<<nb(HD * HD), WB>>>(pW2_paper, p_wh + WOFF_P2P, p_wl + WOFF_P2P, HD * HD);
    k_wsplit<<<nb(AN * DIN), WB>>>(x_author, p_xah, p_xal, AN * DIN);
    k_wsplit<<<nb(PN * DIN), WB>>>(x_paper, p_xph, p_xpl, PN * DIN);

    // ---- CSR build ----
    const int* srcs[3] = {e0_src, e1_src, e2_src};
    const int* dsts[3] = {e0_dst, e1_dst, e2_dst};
    const int ndsts[3] = {PN, PN, AN};
    const int EB = (EN + 255) / 256;
    for (int tt = 0; tt < 3; ++tt) {
        int* deg = p_deg + tt * PN;
        int* off = p_off + tt * (PN + 1);
        int* cur = p_cur + tt * PN;
        int* perm = p_perm + tt * EN;
        int nd = ndsts[tt];
        int NB = (nd + 255) / 256;
        k_zero_int<<<NB, 256>>>(deg, nd);
        k_hist<<<EB, 256>>>(dsts[tt], deg, EN);
        k_scan<<<1, 1024>>>(deg, off, nd);
        k_copy_int<<<NB, 256>>>(off, cur, nd);
        k_fill<<<EB, 256>>>(srcs[tt], dsts[tt], cur, perm, EN);
    }

    // ---- embeddings (fp32 h + split h) ----
    bgemm(p_xah, p_xal, 0, 0, 0, 0, p_wh + WOFF_EMBA, p_wl + WOFF_EMBA,
          emb_b_author, p_ha, p_hah, p_hal, AN, HD, DIN, DIN, 0);
    bgemm(p_xph, p_xpl, 0, 0, 0, 0, p_wh + WOFF_EMBP, p_wl + WOFF_EMBP,
          emb_b_paper, p_hp, p_hph, p_hpl, PN, HD, DIN, DIN, 0);

    // ---- 2 SAGE layers ----
    const int AGG_BLK = 128;
    for (int l = 0; l < 2; ++l) {
        const float* bc = b_conv + (size_t)l * 3 * HD;
        // aggs from pre-update h
        k_agg<<<(PN * 32 + AGG_BLK - 1) / AGG_BLK, AGG_BLK>>>(
            p_ha, p_off + 0 * (PN + 1), p_perm + 0 * EN, p_ag0h, p_ag0l, PN);
        k_agg<<<(PN * 32 + AGG_BLK - 1) / AGG_BLK, AGG_BLK>>>(
            p_hp, p_off + 1 * (PN + 1), p_perm + 1 * EN, p_ag1h, p_ag1l, PN);
        // paper conv: one K=768 GEMM over [hp | agg0 | agg1]
        bgemm(p_hph, p_hpl, p_ag0h, p_ag0l, p_ag1h, p_ag1l,
              p_wh + WPO[l], p_wl + WPO[l], p_b01 + l * HD,
              p_tp, 0, 0, PN, HD, 3 * HD, HD, 0);
        // author agg (reuses ag0 buffers, consumed above)
        k_agg<<<(AN * 32 + AGG_BLK - 1) / AGG_BLK, AGG_BLK>>>(
            p_hp, p_off + 2 * (PN + 1), p_perm + 2 * EN, p_ag0h, p_ag0l, AN);
        // author conv: one K=512 GEMM over [ha | agg2]
        bgemm(p_hah, p_hal, p_ag0h, p_ag0l, 0, 0,
              p_wh + WAO[l], p_wl + WAO[l], bc + 2 * HD,
              p_ta, 0, 0, AN, HD, 2 * HD, HD, 0);
        // relu+residual+LN (+ fresh splits)
        k_ln<<<(AN * 32 + 127) / 128, 128>>>(p_ta, p_ha, p_hah, p_hal,
                                             ln_g_author, ln_b_author, AN);
        k_ln<<<(PN * 32 + 127) / 128, 128>>>(p_tp, p_hp, p_hph, p_hpl,
                                             ln_g_paper, ln_b_paper, PN);
    }

    // ---- output heads ----
    float* out = (float*)d_out;
    // author: relu GEMM -> fp32 tmp -> N=40 sgemm -> log_softmax
    bgemm(p_hah, p_hal, 0, 0, 0, 0, p_wh + WOFF_P1A, p_wl + WOFF_P1A,
          pb1_author, p_ta, 0, 0, AN, HD, HD, HD, 1);
    {
        dim3 grid((CN + BN - 1) / BN, (AN + BM - 1) / BM);
        k_sgemm<<<grid, 256>>>(p_ta, pW2_author, pb2_author, out, AN, CN, HD);
    }
    k_lsm<<<(AN * 32 + 127) / 128, 128>>>(out, AN);
    // paper: relu GEMM emits split A -> second GEMM -> fp32 out
    bgemm(p_hph, p_hpl, 0, 0, 0, 0, p_wh + WOFF_P1P, p_wl + WOFF_P1P,
          pb1_paper, 0, p_ag0h, p_ag0l, PN, HD, HD, HD, 1);
    bgemm(p_ag0h, p_ag0l, 0, 0, 0, 0, p_wh + WOFF_P2P, p_wl + WOFF_P2P,
          pb2_paper, out + (size_t)AN * CN, 0, 0, PN, HD, HD, HD, 0);
}

// round 8
// speedup vs baseline: 1.9284x; 1.1225x over previous
#include <cuda_runtime.h>
#include <cuda_bf16.h>
#include <math.h>

#define AN 50000
#define PN 100000
#define DIN 128
#define HD 256
#define CN 40
#define EN 300000

typedef unsigned short ushortx;

// fp32 state
__device__ float g_ha[(size_t)AN * HD];
__device__ float g_hp[(size_t)PN * HD];
__device__ float g_ta[(size_t)AN * HD];
__device__ float g_tp[(size_t)PN * HD];
__device__ float g_b01[2 * HD];
// bf16 hi/lo operand buffers
__device__ ushortx g_xah[(size_t)AN * DIN], g_xal[(size_t)AN * DIN];
__device__ ushortx g_xph[(size_t)PN * DIN], g_xpl[(size_t)PN * DIN];
__device__ ushortx g_hah[(size_t)AN * HD],  g_hal[(size_t)AN * HD];
__device__ ushortx g_hph[(size_t)PN * HD],  g_hpl[(size_t)PN * HD];
__device__ ushortx g_ag0h[(size_t)PN * HD], g_ag0l[(size_t)PN * HD];
__device__ ushortx g_ag1h[(size_t)PN * HD], g_ag1l[(size_t)PN * HD];
// split weights, stacked segments
#define WOFF_EMBA 0
#define WOFF_EMBP (WOFF_EMBA + 128 * 256)
#define WOFF_WP0  (WOFF_EMBP + 128 * 256)
#define WOFF_WA0  (WOFF_WP0 + 768 * 256)
#define WOFF_WP1  (WOFF_WA0 + 512 * 256)
#define WOFF_WA1  (WOFF_WP1 + 768 * 256)
#define WOFF_P1A  (WOFF_WA1 + 512 * 256)
#define WOFF_P1P  (WOFF_P1A + 256 * 256)
#define WOFF_P2P  (WOFF_P1P + 256 * 256)
#define WTOT      (WOFF_P2P + 256 * 256)
__device__ ushortx g_wh[WTOT], g_wl[WTOT];
// CSR
__device__ int g_deg[3 * PN];
__device__ int g_off[3 * (PN + 1)];
__device__ int g_cur[3 * PN];
__device__ int g_perm[3 * EN];

// ---------------- helpers ----------------
__device__ __forceinline__ unsigned smem_u32(const void* p) {
    unsigned a;
    asm("{ .reg .u64 t; cvta.to.shared.u64 t, %1; cvt.u32.u64 %0, t; }" : "=r"(a) : "l"(p));
    return a;
}
__device__ __forceinline__ void cp16(unsigned dst, const void* src, int n) {
    asm volatile("cp.async.cg.shared.global [%0], [%1], 16, %2;" :: "r"(dst), "l"(src), "r"(n));
}
#define CP_COMMIT() asm volatile("cp.async.commit_group;" ::: "memory")
#define CP_WAIT1()  asm volatile("cp.async.wait_group 1;" ::: "memory")

__device__ __forceinline__ void bsplit(float x, float y, unsigned& h, unsigned& l) {
    __nv_bfloat162 hb = __floats2bfloat162_rn(x, y);
    float rx = x - __bfloat162float(hb.x);
    float ry = y - __bfloat162float(hb.y);
    __nv_bfloat162 lb = __floats2bfloat162_rn(rx, ry);
    h = *(unsigned*)&hb;
    l = *(unsigned*)&lb;
}
#define MMA16816(c, a, b) \
    asm volatile("mma.sync.aligned.m16n8k16.row.col.f32.bf16.bf16.f32 " \
        "{%0,%1,%2,%3},{%4,%5,%6,%7},{%8,%9},{%0,%1,%2,%3};" \
        : "+f"((c)[0]), "+f"((c)[1]), "+f"((c)[2]), "+f"((c)[3]) \
        : "r"((a)[0]), "r"((a)[1]), "r"((a)[2]), "r"((a)[3]), "r"((b)[0]), "r"((b)[1]))
#define LDSM4(r, addr) \
    asm volatile("ldmatrix.sync.aligned.m8n8.x4.shared.b16 {%0,%1,%2,%3},[%4];" \
        : "=r"((r)[0]), "=r"((r)[1]), "=r"((r)[2]), "=r"((r)[3]) : "r"(addr))
#define LDSM4T(r, addr) \
    asm volatile("ldmatrix.sync.aligned.m8n8.x4.trans.shared.b16 {%0,%1,%2,%3},[%4];" \
        : "=r"((r)[0]), "=r"((r)[1]), "=r"((r)[2]), "=r"((r)[3]) : "r"(addr))

__device__ __forceinline__ float warp_sum(float v) {
#pragma unroll
    for (int o = 16; o; o >>= 1) v += __shfl_xor_sync(0xffffffffu, v, o);
    return v;
}
__device__ __forceinline__ float warp_max(float v) {
#pragma unroll
    for (int o = 16; o; o >>= 1) v = fmaxf(v, __shfl_xor_sync(0xffffffffu, v, o));
    return v;
}

// ---------------- prep: fp32 -> bf16 hi/lo split ----------------
__global__ void k_wsplit(const float* __restrict__ s, ushortx* __restrict__ dh,
                         ushortx* __restrict__ dl, int n) {
    int i = blockIdx.x * blockDim.x + threadIdx.x;
    if (i >= n) return;
    float v = s[i];
    __nv_bfloat16 h = __float2bfloat16(v);
    __nv_bfloat16 l = __float2bfloat16(v - __bfloat162float(h));
    dh[i] = *(ushortx*)&h;
    dl[i] = *(ushortx*)&l;
}
__global__ void k_wsplit_add(const float* __restrict__ a, const float* __restrict__ b,
                             ushortx* __restrict__ dh, ushortx* __restrict__ dl, int n) {
    int i = blockIdx.x * blockDim.x + threadIdx.x;
    if (i >= n) return;
    float v = a[i] + b[i];
    __nv_bfloat16 h = __float2bfloat16(v);
    __nv_bfloat16 l = __float2bfloat16(v - __bfloat162float(h));
    dh[i] = *(ushortx*)&h;
    dl[i] = *(ushortx*)&l;
}
__global__ void k_badd(const float* __restrict__ a, const float* __restrict__ b,
                       float* __restrict__ o, int n) {
    int i = blockIdx.x * blockDim.x + threadIdx.x;
    if (i < n) o[i] = a[i] + b[i];
}

// ---------------- CSR build ----------------
__global__ void k_zero_int(int* __restrict__ p, int n) {
    int i = blockIdx.x * blockDim.x + threadIdx.x;
    if (i < n) p[i] = 0;
}
__global__ void k_hist(const int* __restrict__ dst, int* __restrict__ deg, int n) {
    int i = blockIdx.x * blockDim.x + threadIdx.x;
    if (i < n) atomicAdd(&deg[dst[i]], 1);
}
__global__ void k_scan(const int* __restrict__ deg, int* __restrict__ off, int n) {
    __shared__ int part[1024];
    int tid = threadIdx.x;
    int chunk = (n + 1023) >> 10;
    int s = tid * chunk, e = min(s + chunk, n);
    int sum = 0;
    for (int i = s; i < e; ++i) sum += deg[i];
    part[tid] = sum;
    __syncthreads();
#pragma unroll
    for (int d = 1; d < 1024; d <<= 1) {
        int v = (tid >= d) ? part[tid - d] : 0;
        __syncthreads();
        part[tid] += v;
        __syncthreads();
    }
    int run = (tid == 0) ? 0 : part[tid - 1];
    for (int i = s; i < e; ++i) { off[i] = run; run += deg[i]; }
    if (tid == 0) off[n] = part[1023];
}
__global__ void k_copy_int(const int* __restrict__ a, int* __restrict__ b, int n) {
    int i = blockIdx.x * blockDim.x + threadIdx.x;
    if (i < n) b[i] = a[i];
}
__global__ void k_fill(const int* __restrict__ src, const int* __restrict__ dst,
                       int* __restrict__ cur, int* __restrict__ perm, int n) {
    int i = blockIdx.x * blockDim.x + threadIdx.x;
    if (i < n) { int slot = atomicAdd(&cur[dst[i]], 1); perm[slot] = src[i]; }
}

// ---------------- mean aggregation: fp32 gather -> bf16 hi/lo out ----------
__global__ void k_agg(const float* __restrict__ h, const int* __restrict__ off,
                      const int* __restrict__ perm, ushortx* __restrict__ oh,
                      ushortx* __restrict__ ol, int ndst) {
    int w = (blockIdx.x * blockDim.x + threadIdx.x) >> 5;
    int lane = threadIdx.x & 31;
    if (w >= ndst) return;
    int s = off[w], e = off[w + 1];
    float4 a0 = make_float4(0.f, 0.f, 0.f, 0.f);
    float4 a1 = make_float4(0.f, 0.f, 0.f, 0.f);
    for (int i = s; i < e; ++i) {
        const float4* r = (const float4*)(h + (size_t)perm[i] * HD);
        float4 v0 = __ldg(&r[lane]);
        float4 v1 = __ldg(&r[lane + 32]);
        a0.x += v0.x; a0.y += v0.y; a0.z += v0.z; a0.w += v0.w;
        a1.x += v1.x; a1.y += v1.y; a1.z += v1.z; a1.w += v1.w;
    }
    float inv = (e > s) ? 1.f / (float)(e - s) : 0.f;
    a0.x *= inv; a0.y *= inv; a0.z *= inv; a0.w *= inv;
    a1.x *= inv; a1.y *= inv; a1.z *= inv; a1.w *= inv;
    unsigned h0, l0, h1, l1;
    unsigned* ohu = (unsigned*)(oh + (size_t)w * HD);
    unsigned* olu = (unsigned*)(ol + (size_t)w * HD);
    bsplit(a0.x, a0.y, h0, l0); bsplit(a0.z, a0.w, h1, l1);
    ohu[lane * 2] = h0; ohu[lane * 2 + 1] = h1;
    olu[lane * 2] = l0; olu[lane * 2 + 1] = l1;
    bsplit(a1.x, a1.y, h0, l0); bsplit(a1.z, a1.w, h1, l1);
    ohu[64 + lane * 2] = h0; ohu[64 + lane * 2 + 1] = h1;
    olu[64 + lane * 2] = l0; olu[64 + lane * 2 + 1] = l1;
}

// ---------------- bf16-input HMMA 3-split GEMM, 2-stage, occ=2 -------------
// C = sum_seg A_seg[M,Kseg] @ B[Ktot,N]  (+bias)(relu). N%128==0, Kseg%32==0.
// Double-buffer schedule: prefetch exactly ONE tile ahead (stage (it+1)&1),
// compute stage it&1 after wait_group(1). Never touches the buffer in use.
#define A_ST 80
#define B_ST 272
#define OFF_AL 10240
#define OFF_BH 20480
#define OFF_BL 29184
#define STAGE 37888
#define NSTAGE 2

__global__ __launch_bounds__(256, 2) void k_bgemm(
    const ushortx* __restrict__ ah0, const ushortx* __restrict__ al0,
    const ushortx* __restrict__ ah1, const ushortx* __restrict__ al1,
    const ushortx* __restrict__ ah2, const ushortx* __restrict__ al2,
    const ushortx* __restrict__ Bh, const ushortx* __restrict__ Bl,
    const float* __restrict__ bias, float* __restrict__ C,
    ushortx* __restrict__ Ch, ushortx* __restrict__ Cl,
    int M, int N, int Ktot, int Kseg, int relu) {
    extern __shared__ char smc[];
    const int tid = threadIdx.x;
    const int lane = tid & 31;
    const int warp = tid >> 5;
    const int g = lane >> 2;
    const int t = lane & 3;
    const int wm = warp & 1;
    const int wn = warp >> 1;
    const int bm = blockIdx.y * 128;
    const int bn = blockIdx.x * 128;
    const unsigned sbase = smem_u32(smc);
    const int NIT = Ktot >> 5;
    const int segC = Kseg >> 5;

    float acc[4][4][4];
#pragma unroll
    for (int i = 0; i < 4; ++i)
#pragma unroll
        for (int j = 0; j < 4; ++j)
#pragma unroll
            for (int q = 0; q < 4; ++q) acc[i][j][q] = 0.f;

    const int ca = tid * 2;
    const int arow0 = ca >> 2, ac0 = ca & 3;
    const int arow1 = (ca + 1) >> 2, ac1 = (ca + 1) & 3;
    const int brow0 = ca >> 4, bc0 = ca & 15;
    const int brow1 = (ca + 1) >> 4, bc1 = (ca + 1) & 15;

    auto issue = [&](int it) {
        int seg = it / segC;
        int kloc = (it - seg * segC) << 5;
        const ushortx* pah = (seg == 0) ? ah0 : ((seg == 1) ? ah1 : ah2);
        const ushortx* pal = (seg == 0) ? al0 : ((seg == 1) ? al1 : al2);
        unsigned sa = sbase + (it & 1) * STAGE;
        int gr0 = bm + arow0, gr1 = bm + arow1;
        int ok0 = gr0 < M ? 16 : 0, ok1 = gr1 < M ? 16 : 0;
        size_t off0 = (size_t)(gr0 < M ? gr0 : 0) * Kseg + kloc + ac0 * 8;
        size_t off1 = (size_t)(gr1 < M ? gr1 : 0) * Kseg + kloc + ac1 * 8;
        cp16(sa + arow0 * A_ST + ac0 * 16, pah + off0, ok0);
        cp16(sa + arow1 * A_ST + ac1 * 16, pah + off1, ok1);
        cp16(sa + OFF_AL + arow0 * A_ST + ac0 * 16, pal + off0, ok0);
        cp16(sa + OFF_AL + arow1 * A_ST + ac1 * 16, pal + off1, ok1);
        int kg = it << 5;
        size_t bo0 = (size_t)(kg + brow0) * N + bn + bc0 * 8;
        size_t bo1 = (size_t)(kg + brow1) * N + bn + bc1 * 8;
        cp16(sa + OFF_BH + brow0 * B_ST + bc0 * 16, Bh + bo0, 16);
        cp16(sa + OFF_BH + brow1 * B_ST + bc1 * 16, Bh + bo1, 16);
        cp16(sa + OFF_BL + brow0 * B_ST + bc0 * 16, Bl + bo0, 16);
        cp16(sa + OFF_BL + brow1 * B_ST + bc1 * 16, Bl + bo1, 16);
        CP_COMMIT();
    };

    issue(0);
    for (int it = 0; it < NIT; ++it) {
        // prefetch ONE ahead into the other buffer; its previous readers all
        // passed the trailing __syncthreads of iteration it-1.
        if (it + 1 < NIT) issue(it + 1);
        else CP_COMMIT();          // keep pending-group count consistent
        CP_WAIT1();                // group(it) complete; group(it+1) may fly
        __syncthreads();
        const unsigned sa = sbase + (it & 1) * STAGE;
#pragma unroll
        for (int kk = 0; kk < 2; ++kk) {
            unsigned ah[4][4], al[4][4], bh[2][4], bl[2][4];
            unsigned abase = sa + (wm * 64 + (lane & 15)) * A_ST + kk * 32 + ((lane >> 4) << 4);
#pragma unroll
            for (int i = 0; i < 4; ++i) {
                LDSM4(ah[i], abase + i * (16 * A_ST));
                LDSM4(al[i], abase + i * (16 * A_ST) + OFF_AL);
            }
            unsigned bbase = sa + OFF_BH + (kk * 16 + (lane & 15)) * B_ST +
                             (wn * 32 + ((lane >> 4) << 3)) * 2;
#pragma unroll
            for (int p = 0; p < 2; ++p) {
                LDSM4T(bh[p], bbase + p * 32);
                LDSM4T(bl[p], bbase + p * 32 + (OFF_BL - OFF_BH));
            }
#pragma unroll
            for (int i = 0; i < 4; ++i)
#pragma unroll
                for (int j = 0; j < 4; ++j) {
                    unsigned* bhj = &bh[j >> 1][(j & 1) * 2];
                    unsigned* blj = &bl[j >> 1][(j & 1) * 2];
                    MMA16816(acc[i][j], ah[i], bhj);
                    MMA16816(acc[i][j], ah[i], blj);
                    MMA16816(acc[i][j], al[i], bhj);
                }
        }
        __syncthreads();
    }

#pragma unroll
    for (int i = 0; i < 4; ++i) {
        int r0 = bm + wm * 64 + i * 16 + g;
#pragma unroll
        for (int j = 0; j < 4; ++j) {
            int cn = bn + wn * 32 + j * 8 + 2 * t;
            float2 bv = make_float2(0.f, 0.f);
            if (bias) bv = *(const float2*)(bias + cn);
#pragma unroll
            for (int h = 0; h < 2; ++h) {
                int row = r0 + h * 8;
                if (row >= M) continue;
                float vx = acc[i][j][h * 2 + 0] + bv.x;
                float vy = acc[i][j][h * 2 + 1] + bv.y;
                if (relu) { vx = fmaxf(vx, 0.f); vy = fmaxf(vy, 0.f); }
                size_t o = (size_t)row * N + cn;
                if (C) *(float2*)(C + o) = make_float2(vx, vy);
                if (Ch) {
                    unsigned hh, ll;
                    bsplit(vx, vy, hh, ll);
                    *(unsigned*)(Ch + o) = hh;
                    *(unsigned*)(Cl + o) = ll;
                }
            }
        }
    }
}

// ---------------- fp32 SGEMM (N=40 head only) ----------------
#define BM 128
#define BN 64
#define BK 16
#define TM 8
#define TN 4
__global__ __launch_bounds__(256) void k_sgemm(
    const float* __restrict__ A, const float* __restrict__ B,
    const float* __restrict__ bias, float* __restrict__ C,
    int M, int N, int K) {
    __shared__ float As[BK][BM];
    __shared__ float Bs[BK][BN];
    const int tid = threadIdx.x;
    const int tx = tid & 15, ty = tid >> 4;
    const int bm = blockIdx.y * BM, bn = blockIdx.x * BN;
    float acc[TM][TN];
#pragma unroll
    for (int i = 0; i < TM; ++i)
#pragma unroll
        for (int j = 0; j < TN; ++j) acc[i][j] = 0.f;
    const int ar = tid >> 2, ac = (tid & 3) << 2;
    const int br = tid >> 4, bc = (tid & 15) << 2;
    for (int k0 = 0; k0 < K; k0 += BK) {
#pragma unroll
        for (int h = 0; h < 2; ++h) {
            int r = ar + h * 64, gr = bm + r;
            float4 v = make_float4(0.f, 0.f, 0.f, 0.f);
            if (gr < M) v = *(const float4*)(A + (size_t)gr * K + k0 + ac);
            As[ac + 0][r] = v.x; As[ac + 1][r] = v.y;
            As[ac + 2][r] = v.z; As[ac + 3][r] = v.w;
        }
        {
            int gc = bn + bc;
            float4 v = make_float4(0.f, 0.f, 0.f, 0.f);
            if (gc < N) v = *(const float4*)(B + (size_t)(k0 + br) * N + gc);
            *(float4*)&Bs[br][bc] = v;
        }
        __syncthreads();
#pragma unroll
        for (int kk = 0; kk < BK; ++kk) {
            float aF[TM], bF[TN];
#pragma unroll
            for (int i = 0; i < TM; ++i) aF[i] = As[kk][ty * TM + i];
#pragma unroll
            for (int j = 0; j < TN; ++j) bF[j] = Bs[kk][tx * TN + j];
#pragma unroll
            for (int i = 0; i < TM; ++i)
#pragma unroll
                for (int j = 0; j < TN; ++j) acc[i][j] = fmaf(aF[i], bF[j], acc[i][j]);
        }
        __syncthreads();
    }
    const int col = bn + tx * TN;
    if (col < N) {
        float4 bv = make_float4(0.f, 0.f, 0.f, 0.f);
        if (bias) bv = *(const float4*)(bias + col);
#pragma unroll
        for (int i = 0; i < TM; ++i) {
            int row = bm + ty * TM + i;
            if (row >= M) continue;
            *(float4*)(C + (size_t)row * N + col) =
                make_float4(acc[i][0] + bv.x, acc[i][1] + bv.y,
                            acc[i][2] + bv.z, acc[i][3] + bv.w);
        }
    }
}

// ---------------- fused relu+residual+LayerNorm + split ----------------
__global__ void k_ln(const float* __restrict__ t, float* __restrict__ h,
                     ushortx* __restrict__ hh, ushortx* __restrict__ hl,
                     const float* __restrict__ g, const float* __restrict__ b, int rows) {
    int w = (blockIdx.x * blockDim.x + threadIdx.x) >> 5;
    int lane = threadIdx.x & 31;
    if (w >= rows) return;
    const float4* t4 = (const float4*)(t + (size_t)w * HD);
    float4* h4 = (float4*)(h + (size_t)w * HD);
    float4 x0 = t4[lane], x1 = t4[lane + 32];
    float4 p0 = h4[lane], p1 = h4[lane + 32];
    float u[8];
    u[0] = fmaxf(x0.x, 0.f) + p0.x; u[1] = fmaxf(x0.y, 0.f) + p0.y;
    u[2] = fmaxf(x0.z, 0.f) + p0.z; u[3] = fmaxf(x0.w, 0.f) + p0.w;
    u[4] = fmaxf(x1.x, 0.f) + p1.x; u[5] = fmaxf(x1.y, 0.f) + p1.y;
    u[6] = fmaxf(x1.z, 0.f) + p1.z; u[7] = fmaxf(x1.w, 0.f) + p1.w;
    float s = 0.f;
#pragma unroll
    for (int i = 0; i < 8; ++i) s += u[i];
    s = warp_sum(s);
    float mu = s * (1.f / HD);
    float v = 0.f;
#pragma unroll
    for (int i = 0; i < 8; ++i) { float d = u[i] - mu; v += d * d; }
    v = warp_sum(v);
    float rstd = rsqrtf(v * (1.f / HD) + 1e-5f);
    const float4* g4 = (const float4*)g;
    const float4* b4 = (const float4*)b;
    float4 ga = g4[lane], gb = g4[lane + 32];
    float4 ba = b4[lane], bb = b4[lane + 32];
    float o[8];
    o[0] = (u[0] - mu) * rstd * ga.x + ba.x; o[1] = (u[1] - mu) * rstd * ga.y + ba.y;
    o[2] = (u[2] - mu) * rstd * ga.z + ba.z; o[3] = (u[3] - mu) * rstd * ga.w + ba.w;
    o[4] = (u[4] - mu) * rstd * gb.x + bb.x; o[5] = (u[5] - mu) * rstd * gb.y + bb.y;
    o[6] = (u[6] - mu) * rstd * gb.z + bb.z; o[7] = (u[7] - mu) * rstd * gb.w + bb.w;
    h4[lane] = make_float4(o[0], o[1], o[2], o[3]);
    h4[lane + 32] = make_float4(o[4], o[5], o[6], o[7]);
    unsigned* hhu = (unsigned*)(hh + (size_t)w * HD);
    unsigned* hlu = (unsigned*)(hl + (size_t)w * HD);
    unsigned hv0, lv0, hv1, lv1;
    bsplit(o[0], o[1], hv0, lv0); bsplit(o[2], o[3], hv1, lv1);
    hhu[lane * 2] = hv0; hhu[lane * 2 + 1] = hv1;
    hlu[lane * 2] = lv0; hlu[lane * 2 + 1] = lv1;
    bsplit(o[4], o[5], hv0, lv0); bsplit(o[6], o[7], hv1, lv1);
    hhu[64 + lane * 2] = hv0; hhu[64 + lane * 2 + 1] = hv1;
    hlu[64 + lane * 2] = lv0; hlu[64 + lane * 2 + 1] = lv1;
}

__global__ void k_lsm(float* __restrict__ x, int rows) {
    int w = (blockIdx.x * blockDim.x + threadIdx.x) >> 5;
    int lane = threadIdx.x & 31;
    if (w >= rows) return;
    float* r = x + (size_t)w * CN;
    float v0 = r[lane];
    bool has1 = (lane + 32) < CN;
    float v1 = has1 ? r[lane + 32] : -3.4e38f;
    float m = warp_max(fmaxf(v0, v1));
    float s = expf(v0 - m) + (has1 ? expf(v1 - m) : 0.f);
    s = warp_sum(s);
    float lse = m + logf(s);
    r[lane] = v0 - lse;
    if (has1) r[lane + 32] = v1 - lse;
}

// ---------------- host ----------------
static inline void bgemm(const ushortx* ah0, const ushortx* al0,
                         const ushortx* ah1, const ushortx* al1,
                         const ushortx* ah2, const ushortx* al2,
                         const ushortx* Bh, const ushortx* Bl,
                         const float* bias, float* C, ushortx* Ch, ushortx* Cl,
                         int M, int N, int Ktot, int Kseg, int relu) {
    dim3 grid(N >> 7, (M + 127) >> 7);
    k_bgemm<<<grid, 256, NSTAGE * STAGE>>>(ah0, al0, ah1, al1, ah2, al2,
                                           Bh, Bl, bias, C, Ch, Cl,
                                           M, N, Ktot, Kseg, relu);
}

extern "C" void kernel_launch(void* const* d_in, const int* in_sizes, int n_in,
                              void* d_out, int out_size) {
    const float* x_author     = (const float*)d_in[0];
    const float* x_paper      = (const float*)d_in[1];
    const int*   e0_src       = (const int*)d_in[2];
    const int*   e0_dst       = (const int*)d_in[3];
    const int*   e1_src       = (const int*)d_in[4];
    const int*   e1_dst       = (const int*)d_in[5];
    const int*   e2_src       = (const int*)d_in[6];
    const int*   e2_dst       = (const int*)d_in[7];
    const float* emb_W_author = (const float*)d_in[8];
    const float* emb_b_author = (const float*)d_in[9];
    const float* emb_W_paper  = (const float*)d_in[10];
    const float* emb_b_paper  = (const float*)d_in[11];
    const float* W_self       = (const float*)d_in[12];
    const float* W_neigh      = (const float*)d_in[13];
    const float* b_conv       = (const float*)d_in[14];
    const float* ln_g_author  = (const float*)d_in[15];
    const float* ln_b_author  = (const float*)d_in[16];
    const float* ln_g_paper   = (const float*)d_in[17];
    const float* ln_b_paper   = (const float*)d_in[18];
    const float* pW1_author   = (const float*)d_in[19];
    const float* pb1_author   = (const float*)d_in[20];
    const float* pW2_author   = (const float*)d_in[21];
    const float* pb2_author   = (const float*)d_in[22];
    const float* pW1_paper    = (const float*)d_in[23];
    const float* pb1_paper    = (const float*)d_in[24];
    const float* pW2_paper    = (const float*)d_in[25];
    const float* pb2_paper    = (const float*)d_in[26];

    cudaFuncSetAttribute(k_bgemm, cudaFuncAttributeMaxDynamicSharedMemorySize, NSTAGE * STAGE);

    float *p_ha, *p_hp, *p_ta, *p_tp, *p_b01;
    ushortx *p_xah, *p_xal, *p_xph, *p_xpl, *p_hah, *p_hal, *p_hph, *p_hpl;
    ushortx *p_ag0h, *p_ag0l, *p_ag1h, *p_ag1l, *p_wh, *p_wl;
    int *p_deg, *p_off, *p_cur, *p_perm;
    cudaGetSymbolAddress((void**)&p_ha, g_ha);
    cudaGetSymbolAddress((void**)&p_hp, g_hp);
    cudaGetSymbolAddress((void**)&p_ta, g_ta);
    cudaGetSymbolAddress((void**)&p_tp, g_tp);
    cudaGetSymbolAddress((void**)&p_b01, g_b01);
    cudaGetSymbolAddress((void**)&p_xah, g_xah);
    cudaGetSymbolAddress((void**)&p_xal, g_xal);
    cudaGetSymbolAddress((void**)&p_xph, g_xph);
    cudaGetSymbolAddress((void**)&p_xpl, g_xpl);
    cudaGetSymbolAddress((void**)&p_hah, g_hah);
    cudaGetSymbolAddress((void**)&p_hal, g_hal);
    cudaGetSymbolAddress((void**)&p_hph, g_hph);
    cudaGetSymbolAddress((void**)&p_hpl, g_hpl);
    cudaGetSymbolAddress((void**)&p_ag0h, g_ag0h);
    cudaGetSymbolAddress((void**)&p_ag0l, g_ag0l);
    cudaGetSymbolAddress((void**)&p_ag1h, g_ag1h);
    cudaGetSymbolAddress((void**)&p_ag1l, g_ag1l);
    cudaGetSymbolAddress((void**)&p_wh, g_wh);
    cudaGetSymbolAddress((void**)&p_wl, g_wl);
    cudaGetSymbolAddress((void**)&p_deg, g_deg);
    cudaGetSymbolAddress((void**)&p_off, g_off);
    cudaGetSymbolAddress((void**)&p_cur, g_cur);
    cudaGetSymbolAddress((void**)&p_perm, g_perm);

    // ---- weight + input splits ----
    const int WB = 256;
    auto nb = [](int n) { return (n + 255) / 256; };
    k_wsplit<<<nb(128 * 256), WB>>>(emb_W_author, p_wh + WOFF_EMBA, p_wl + WOFF_EMBA, 128 * 256);
    k_wsplit<<<nb(128 * 256), WB>>>(emb_W_paper, p_wh + WOFF_EMBP, p_wl + WOFF_EMBP, 128 * 256);
    const int WPO[2] = {WOFF_WP0, WOFF_WP1};
    const int WAO[2] = {WOFF_WA0, WOFF_WA1};
    for (int l = 0; l < 2; ++l) {
        const float* Ws = W_self + (size_t)l * 3 * HD * HD;
        const float* Wn = W_neigh + (size_t)l * 3 * HD * HD;
        const float* bc = b_conv + (size_t)l * 3 * HD;
        k_wsplit_add<<<nb(HD * HD), WB>>>(Ws, Ws + HD * HD,
                                          p_wh + WPO[l], p_wl + WPO[l], HD * HD);
        k_wsplit<<<nb(HD * HD), WB>>>(Wn, p_wh + WPO[l] + HD * HD, p_wl + WPO[l] + HD * HD, HD * HD);
        k_wsplit<<<nb(HD * HD), WB>>>(Wn + HD * HD, p_wh + WPO[l] + 2 * HD * HD,
                                      p_wl + WPO[l] + 2 * HD * HD, HD * HD);
        k_wsplit<<<nb(HD * HD), WB>>>(Ws + 2 * HD * HD, p_wh + WAO[l], p_wl + WAO[l], HD * HD);
        k_wsplit<<<nb(HD * HD), WB>>>(Wn + 2 * HD * HD, p_wh + WAO[l] + HD * HD,
                                      p_wl + WAO[l] + HD * HD, HD * HD);
        k_badd<<<1, 256>>>(bc, bc + HD, p_b01 + l * HD, HD);
    }
    k_wsplit<<<nb(HD * HD), WB>>>(pW1_author, p_wh + WOFF_P1A, p_wl + WOFF_P1A, HD * HD);
    k_wsplit<<<nb(HD * HD), WB>>>(pW1_paper, p_wh + WOFF_P1P, p_wl + WOFF_P1P, HD * HD);
    k_wsplit<<<nb(HD * HD), WB>>>(pW2_paper, p_wh + WOFF_P2P, p_wl + WOFF_P2P, HD * HD);
    k_wsplit<<<nb(AN * DIN), WB>>>(x_author, p_xah, p_xal, AN * DIN);
    k_wsplit<<<nb(PN * DIN), WB>>>(x_paper, p_xph, p_xpl, PN * DIN);

    // ---- CSR build ----
    const int* srcs[3] = {e0_src, e1_src, e2_src};
    const int* dsts[3] = {e0_dst, e1_dst, e2_dst};
    const int ndsts[3] = {PN, PN, AN};
    const int EB = (EN + 255) / 256;
    for (int tt = 0; tt < 3; ++tt) {
        int* deg = p_deg + tt * PN;
        int* off = p_off + tt * (PN + 1);
        int* cur = p_cur + tt * PN;
        int* perm = p_perm + tt * EN;
        int nd = ndsts[tt];
        int NB = (nd + 255) / 256;
        k_zero_int<<<NB, 256>>>(deg, nd);
        k_hist<<<EB, 256>>>(dsts[tt], deg, EN);
        k_scan<<<1, 1024>>>(deg, off, nd);
        k_copy_int<<<NB, 256>>>(off, cur, nd);
        k_fill<<<EB, 256>>>(srcs[tt], dsts[tt], cur, perm, EN);
    }

    // ---- embeddings (fp32 h + split h) ----
    bgemm(p_xah, p_xal, 0, 0, 0, 0, p_wh + WOFF_EMBA, p_wl + WOFF_EMBA,
          emb_b_author, p_ha, p_hah, p_hal, AN, HD, DIN, DIN, 0);
    bgemm(p_xph, p_xpl, 0, 0, 0, 0, p_wh + WOFF_EMBP, p_wl + WOFF_EMBP,
          emb_b_paper, p_hp, p_hph, p_hpl, PN, HD, DIN, DIN, 0);

    // ---- 2 SAGE layers ----
    const int AGG_BLK = 128;
    for (int l = 0; l < 2; ++l) {
        const float* bc = b_conv + (size_t)l * 3 * HD;
        k_agg<<<(PN * 32 + AGG_BLK - 1) / AGG_BLK, AGG_BLK>>>(
            p_ha, p_off + 0 * (PN + 1), p_perm + 0 * EN, p_ag0h, p_ag0l, PN);
        k_agg<<<(PN * 32 + AGG_BLK - 1) / AGG_BLK, AGG_BLK>>>(
            p_hp, p_off + 1 * (PN + 1), p_perm + 1 * EN, p_ag1h, p_ag1l, PN);
        bgemm(p_hph, p_hpl, p_ag0h, p_ag0l, p_ag1h, p_ag1l,
              p_wh + WPO[l], p_wl + WPO[l], p_b01 + l * HD,
              p_tp, 0, 0, PN, HD, 3 * HD, HD, 0);
        k_agg<<<(AN * 32 + AGG_BLK - 1) / AGG_BLK, AGG_BLK>>>(
            p_hp, p_off + 2 * (PN + 1), p_perm + 2 * EN, p_ag0h, p_ag0l, AN);
        bgemm(p_hah, p_hal, p_ag0h, p_ag0l, 0, 0,
              p_wh + WAO[l], p_wl + WAO[l], bc + 2 * HD,
              p_ta, 0, 0, AN, HD, 2 * HD, HD, 0);
        k_ln<<<(AN * 32 + 127) / 128, 128>>>(p_ta, p_ha, p_hah, p_hal,
                                             ln_g_author, ln_b_author, AN);
        k_ln<<<(PN * 32 + 127) / 128, 128>>>(p_tp, p_hp, p_hph, p_hpl,
                                             ln_g_paper, ln_b_paper, PN);
    }

    // ---- output heads ----
    float* out = (float*)d_out;
    bgemm(p_hah, p_hal, 0, 0, 0, 0, p_wh + WOFF_P1A, p_wl + WOFF_P1A,
          pb1_author, p_ta, 0, 0, AN, HD, HD, HD, 1);
    {
        dim3 grid((CN + BN - 1) / BN, (AN + BM - 1) / BM);
        k_sgemm<<<grid, 256>>>(p_ta, pW2_author, pb2_author, out, AN, CN, HD);
    }
    k_lsm<<<(AN * 32 + 127) / 128, 128>>>(out, AN);
    bgemm(p_hph, p_hpl, 0, 0, 0, 0, p_wh + WOFF_P1P, p_wl + WOFF_P1P,
          pb1_paper, 0, p_ag0h, p_ag0l, PN, HD, HD, HD, 1);
    bgemm(p_ag0h, p_ag0l, 0, 0, 0, 0, p_wh + WOFF_P2P, p_wl + WOFF_P2P,
          pb2_paper, out + (size_t)AN * CN, 0, 0, PN, HD, HD, HD, 0);
}

// round 9
// speedup vs baseline: 2.0975x; 1.0877x over previous
#include <cuda_runtime.h>
#include <cuda_bf16.h>
#include <math.h>

#define AN 50000
#define PN 100000
#define DIN 128
#define HD 256
#define CN 40
#define EN 300000

typedef unsigned short ushortx;

// fp32 state
__device__ float g_ha[(size_t)AN * HD];
__device__ float g_hp[(size_t)PN * HD];
__device__ float g_ta[(size_t)AN * HD];
__device__ float g_tp[(size_t)PN * HD];
__device__ float g_b01[2 * HD];
// bf16 hi/lo operand buffers
__device__ ushortx g_xah[(size_t)AN * DIN], g_xal[(size_t)AN * DIN];
__device__ ushortx g_xph[(size_t)PN * DIN], g_xpl[(size_t)PN * DIN];
__device__ ushortx g_hah[(size_t)AN * HD],  g_hal[(size_t)AN * HD];
__device__ ushortx g_hph[(size_t)PN * HD],  g_hpl[(size_t)PN * HD];
__device__ ushortx g_ag0h[(size_t)PN * HD], g_ag0l[(size_t)PN * HD];
__device__ ushortx g_ag1h[(size_t)PN * HD], g_ag1l[(size_t)PN * HD];
// split weights, stacked segments (contiguous: dst index == linear j)
#define WOFF_EMBA 0
#define WOFF_EMBP (WOFF_EMBA + 128 * 256)
#define WOFF_WP0  (WOFF_EMBP + 128 * 256)
#define WOFF_WA0  (WOFF_WP0 + 768 * 256)
#define WOFF_WP1  (WOFF_WA0 + 512 * 256)
#define WOFF_WA1  (WOFF_WP1 + 768 * 256)
#define WOFF_P1A  (WOFF_WA1 + 512 * 256)
#define WOFF_P1P  (WOFF_P1A + 256 * 256)
#define WOFF_P2P  (WOFF_P1P + 256 * 256)
#define WTOT      (WOFF_P2P + 256 * 256)
__device__ ushortx g_wh[WTOT], g_wl[WTOT];
// CSR
__device__ int g_deg[3 * PN];
__device__ int g_off[3 * (PN + 1)];
__device__ int g_cur[3 * PN];
__device__ int g_perm[3 * EN];

// ---------------- helpers ----------------
__device__ __forceinline__ unsigned smem_u32(const void* p) {
    unsigned a;
    asm("{ .reg .u64 t; cvta.to.shared.u64 t, %1; cvt.u32.u64 %0, t; }" : "=r"(a) : "l"(p));
    return a;
}
__device__ __forceinline__ void cp16(unsigned dst, const void* src, int n) {
    asm volatile("cp.async.cg.shared.global [%0], [%1], 16, %2;" :: "r"(dst), "l"(src), "r"(n));
}
#define CP_COMMIT() asm volatile("cp.async.commit_group;" ::: "memory")
#define CP_WAIT0()  asm volatile("cp.async.wait_group 0;" ::: "memory")

__device__ __forceinline__ void bsplit(float x, float y, unsigned& h, unsigned& l) {
    __nv_bfloat162 hb = __floats2bfloat162_rn(x, y);
    float rx = x - __bfloat162float(hb.x);
    float ry = y - __bfloat162float(hb.y);
    __nv_bfloat162 lb = __floats2bfloat162_rn(rx, ry);
    h = *(unsigned*)&hb;
    l = *(unsigned*)&lb;
}
#define MMA16816(c, a, b) \
    asm volatile("mma.sync.aligned.m16n8k16.row.col.f32.bf16.bf16.f32 " \
        "{%0,%1,%2,%3},{%4,%5,%6,%7},{%8,%9},{%0,%1,%2,%3};" \
        : "+f"((c)[0]), "+f"((c)[1]), "+f"((c)[2]), "+f"((c)[3]) \
        : "r"((a)[0]), "r"((a)[1]), "r"((a)[2]), "r"((a)[3]), "r"((b)[0]), "r"((b)[1]))
#define LDSM4(r, addr) \
    asm volatile("ldmatrix.sync.aligned.m8n8.x4.shared.b16 {%0,%1,%2,%3},[%4];" \
        : "=r"((r)[0]), "=r"((r)[1]), "=r"((r)[2]), "=r"((r)[3]) : "r"(addr))
#define LDSM4T(r, addr) \
    asm volatile("ldmatrix.sync.aligned.m8n8.x4.trans.shared.b16 {%0,%1,%2,%3},[%4];" \
        : "=r"((r)[0]), "=r"((r)[1]), "=r"((r)[2]), "=r"((r)[3]) : "r"(addr))

__device__ __forceinline__ float warp_sum(float v) {
#pragma unroll
    for (int o = 16; o; o >>= 1) v += __shfl_xor_sync(0xffffffffu, v, o);
    return v;
}
__device__ __forceinline__ float warp_max(float v) {
#pragma unroll
    for (int o = 16; o; o >>= 1) v = fmaxf(v, __shfl_xor_sync(0xffffffffu, v, o));
    return v;
}

// ---------------- one mega split kernel: x inputs, all weights, biases -----
#define NXA (AN * DIN)
#define NXP (PN * DIN)
#define NSPLIT_TOT (NXA + NXP + WTOT + 512)

__global__ void k_split_all(
    const float* __restrict__ x_author, const float* __restrict__ x_paper,
    const float* __restrict__ emb_W_author, const float* __restrict__ emb_W_paper,
    const float* __restrict__ W_self, const float* __restrict__ W_neigh,
    const float* __restrict__ pW1_author, const float* __restrict__ pW1_paper,
    const float* __restrict__ pW2_paper, const float* __restrict__ b_conv,
    ushortx* __restrict__ wh, ushortx* __restrict__ wl,
    ushortx* __restrict__ xah, ushortx* __restrict__ xal,
    ushortx* __restrict__ xph, ushortx* __restrict__ xpl,
    float* __restrict__ b01) {
    int i = blockIdx.x * blockDim.x + threadIdx.x;
    if (i >= NSPLIT_TOT) return;
    if (i < NXA) {
        float v = x_author[i];
        __nv_bfloat16 h = __float2bfloat16(v);
        xah[i] = *(ushortx*)&h;
        __nv_bfloat16 l = __float2bfloat16(v - __bfloat162float(h));
        xal[i] = *(ushortx*)&l;
        return;
    }
    i -= NXA;
    if (i < NXP) {
        float v = x_paper[i];
        __nv_bfloat16 h = __float2bfloat16(v);
        xph[i] = *(ushortx*)&h;
        __nv_bfloat16 l = __float2bfloat16(v - __bfloat162float(h));
        xpl[i] = *(ushortx*)&l;
        return;
    }
    i -= NXP;
    if (i < WTOT) {
        const int j = i;
        const int Q = 65536;  // 256*256
        float v;
        if (j < Q)               v = (j < Q / 2) ? emb_W_author[j] : emb_W_paper[j - Q / 2];
        else if (j < 2 * Q)      { int r = j - Q;     v = W_self[r] + W_self[Q + r]; }
        else if (j < 3 * Q)      v = W_neigh[j - 2 * Q];
        else if (j < 4 * Q)      v = W_neigh[Q + j - 3 * Q];
        else if (j < 5 * Q)      v = W_self[2 * Q + j - 4 * Q];
        else if (j < 6 * Q)      v = W_neigh[2 * Q + j - 5 * Q];
        else if (j < 7 * Q)      { int r = j - 6 * Q; v = W_self[3 * Q + r] + W_self[4 * Q + r]; }
        else if (j < 8 * Q)      v = W_neigh[3 * Q + j - 7 * Q];
        else if (j < 9 * Q)      v = W_neigh[4 * Q + j - 8 * Q];
        else if (j < 10 * Q)     v = W_self[5 * Q + j - 9 * Q];
        else if (j < 11 * Q)     v = W_neigh[5 * Q + j - 10 * Q];
        else if (j < 12 * Q)     v = pW1_author[j - 11 * Q];
        else if (j < 13 * Q)     v = pW1_paper[j - 12 * Q];
        else                     v = pW2_paper[j - 13 * Q];
        __nv_bfloat16 h = __float2bfloat16(v);
        wh[j] = *(ushortx*)&h;
        __nv_bfloat16 l = __float2bfloat16(v - __bfloat162float(h));
        wl[j] = *(ushortx*)&l;
        return;
    }
    i -= WTOT;  // i in [0,512): combined conv biases per layer
    int l = i >> 8, c = i & 255;
    b01[i] = b_conv[l * 768 + c] + b_conv[l * 768 + 256 + c];
}

// ---------------- CSR build, merged across the 3 edge types ----------------
__global__ void k_zero3(int* __restrict__ deg) {
    int i = blockIdx.x * blockDim.x + threadIdx.x;
    if (i < 3 * PN) deg[i] = 0;
}
__global__ void k_hist3(const int* __restrict__ d0, const int* __restrict__ d1,
                        const int* __restrict__ d2, int* __restrict__ deg) {
    int i = blockIdx.x * blockDim.x + threadIdx.x;
    if (i >= 3 * EN) return;
    int t = i / EN, k = i - t * EN;
    const int* d = (t == 0) ? d0 : ((t == 1) ? d1 : d2);
    atomicAdd(&deg[t * PN + d[k]], 1);
}
// one block per edge type; writes off AND cur
__global__ void k_scan3(const int* __restrict__ deg, int* __restrict__ off,
                        int* __restrict__ cur) {
    __shared__ int part[1024];
    const int t = blockIdx.x;
    const int nd = (t == 2) ? AN : PN;
    const int* dg = deg + t * PN;
    int* of = off + t * (PN + 1);
    int* cu = cur + t * PN;
    int tid = threadIdx.x;
    int chunk = (nd + 1023) >> 10;
    int s = tid * chunk, e = min(s + chunk, nd);
    int sum = 0;
    for (int i = s; i < e; ++i) sum += dg[i];
    part[tid] = sum;
    __syncthreads();
#pragma unroll
    for (int d = 1; d < 1024; d <<= 1) {
        int v = (tid >= d) ? part[tid - d] : 0;
        __syncthreads();
        part[tid] += v;
        __syncthreads();
    }
    int run = (tid == 0) ? 0 : part[tid - 1];
    for (int i = s; i < e; ++i) { of[i] = run; cu[i] = run; run += dg[i]; }
    if (tid == 0) of[nd] = part[1023];
}
__global__ void k_fill3(const int* __restrict__ s0, const int* __restrict__ d0,
                        const int* __restrict__ s1, const int* __restrict__ d1,
                        const int* __restrict__ s2, const int* __restrict__ d2,
                        int* __restrict__ cur, int* __restrict__ perm) {
    int i = blockIdx.x * blockDim.x + threadIdx.x;
    if (i >= 3 * EN) return;
    int t = i / EN, k = i - t * EN;
    const int* s = (t == 0) ? s0 : ((t == 1) ? s1 : s2);
    const int* d = (t == 0) ? d0 : ((t == 1) ? d1 : d2);
    int slot = atomicAdd(&cur[t * PN + d[k]], 1);
    perm[t * EN + slot] = s[k];
}

// ---------------- mean aggregation: fp32 gather -> bf16 hi/lo out ----------
__global__ void k_agg(const float* __restrict__ h, const int* __restrict__ off,
                      const int* __restrict__ perm, ushortx* __restrict__ oh,
                      ushortx* __restrict__ ol, int ndst) {
    int w = (blockIdx.x * blockDim.x + threadIdx.x) >> 5;
    int lane = threadIdx.x & 31;
    if (w >= ndst) return;
    int s = off[w], e = off[w + 1];
    float4 a0 = make_float4(0.f, 0.f, 0.f, 0.f);
    float4 a1 = make_float4(0.f, 0.f, 0.f, 0.f);
    for (int i = s; i < e; ++i) {
        const float4* r = (const float4*)(h + (size_t)perm[i] * HD);
        float4 v0 = __ldg(&r[lane]);
        float4 v1 = __ldg(&r[lane + 32]);
        a0.x += v0.x; a0.y += v0.y; a0.z += v0.z; a0.w += v0.w;
        a1.x += v1.x; a1.y += v1.y; a1.z += v1.z; a1.w += v1.w;
    }
    float inv = (e > s) ? 1.f / (float)(e - s) : 0.f;
    a0.x *= inv; a0.y *= inv; a0.z *= inv; a0.w *= inv;
    a1.x *= inv; a1.y *= inv; a1.z *= inv; a1.w *= inv;
    unsigned h0, l0, h1, l1;
    unsigned* ohu = (unsigned*)(oh + (size_t)w * HD);
    unsigned* olu = (unsigned*)(ol + (size_t)w * HD);
    bsplit(a0.x, a0.y, h0, l0); bsplit(a0.z, a0.w, h1, l1);
    ohu[lane * 2] = h0; ohu[lane * 2 + 1] = h1;
    olu[lane * 2] = l0; olu[lane * 2 + 1] = l1;
    bsplit(a1.x, a1.y, h0, l0); bsplit(a1.z, a1.w, h1, l1);
    ohu[64 + lane * 2] = h0; ohu[64 + lane * 2 + 1] = h1;
    olu[64 + lane * 2] = l0; olu[64 + lane * 2 + 1] = l1;
}

// ---------------- bf16-input HMMA 3-split GEMM, 2-stage, occ=2, 1 sync/iter
// C = sum_seg A_seg[M,Kseg] @ B[Ktot,N]  (+bias)(relu). N%128==0, Kseg%32==0.
// Schedule per iter: wait_group(0) [group(it) done] -> sync [all warps left
// buf^1] -> issue(it+1) into buf^1 -> compute buf(it&1). One barrier/iter.
#define A_ST 80
#define B_ST 272
#define OFF_AL 10240
#define OFF_BH 20480
#define OFF_BL 29184
#define STAGE 37888
#define NSTAGE 2

__global__ __launch_bounds__(256, 2) void k_bgemm(
    const ushortx* __restrict__ ah0, const ushortx* __restrict__ al0,
    const ushortx* __restrict__ ah1, const ushortx* __restrict__ al1,
    const ushortx* __restrict__ ah2, const ushortx* __restrict__ al2,
    const ushortx* __restrict__ Bh, const ushortx* __restrict__ Bl,
    const float* __restrict__ bias, float* __restrict__ C,
    ushortx* __restrict__ Ch, ushortx* __restrict__ Cl,
    int M, int N, int Ktot, int Kseg, int relu) {
    extern __shared__ char smc[];
    const int tid = threadIdx.x;
    const int lane = tid & 31;
    const int warp = tid >> 5;
    const int g = lane >> 2;
    const int t = lane & 3;
    const int wm = warp & 1;
    const int wn = warp >> 1;
    const int bm = blockIdx.y * 128;
    const int bn = blockIdx.x * 128;
    const unsigned sbase = smem_u32(smc);
    const int NIT = Ktot >> 5;
    const int segC = Kseg >> 5;

    float acc[4][4][4];
#pragma unroll
    for (int i = 0; i < 4; ++i)
#pragma unroll
        for (int j = 0; j < 4; ++j)
#pragma unroll
            for (int q = 0; q < 4; ++q) acc[i][j][q] = 0.f;

    const int ca = tid * 2;
    const int arow0 = ca >> 2, ac0 = ca & 3;
    const int arow1 = (ca + 1) >> 2, ac1 = (ca + 1) & 3;
    const int brow0 = ca >> 4, bc0 = ca & 15;
    const int brow1 = (ca + 1) >> 4, bc1 = (ca + 1) & 15;

    auto issue = [&](int it) {
        int seg = it / segC;
        int kloc = (it - seg * segC) << 5;
        const ushortx* pah = (seg == 0) ? ah0 : ((seg == 1) ? ah1 : ah2);
        const ushortx* pal = (seg == 0) ? al0 : ((seg == 1) ? al1 : al2);
        unsigned sa = sbase + (it & 1) * STAGE;
        int gr0 = bm + arow0, gr1 = bm + arow1;
        int ok0 = gr0 < M ? 16 : 0, ok1 = gr1 < M ? 16 : 0;
        size_t off0 = (size_t)(gr0 < M ? gr0 : 0) * Kseg + kloc + ac0 * 8;
        size_t off1 = (size_t)(gr1 < M ? gr1 : 0) * Kseg + kloc + ac1 * 8;
        cp16(sa + arow0 * A_ST + ac0 * 16, pah + off0, ok0);
        cp16(sa + arow1 * A_ST + ac1 * 16, pah + off1, ok1);
        cp16(sa + OFF_AL + arow0 * A_ST + ac0 * 16, pal + off0, ok0);
        cp16(sa + OFF_AL + arow1 * A_ST + ac1 * 16, pal + off1, ok1);
        int kg = it << 5;
        size_t bo0 = (size_t)(kg + brow0) * N + bn + bc0 * 8;
        size_t bo1 = (size_t)(kg + brow1) * N + bn + bc1 * 8;
        cp16(sa + OFF_BH + brow0 * B_ST + bc0 * 16, Bh + bo0, 16);
        cp16(sa + OFF_BH + brow1 * B_ST + bc1 * 16, Bh + bo1, 16);
        cp16(sa + OFF_BL + brow0 * B_ST + bc0 * 16, Bl + bo0, 16);
        cp16(sa + OFF_BL + brow1 * B_ST + bc1 * 16, Bl + bo1, 16);
        CP_COMMIT();
    };

    issue(0);
    for (int it = 0; it < NIT; ++it) {
        CP_WAIT0();                 // group(it) complete (only pending group)
        __syncthreads();            // all warps done reading buf^1 (iter it-1)
        if (it + 1 < NIT) issue(it + 1);  // overlaps compute of this iter
        const unsigned sa = sbase + (it & 1) * STAGE;
#pragma unroll
        for (int kk = 0; kk < 2; ++kk) {
            unsigned ah[4][4], al[4][4], bh[2][4], bl[2][4];
            unsigned abase = sa + (wm * 64 + (lane & 15)) * A_ST + kk * 32 + ((lane >> 4) << 4);
#pragma unroll
            for (int i = 0; i < 4; ++i) {
                LDSM4(ah[i], abase + i * (16 * A_ST));
                LDSM4(al[i], abase + i * (16 * A_ST) + OFF_AL);
            }
            unsigned bbase = sa + OFF_BH + (kk * 16 + (lane & 15)) * B_ST +
                             (wn * 32 + ((lane >> 4) << 3)) * 2;
#pragma unroll
            for (int p = 0; p < 2; ++p) {
                LDSM4T(bh[p], bbase + p * 32);
                LDSM4T(bl[p], bbase + p * 32 + (OFF_BL - OFF_BH));
            }
#pragma unroll
            for (int i = 0; i < 4; ++i)
#pragma unroll
                for (int j = 0; j < 4; ++j) {
                    unsigned* bhj = &bh[j >> 1][(j & 1) * 2];
                    unsigned* blj = &bl[j >> 1][(j & 1) * 2];
                    MMA16816(acc[i][j], ah[i], bhj);
                    MMA16816(acc[i][j], ah[i], blj);
                    MMA16816(acc[i][j], al[i], bhj);
                }
        }
    }

#pragma unroll
    for (int i = 0; i < 4; ++i) {
        int r0 = bm + wm * 64 + i * 16 + g;
#pragma unroll
        for (int j = 0; j < 4; ++j) {
            int cn = bn + wn * 32 + j * 8 + 2 * t;
            float2 bv = make_float2(0.f, 0.f);
            if (bias) bv = *(const float2*)(bias + cn);
#pragma unroll
            for (int h = 0; h < 2; ++h) {
                int row = r0 + h * 8;
                if (row >= M) continue;
                float vx = acc[i][j][h * 2 + 0] + bv.x;
                float vy = acc[i][j][h * 2 + 1] + bv.y;
                if (relu) { vx = fmaxf(vx, 0.f); vy = fmaxf(vy, 0.f); }
                size_t o = (size_t)row * N + cn;
                if (C) *(float2*)(C + o) = make_float2(vx, vy);
                if (Ch) {
                    unsigned hh, ll;
                    bsplit(vx, vy, hh, ll);
                    *(unsigned*)(Ch + o) = hh;
                    *(unsigned*)(Cl + o) = ll;
                }
            }
        }
    }
}

// ---------------- fp32 SGEMM (N=40 head only) ----------------
#define BM 128
#define BN 64
#define BK 16
#define TM 8
#define TN 4
__global__ __launch_bounds__(256) void k_sgemm(
    const float* __restrict__ A, const float* __restrict__ B,
    const float* __restrict__ bias, float* __restrict__ C,
    int M, int N, int K) {
    __shared__ float As[BK][BM];
    __shared__ float Bs[BK][BN];
    const int tid = threadIdx.x;
    const int tx = tid & 15, ty = tid >> 4;
    const int bm = blockIdx.y * BM, bn = blockIdx.x * BN;
    float acc[TM][TN];
#pragma unroll
    for (int i = 0; i < TM; ++i)
#pragma unroll
        for (int j = 0; j < TN; ++j) acc[i][j] = 0.f;
    const int ar = tid >> 2, ac = (tid & 3) << 2;
    const int br = tid >> 4, bc = (tid & 15) << 2;
    for (int k0 = 0; k0 < K; k0 += BK) {
#pragma unroll
        for (int h = 0; h < 2; ++h) {
            int r = ar + h * 64, gr = bm + r;
            float4 v = make_float4(0.f, 0.f, 0.f, 0.f);
            if (gr < M) v = *(const float4*)(A + (size_t)gr * K + k0 + ac);
            As[ac + 0][r] = v.x; As[ac + 1][r] = v.y;
            As[ac + 2][r] = v.z; As[ac + 3][r] = v.w;
        }
        {
            int gc = bn + bc;
            float4 v = make_float4(0.f, 0.f, 0.f, 0.f);
            if (gc < N) v = *(const float4*)(B + (size_t)(k0 + br) * N + gc);
            *(float4*)&Bs[br][bc] = v;
        }
        __syncthreads();
#pragma unroll
        for (int kk = 0; kk < BK; ++kk) {
            float aF[TM], bF[TN];
#pragma unroll
            for (int i = 0; i < TM; ++i) aF[i] = As[kk][ty * TM + i];
#pragma unroll
            for (int j = 0; j < TN; ++j) bF[j] = Bs[kk][tx * TN + j];
#pragma unroll
            for (int i = 0; i < TM; ++i)
#pragma unroll
                for (int j = 0; j < TN; ++j) acc[i][j] = fmaf(aF[i], bF[j], acc[i][j]);
        }
        __syncthreads();
    }
    const int col = bn + tx * TN;
    if (col < N) {
        float4 bv = make_float4(0.f, 0.f, 0.f, 0.f);
        if (bias) bv = *(const float4*)(bias + col);
#pragma unroll
        for (int i = 0; i < TM; ++i) {
            int row = bm + ty * TM + i;
            if (row >= M) continue;
            *(float4*)(C + (size_t)row * N + col) =
                make_float4(acc[i][0] + bv.x, acc[i][1] + bv.y,
                            acc[i][2] + bv.z, acc[i][3] + bv.w);
        }
    }
}

// ---------------- fused relu+residual+LayerNorm + split ----------------
__global__ void k_ln(const float* __restrict__ t, float* __restrict__ h,
                     ushortx* __restrict__ hh, ushortx* __restrict__ hl,
                     const float* __restrict__ g, const float* __restrict__ b, int rows) {
    int w = (blockIdx.x * blockDim.x + threadIdx.x) >> 5;
    int lane = threadIdx.x & 31;
    if (w >= rows) return;
    const float4* t4 = (const float4*)(t + (size_t)w * HD);
    float4* h4 = (float4*)(h + (size_t)w * HD);
    float4 x0 = t4[lane], x1 = t4[lane + 32];
    float4 p0 = h4[lane], p1 = h4[lane + 32];
    float u[8];
    u[0] = fmaxf(x0.x, 0.f) + p0.x; u[1] = fmaxf(x0.y, 0.f) + p0.y;
    u[2] = fmaxf(x0.z, 0.f) + p0.z; u[3] = fmaxf(x0.w, 0.f) + p0.w;
    u[4] = fmaxf(x1.x, 0.f) + p1.x; u[5] = fmaxf(x1.y, 0.f) + p1.y;
    u[6] = fmaxf(x1.z, 0.f) + p1.z; u[7] = fmaxf(x1.w, 0.f) + p1.w;
    float s = 0.f;
#pragma unroll
    for (int i = 0; i < 8; ++i) s += u[i];
    s = warp_sum(s);
    float mu = s * (1.f / HD);
    float v = 0.f;
#pragma unroll
    for (int i = 0; i < 8; ++i) { float d = u[i] - mu; v += d * d; }
    v = warp_sum(v);
    float rstd = rsqrtf(v * (1.f / HD) + 1e-5f);
    const float4* g4 = (const float4*)g;
    const float4* b4 = (const float4*)b;
    float4 ga = g4[lane], gb = g4[lane + 32];
    float4 ba = b4[lane], bb = b4[lane + 32];
    float o[8];
    o[0] = (u[0] - mu) * rstd * ga.x + ba.x; o[1] = (u[1] - mu) * rstd * ga.y + ba.y;
    o[2] = (u[2] - mu) * rstd * ga.z + ba.z; o[3] = (u[3] - mu) * rstd * ga.w + ba.w;
    o[4] = (u[4] - mu) * rstd * gb.x + bb.x; o[5] = (u[5] - mu) * rstd * gb.y + bb.y;
    o[6] = (u[6] - mu) * rstd * gb.z + bb.z; o[7] = (u[7] - mu) * rstd * gb.w + bb.w;
    h4[lane] = make_float4(o[0], o[1], o[2], o[3]);
    h4[lane + 32] = make_float4(o[4], o[5], o[6], o[7]);
    unsigned* hhu = (unsigned*)(hh + (size_t)w * HD);
    unsigned* hlu = (unsigned*)(hl + (size_t)w * HD);
    unsigned hv0, lv0, hv1, lv1;
    bsplit(o[0], o[1], hv0, lv0); bsplit(o[2], o[3], hv1, lv1);
    hhu[lane * 2] = hv0; hhu[lane * 2 + 1] = hv1;
    hlu[lane * 2] = lv0; hlu[lane * 2 + 1] = lv1;
    bsplit(o[4], o[5], hv0, lv0); bsplit(o[6], o[7], hv1, lv1);
    hhu[64 + lane * 2] = hv0; hhu[64 + lane * 2 + 1] = hv1;
    hlu[64 + lane * 2] = lv0; hlu[64 + lane * 2 + 1] = lv1;
}

__global__ void k_lsm(float* __restrict__ x, int rows) {
    int w = (blockIdx.x * blockDim.x + threadIdx.x) >> 5;
    int lane = threadIdx.x & 31;
    if (w >= rows) return;
    float* r = x + (size_t)w * CN;
    float v0 = r[lane];
    bool has1 = (lane + 32) < CN;
    float v1 = has1 ? r[lane + 32] : -3.4e38f;
    float m = warp_max(fmaxf(v0, v1));
    float s = expf(v0 - m) + (has1 ? expf(v1 - m) : 0.f);
    s = warp_sum(s);
    float lse = m + logf(s);
    r[lane] = v0 - lse;
    if (has1) r[lane + 32] = v1 - lse;
}

// ---------------- host ----------------
static inline void bgemm(const ushortx* ah0, const ushortx* al0,
                         const ushortx* ah1, const ushortx* al1,
                         const ushortx* ah2, const ushortx* al2,
                         const ushortx* Bh, const ushortx* Bl,
                         const float* bias, float* C, ushortx* Ch, ushortx* Cl,
                         int M, int N, int Ktot, int Kseg, int relu) {
    dim3 grid(N >> 7, (M + 127) >> 7);
    k_bgemm<<<grid, 256, NSTAGE * STAGE>>>(ah0, al0, ah1, al1, ah2, al2,
                                           Bh, Bl, bias, C, Ch, Cl,
                                           M, N, Ktot, Kseg, relu);
}

extern "C" void kernel_launch(void* const* d_in, const int* in_sizes, int n_in,
                              void* d_out, int out_size) {
    const float* x_author     = (const float*)d_in[0];
    const float* x_paper      = (const float*)d_in[1];
    const int*   e0_src       = (const int*)d_in[2];
    const int*   e0_dst       = (const int*)d_in[3];
    const int*   e1_src       = (const int*)d_in[4];
    const int*   e1_dst       = (const int*)d_in[5];
    const int*   e2_src       = (const int*)d_in[6];
    const int*   e2_dst       = (const int*)d_in[7];
    const float* emb_W_author = (const float*)d_in[8];
    const float* emb_b_author = (const float*)d_in[9];
    const float* emb_W_paper  = (const float*)d_in[10];
    const float* emb_b_paper  = (const float*)d_in[11];
    const float* W_self       = (const float*)d_in[12];
    const float* W_neigh      = (const float*)d_in[13];
    const float* b_conv       = (const float*)d_in[14];
    const float* ln_g_author  = (const float*)d_in[15];
    const float* ln_b_author  = (const float*)d_in[16];
    const float* ln_g_paper   = (const float*)d_in[17];
    const float* ln_b_paper   = (const float*)d_in[18];
    const float* pW1_author   = (const float*)d_in[19];
    const float* pb1_author   = (const float*)d_in[20];
    const float* pW2_author   = (const float*)d_in[21];
    const float* pb2_author   = (const float*)d_in[22];
    const float* pW1_paper    = (const float*)d_in[23];
    const float* pb1_paper    = (const float*)d_in[24];
    const float* pW2_paper    = (const float*)d_in[25];
    const float* pb2_paper    = (const float*)d_in[26];

    cudaFuncSetAttribute(k_bgemm, cudaFuncAttributeMaxDynamicSharedMemorySize, NSTAGE * STAGE);

    float *p_ha, *p_hp, *p_ta, *p_tp, *p_b01;
    ushortx *p_xah, *p_xal, *p_xph, *p_xpl, *p_hah, *p_hal, *p_hph, *p_hpl;
    ushortx *p_ag0h, *p_ag0l, *p_ag1h, *p_ag1l, *p_wh, *p_wl;
    int *p_deg, *p_off, *p_cur, *p_perm;
    cudaGetSymbolAddress((void**)&p_ha, g_ha);
    cudaGetSymbolAddress((void**)&p_hp, g_hp);
    cudaGetSymbolAddress((void**)&p_ta, g_ta);
    cudaGetSymbolAddress((void**)&p_tp, g_tp);
    cudaGetSymbolAddress((void**)&p_b01, g_b01);
    cudaGetSymbolAddress((void**)&p_xah, g_xah);
    cudaGetSymbolAddress((void**)&p_xal, g_xal);
    cudaGetSymbolAddress((void**)&p_xph, g_xph);
    cudaGetSymbolAddress((void**)&p_xpl, g_xpl);
    cudaGetSymbolAddress((void**)&p_hah, g_hah);
    cudaGetSymbolAddress((void**)&p_hal, g_hal);
    cudaGetSymbolAddress((void**)&p_hph, g_hph);
    cudaGetSymbolAddress((void**)&p_hpl, g_hpl);
    cudaGetSymbolAddress((void**)&p_ag0h, g_ag0h);
    cudaGetSymbolAddress((void**)&p_ag0l, g_ag0l);
    cudaGetSymbolAddress((void**)&p_ag1h, g_ag1h);
    cudaGetSymbolAddress((void**)&p_ag1l, g_ag1l);
    cudaGetSymbolAddress((void**)&p_wh, g_wh);
    cudaGetSymbolAddress((void**)&p_wl, g_wl);
    cudaGetSymbolAddress((void**)&p_deg, g_deg);
    cudaGetSymbolAddress((void**)&p_off, g_off);
    cudaGetSymbolAddress((void**)&p_cur, g_cur);
    cudaGetSymbolAddress((void**)&p_perm, g_perm);

    // ---- all input/weight/bias splits in ONE launch ----
    k_split_all<<<(NSPLIT_TOT + 255) / 256, 256>>>(
        x_author, x_paper, emb_W_author, emb_W_paper, W_self, W_neigh,
        pW1_author, pW1_paper, pW2_paper, b_conv,
        p_wh, p_wl, p_xah, p_xal, p_xph, p_xpl, p_b01);

    // ---- CSR build, 4 launches total ----
    k_zero3<<<(3 * PN + 255) / 256, 256>>>(p_deg);
    k_hist3<<<(3 * EN + 255) / 256, 256>>>(e0_dst, e1_dst, e2_dst, p_deg);
    k_scan3<<<3, 1024>>>(p_deg, p_off, p_cur);
    k_fill3<<<(3 * EN + 255) / 256, 256>>>(e0_src, e0_dst, e1_src, e1_dst,
                                           e2_src, e2_dst, p_cur, p_perm);

    // ---- embeddings (fp32 h + split h) ----
    bgemm(p_xah, p_xal, 0, 0, 0, 0, p_wh + WOFF_EMBA, p_wl + WOFF_EMBA,
          emb_b_author, p_ha, p_hah, p_hal, AN, HD, DIN, DIN, 0);
    bgemm(p_xph, p_xpl, 0, 0, 0, 0, p_wh + WOFF_EMBP, p_wl + WOFF_EMBP,
          emb_b_paper, p_hp, p_hph, p_hpl, PN, HD, DIN, DIN, 0);

    // ---- 2 SAGE layers ----
    const int WPO[2] = {WOFF_WP0, WOFF_WP1};
    const int WAO[2] = {WOFF_WA0, WOFF_WA1};
    const int AGG_BLK = 128;
    for (int l = 0; l < 2; ++l) {
        const float* bc = b_conv + (size_t)l * 3 * HD;
        k_agg<<<(PN * 32 + AGG_BLK - 1) / AGG_BLK, AGG_BLK>>>(
            p_ha, p_off + 0 * (PN + 1), p_perm + 0 * EN, p_ag0h, p_ag0l, PN);
        k_agg<<<(PN * 32 + AGG_BLK - 1) / AGG_BLK, AGG_BLK>>>(
            p_hp, p_off + 1 * (PN + 1), p_perm + 1 * EN, p_ag1h, p_ag1l, PN);
        bgemm(p_hph, p_hpl, p_ag0h, p_ag0l, p_ag1h, p_ag1l,
              p_wh + WPO[l], p_wl + WPO[l], p_b01 + l * HD,
              p_tp, 0, 0, PN, HD, 3 * HD, HD, 0);
        k_agg<<<(AN * 32 + AGG_BLK - 1) / AGG_BLK, AGG_BLK>>>(
            p_hp, p_off + 2 * (PN + 1), p_perm + 2 * EN, p_ag0h, p_ag0l, AN);
        bgemm(p_hah, p_hal, p_ag0h, p_ag0l, 0, 0,
              p_wh + WAO[l], p_wl + WAO[l], bc + 2 * HD,
              p_ta, 0, 0, AN, HD, 2 * HD, HD, 0);
        k_ln<<<(AN * 32 + 127) / 128, 128>>>(p_ta, p_ha, p_hah, p_hal,
                                             ln_g_author, ln_b_author, AN);
        k_ln<<<(PN * 32 + 127) / 128, 128>>>(p_tp, p_hp, p_hph, p_hpl,
                                             ln_g_paper, ln_b_paper, PN);
    }

    // ---- output heads ----
    float* out = (float*)d_out;
    bgemm(p_hah, p_hal, 0, 0, 0, 0, p_wh + WOFF_P1A, p_wl + WOFF_P1A,
          pb1_author, p_ta, 0, 0, AN, HD, HD, HD, 1);
    {
        dim3 grid((CN + BN - 1) / BN, (AN + BM - 1) / BM);
        k_sgemm<<<grid, 256>>>(p_ta, pW2_author, pb2_author, out, AN, CN, HD);
    }
    k_lsm<<<(AN * 32 + 127) / 128, 128>>>(out, AN);
    bgemm(p_hph, p_hpl, 0, 0, 0, 0, p_wh + WOFF_P1P, p_wl + WOFF_P1P,
          pb1_paper, 0, p_ag0h, p_ag0l, PN, HD, HD, HD, 1);
    bgemm(p_ag0h, p_ag0l, 0, 0, 0, 0, p_wh + WOFF_P2P, p_wl + WOFF_P2P,
          pb2_paper, out + (size_t)AN * CN, 0, 0, PN, HD, HD, HD, 0);
}

// round 10
// speedup vs baseline: 2.2384x; 1.0672x over previous
#include <cuda_runtime.h>
#include <cuda_bf16.h>
#include <math.h>

#define AN 50000
#define PN 100000
#define DIN 128
#define HD 256
#define CN 40
#define EN 300000

typedef unsigned short ushortx;

// fp32 state
__device__ float g_ha[(size_t)AN * HD];
__device__ float g_hp[(size_t)PN * HD];
__device__ float g_ta[(size_t)AN * HD];
__device__ float g_tp[(size_t)PN * HD];
__device__ float g_b01[2 * HD];
// bf16 hi/lo operand buffers
__device__ ushortx g_xah[(size_t)AN * DIN], g_xal[(size_t)AN * DIN];
__device__ ushortx g_xph[(size_t)PN * DIN], g_xpl[(size_t)PN * DIN];
__device__ ushortx g_hah[(size_t)AN * HD],  g_hal[(size_t)AN * HD];
__device__ ushortx g_hph[(size_t)PN * HD],  g_hpl[(size_t)PN * HD];
__device__ ushortx g_ag0h[(size_t)PN * HD], g_ag0l[(size_t)PN * HD];
__device__ ushortx g_ag1h[(size_t)PN * HD], g_ag1l[(size_t)PN * HD];
// split weights, stacked segments (contiguous: dst index == linear j)
#define WOFF_EMBA 0
#define WOFF_EMBP (WOFF_EMBA + 128 * 256)
#define WOFF_WP0  (WOFF_EMBP + 128 * 256)
#define WOFF_WA0  (WOFF_WP0 + 768 * 256)
#define WOFF_WP1  (WOFF_WA0 + 512 * 256)
#define WOFF_WA1  (WOFF_WP1 + 768 * 256)
#define WOFF_P1A  (WOFF_WA1 + 512 * 256)
#define WOFF_P1P  (WOFF_P1A + 256 * 256)
#define WOFF_P2P  (WOFF_P1P + 256 * 256)
#define WTOT      (WOFF_P2P + 256 * 256)
__device__ ushortx g_wh[WTOT], g_wl[WTOT];
// CSR
#define NB_P 98                    // ceil(PN/1024)
#define NB_A 49                    // ceil(AN/1024)
#define NBT (NB_P + NB_P + NB_A)   // 245
__device__ int g_deg[3 * PN];
__device__ int g_off[3 * (PN + 1)];
__device__ int g_cur[3 * PN];
__device__ int g_perm[3 * EN];
__device__ int g_part[NBT];

// ---------------- helpers ----------------
__device__ __forceinline__ unsigned smem_u32(const void* p) {
    unsigned a;
    asm("{ .reg .u64 t; cvta.to.shared.u64 t, %1; cvt.u32.u64 %0, t; }" : "=r"(a) : "l"(p));
    return a;
}
__device__ __forceinline__ void cp16(unsigned dst, const void* src, int n) {
    asm volatile("cp.async.cg.shared.global [%0], [%1], 16, %2;" :: "r"(dst), "l"(src), "r"(n));
}
#define CP_COMMIT() asm volatile("cp.async.commit_group;" ::: "memory")
#define CP_WAIT0()  asm volatile("cp.async.wait_group 0;" ::: "memory")

__device__ __forceinline__ void bsplit(float x, float y, unsigned& h, unsigned& l) {
    __nv_bfloat162 hb = __floats2bfloat162_rn(x, y);
    float rx = x - __bfloat162float(hb.x);
    float ry = y - __bfloat162float(hb.y);
    __nv_bfloat162 lb = __floats2bfloat162_rn(rx, ry);
    h = *(unsigned*)&hb;
    l = *(unsigned*)&lb;
}
#define MMA16816(c, a, b) \
    asm volatile("mma.sync.aligned.m16n8k16.row.col.f32.bf16.bf16.f32 " \
        "{%0,%1,%2,%3},{%4,%5,%6,%7},{%8,%9},{%0,%1,%2,%3};" \
        : "+f"((c)[0]), "+f"((c)[1]), "+f"((c)[2]), "+f"((c)[3]) \
        : "r"((a)[0]), "r"((a)[1]), "r"((a)[2]), "r"((a)[3]), "r"((b)[0]), "r"((b)[1]))
#define LDSM4(r, addr) \
    asm volatile("ldmatrix.sync.aligned.m8n8.x4.shared.b16 {%0,%1,%2,%3},[%4];" \
        : "=r"((r)[0]), "=r"((r)[1]), "=r"((r)[2]), "=r"((r)[3]) : "r"(addr))
#define LDSM4T(r, addr) \
    asm volatile("ldmatrix.sync.aligned.m8n8.x4.trans.shared.b16 {%0,%1,%2,%3},[%4];" \
        : "=r"((r)[0]), "=r"((r)[1]), "=r"((r)[2]), "=r"((r)[3]) : "r"(addr))

__device__ __forceinline__ float warp_sum(float v) {
#pragma unroll
    for (int o = 16; o; o >>= 1) v += __shfl_xor_sync(0xffffffffu, v, o);
    return v;
}
__device__ __forceinline__ int warp_sumi(int v) {
#pragma unroll
    for (int o = 16; o; o >>= 1) v += __shfl_xor_sync(0xffffffffu, v, o);
    return v;
}
__device__ __forceinline__ float warp_max(float v) {
#pragma unroll
    for (int o = 16; o; o >>= 1) v = fmaxf(v, __shfl_xor_sync(0xffffffffu, v, o));
    return v;
}

// ---------------- one mega split kernel: x inputs, all weights, biases -----
#define NXA (AN * DIN)
#define NXP (PN * DIN)
#define NSPLIT_TOT (NXA + NXP + WTOT + 512)

__global__ void k_split_all(
    const float* __restrict__ x_author, const float* __restrict__ x_paper,
    const float* __restrict__ emb_W_author, const float* __restrict__ emb_W_paper,
    const float* __restrict__ W_self, const float* __restrict__ W_neigh,
    const float* __restrict__ pW1_author, const float* __restrict__ pW1_paper,
    const float* __restrict__ pW2_paper, const float* __restrict__ b_conv,
    ushortx* __restrict__ wh, ushortx* __restrict__ wl,
    ushortx* __restrict__ xah, ushortx* __restrict__ xal,
    ushortx* __restrict__ xph, ushortx* __restrict__ xpl,
    float* __restrict__ b01) {
    int i = blockIdx.x * blockDim.x + threadIdx.x;
    if (i >= NSPLIT_TOT) return;
    if (i < NXA) {
        float v = x_author[i];
        __nv_bfloat16 h = __float2bfloat16(v);
        xah[i] = *(ushortx*)&h;
        __nv_bfloat16 l = __float2bfloat16(v - __bfloat162float(h));
        xal[i] = *(ushortx*)&l;
        return;
    }
    i -= NXA;
    if (i < NXP) {
        float v = x_paper[i];
        __nv_bfloat16 h = __float2bfloat16(v);
        xph[i] = *(ushortx*)&h;
        __nv_bfloat16 l = __float2bfloat16(v - __bfloat162float(h));
        xpl[i] = *(ushortx*)&l;
        return;
    }
    i -= NXP;
    if (i < WTOT) {
        const int j = i;
        const int Q = 65536;  // 256*256
        float v;
        if (j < Q)               v = (j < Q / 2) ? emb_W_author[j] : emb_W_paper[j - Q / 2];
        else if (j < 2 * Q)      { int r = j - Q;     v = W_self[r] + W_self[Q + r]; }
        else if (j < 3 * Q)      v = W_neigh[j - 2 * Q];
        else if (j < 4 * Q)      v = W_neigh[Q + j - 3 * Q];
        else if (j < 5 * Q)      v = W_self[2 * Q + j - 4 * Q];
        else if (j < 6 * Q)      v = W_neigh[2 * Q + j - 5 * Q];
        else if (j < 7 * Q)      { int r = j - 6 * Q; v = W_self[3 * Q + r] + W_self[4 * Q + r]; }
        else if (j < 8 * Q)      v = W_neigh[3 * Q + j - 7 * Q];
        else if (j < 9 * Q)      v = W_neigh[4 * Q + j - 8 * Q];
        else if (j < 10 * Q)     v = W_self[5 * Q + j - 9 * Q];
        else if (j < 11 * Q)     v = W_neigh[5 * Q + j - 10 * Q];
        else if (j < 12 * Q)     v = pW1_author[j - 11 * Q];
        else if (j < 13 * Q)     v = pW1_paper[j - 12 * Q];
        else                     v = pW2_paper[j - 13 * Q];
        __nv_bfloat16 h = __float2bfloat16(v);
        wh[j] = *(ushortx*)&h;
        __nv_bfloat16 l = __float2bfloat16(v - __bfloat162float(h));
        wl[j] = *(ushortx*)&l;
        return;
    }
    i -= WTOT;  // i in [0,512): combined conv biases per layer
    int l = i >> 8, c = i & 255;
    b01[i] = b_conv[l * 768 + c] + b_conv[l * 768 + 256 + c];
}

// ---------------- CSR build ----------------
__global__ void k_zero3(int* __restrict__ deg) {
    int i = blockIdx.x * blockDim.x + threadIdx.x;
    if (i < 3 * PN) deg[i] = 0;
}
__global__ void k_hist3(const int* __restrict__ d0, const int* __restrict__ d1,
                        const int* __restrict__ d2, int* __restrict__ deg) {
    int i = blockIdx.x * blockDim.x + threadIdx.x;
    if (i >= 3 * EN) return;
    int t = i / EN, k = i - t * EN;
    const int* d = (t == 0) ? d0 : ((t == 1) ? d1 : d2);
    atomicAdd(&deg[t * PN + d[k]], 1);
}
// ---- 3-phase multi-block exclusive scan over deg (per edge type) ----
__device__ __forceinline__ void scan_block_coords(int b, int& t, int& blk, int& nd) {
    if (b < NB_P)            { t = 0; blk = b;              nd = PN; }
    else if (b < 2 * NB_P)   { t = 1; blk = b - NB_P;       nd = PN; }
    else                     { t = 2; blk = b - 2 * NB_P;   nd = AN; }
}
__global__ void k_scan_sum(const int* __restrict__ deg, int* __restrict__ part) {
    __shared__ int sh[32];
    int t, blk, nd;
    scan_block_coords(blockIdx.x, t, blk, nd);
    int i = blk * 1024 + threadIdx.x;
    int v = (i < nd) ? deg[t * PN + i] : 0;
    v = warp_sumi(v);
    if ((threadIdx.x & 31) == 0) sh[threadIdx.x >> 5] = v;
    __syncthreads();
    if (threadIdx.x < 32) {
        int x = sh[threadIdx.x];
        x = warp_sumi(x);
        if (threadIdx.x == 0) part[blockIdx.x] = x;
    }
}
__global__ void k_scan_top(int* __restrict__ part, int* __restrict__ off) {
    int t = threadIdx.x;
    if (t >= 3) return;
    int base = (t == 0) ? 0 : ((t == 1) ? NB_P : 2 * NB_P);
    int n = (t == 2) ? NB_A : NB_P;
    int nd = (t == 2) ? AN : PN;
    int run = 0;
    for (int i = 0; i < n; ++i) { int v = part[base + i]; part[base + i] = run; run += v; }
    off[t * (PN + 1) + nd] = run;
}
__global__ void k_scan_apply(const int* __restrict__ deg, const int* __restrict__ part,
                             int* __restrict__ off, int* __restrict__ cur) {
    __shared__ int sh[1024];
    int t, blk, nd;
    scan_block_coords(blockIdx.x, t, blk, nd);
    int i = blk * 1024 + threadIdx.x;
    int v = (i < nd) ? deg[t * PN + i] : 0;
    sh[threadIdx.x] = v;
    __syncthreads();
#pragma unroll
    for (int d = 1; d < 1024; d <<= 1) {
        int x = (threadIdx.x >= d) ? sh[threadIdx.x - d] : 0;
        __syncthreads();
        sh[threadIdx.x] += x;
        __syncthreads();
    }
    if (i < nd) {
        int o = part[blockIdx.x] + sh[threadIdx.x] - v;  // exclusive
        off[t * (PN + 1) + i] = o;
        cur[t * PN + i] = o;
    }
}
__global__ void k_fill3(const int* __restrict__ s0, const int* __restrict__ d0,
                        const int* __restrict__ s1, const int* __restrict__ d1,
                        const int* __restrict__ s2, const int* __restrict__ d2,
                        int* __restrict__ cur, int* __restrict__ perm) {
    int i = blockIdx.x * blockDim.x + threadIdx.x;
    if (i >= 3 * EN) return;
    int t = i / EN, k = i - t * EN;
    const int* s = (t == 0) ? s0 : ((t == 1) ? s1 : s2);
    const int* d = (t == 0) ? d0 : ((t == 1) ? d1 : d2);
    int slot = atomicAdd(&cur[t * PN + d[k]], 1);
    perm[t * EN + slot] = s[k];
}

// ---------------- mean aggregation: fp32 gather -> bf16 hi/lo out ----------
__global__ void k_agg(const float* __restrict__ h, const int* __restrict__ off,
                      const int* __restrict__ perm, ushortx* __restrict__ oh,
                      ushortx* __restrict__ ol, int ndst) {
    int w = (blockIdx.x * blockDim.x + threadIdx.x) >> 5;
    int lane = threadIdx.x & 31;
    if (w >= ndst) return;
    int s = off[w], e = off[w + 1];
    float4 a0 = make_float4(0.f, 0.f, 0.f, 0.f);
    float4 a1 = make_float4(0.f, 0.f, 0.f, 0.f);
    for (int i = s; i < e; ++i) {
        const float4* r = (const float4*)(h + (size_t)perm[i] * HD);
        float4 v0 = __ldg(&r[lane]);
        float4 v1 = __ldg(&r[lane + 32]);
        a0.x += v0.x; a0.y += v0.y; a0.z += v0.z; a0.w += v0.w;
        a1.x += v1.x; a1.y += v1.y; a1.z += v1.z; a1.w += v1.w;
    }
    float inv = (e > s) ? 1.f / (float)(e - s) : 0.f;
    a0.x *= inv; a0.y *= inv; a0.z *= inv; a0.w *= inv;
    a1.x *= inv; a1.y *= inv; a1.z *= inv; a1.w *= inv;
    unsigned h0, l0, h1, l1;
    unsigned* ohu = (unsigned*)(oh + (size_t)w * HD);
    unsigned* olu = (unsigned*)(ol + (size_t)w * HD);
    bsplit(a0.x, a0.y, h0, l0); bsplit(a0.z, a0.w, h1, l1);
    ohu[lane * 2] = h0; ohu[lane * 2 + 1] = h1;
    olu[lane * 2] = l0; olu[lane * 2 + 1] = l1;
    bsplit(a1.x, a1.y, h0, l0); bsplit(a1.z, a1.w, h1, l1);
    ohu[64 + lane * 2] = h0; ohu[64 + lane * 2 + 1] = h1;
    olu[64 + lane * 2] = l0; olu[64 + lane * 2 + 1] = l1;
}

// ---------------- bf16-input HMMA 3-split GEMM, 2-stage, occ=2, 1 sync/iter
#define A_ST 80
#define B_ST 272
#define OFF_AL 10240
#define OFF_BH 20480
#define OFF_BL 29184
#define STAGE 37888
#define NSTAGE 2

__global__ __launch_bounds__(256, 2) void k_bgemm(
    const ushortx* __restrict__ ah0, const ushortx* __restrict__ al0,
    const ushortx* __restrict__ ah1, const ushortx* __restrict__ al1,
    const ushortx* __restrict__ ah2, const ushortx* __restrict__ al2,
    const ushortx* __restrict__ Bh, const ushortx* __restrict__ Bl,
    const float* __restrict__ bias, float* __restrict__ C,
    ushortx* __restrict__ Ch, ushortx* __restrict__ Cl,
    int M, int N, int Ktot, int Kseg, int relu) {
    extern __shared__ char smc[];
    const int tid = threadIdx.x;
    const int lane = tid & 31;
    const int warp = tid >> 5;
    const int g = lane >> 2;
    const int t = lane & 3;
    const int wm = warp & 1;
    const int wn = warp >> 1;
    const int bm = blockIdx.y * 128;
    const int bn = blockIdx.x * 128;
    const unsigned sbase = smem_u32(smc);
    const int NIT = Ktot >> 5;
    const int segC = Kseg >> 5;

    float acc[4][4][4];
#pragma unroll
    for (int i = 0; i < 4; ++i)
#pragma unroll
        for (int j = 0; j < 4; ++j)
#pragma unroll
            for (int q = 0; q < 4; ++q) acc[i][j][q] = 0.f;

    const int ca = tid * 2;
    const int arow0 = ca >> 2, ac0 = ca & 3;
    const int arow1 = (ca + 1) >> 2, ac1 = (ca + 1) & 3;
    const int brow0 = ca >> 4, bc0 = ca & 15;
    const int brow1 = (ca + 1) >> 4, bc1 = (ca + 1) & 15;

    auto issue = [&](int it) {
        int seg = it / segC;
        int kloc = (it - seg * segC) << 5;
        const ushortx* pah = (seg == 0) ? ah0 : ((seg == 1) ? ah1 : ah2);
        const ushortx* pal = (seg == 0) ? al0 : ((seg == 1) ? al1 : al2);
        unsigned sa = sbase + (it & 1) * STAGE;
        int gr0 = bm + arow0, gr1 = bm + arow1;
        int ok0 = gr0 < M ? 16 : 0, ok1 = gr1 < M ? 16 : 0;
        size_t off0 = (size_t)(gr0 < M ? gr0 : 0) * Kseg + kloc + ac0 * 8;
        size_t off1 = (size_t)(gr1 < M ? gr1 : 0) * Kseg + kloc + ac1 * 8;
        cp16(sa + arow0 * A_ST + ac0 * 16, pah + off0, ok0);
        cp16(sa + arow1 * A_ST + ac1 * 16, pah + off1, ok1);
        cp16(sa + OFF_AL + arow0 * A_ST + ac0 * 16, pal + off0, ok0);
        cp16(sa + OFF_AL + arow1 * A_ST + ac1 * 16, pal + off1, ok1);
        int kg = it << 5;
        size_t bo0 = (size_t)(kg + brow0) * N + bn + bc0 * 8;
        size_t bo1 = (size_t)(kg + brow1) * N + bn + bc1 * 8;
        cp16(sa + OFF_BH + brow0 * B_ST + bc0 * 16, Bh + bo0, 16);
        cp16(sa + OFF_BH + brow1 * B_ST + bc1 * 16, Bh + bo1, 16);
        cp16(sa + OFF_BL + brow0 * B_ST + bc0 * 16, Bl + bo0, 16);
        cp16(sa + OFF_BL + brow1 * B_ST + bc1 * 16, Bl + bo1, 16);
        CP_COMMIT();
    };

    issue(0);
    for (int it = 0; it < NIT; ++it) {
        CP_WAIT0();                 // group(it) complete (only pending group)
        __syncthreads();            // all warps done reading buf^1 (iter it-1)
        if (it + 1 < NIT) issue(it + 1);  // overlaps compute of this iter
        const unsigned sa = sbase + (it & 1) * STAGE;
#pragma unroll
        for (int kk = 0; kk < 2; ++kk) {
            unsigned ah[4][4], al[4][4], bh[2][4], bl[2][4];
            unsigned abase = sa + (wm * 64 + (lane & 15)) * A_ST + kk * 32 + ((lane >> 4) << 4);
#pragma unroll
            for (int i = 0; i < 4; ++i) {
                LDSM4(ah[i], abase + i * (16 * A_ST));
                LDSM4(al[i], abase + i * (16 * A_ST) + OFF_AL);
            }
            unsigned bbase = sa + OFF_BH + (kk * 16 + (lane & 15)) * B_ST +
                             (wn * 32 + ((lane >> 4) << 3)) * 2;
#pragma unroll
            for (int p = 0; p < 2; ++p) {
                LDSM4T(bh[p], bbase + p * 32);
                LDSM4T(bl[p], bbase + p * 32 + (OFF_BL - OFF_BH));
            }
#pragma unroll
            for (int i = 0; i < 4; ++i)
#pragma unroll
                for (int j = 0; j < 4; ++j) {
                    unsigned* bhj = &bh[j >> 1][(j & 1) * 2];
                    unsigned* blj = &bl[j >> 1][(j & 1) * 2];
                    MMA16816(acc[i][j], ah[i], bhj);
                    MMA16816(acc[i][j], ah[i], blj);
                    MMA16816(acc[i][j], al[i], bhj);
                }
        }
    }

#pragma unroll
    for (int i = 0; i < 4; ++i) {
        int r0 = bm + wm * 64 + i * 16 + g;
#pragma unroll
        for (int j = 0; j < 4; ++j) {
            int cn = bn + wn * 32 + j * 8 + 2 * t;
            float2 bv = make_float2(0.f, 0.f);
            if (bias) bv = *(const float2*)(bias + cn);
#pragma unroll
            for (int h = 0; h < 2; ++h) {
                int row = r0 + h * 8;
                if (row >= M) continue;
                float vx = acc[i][j][h * 2 + 0] + bv.x;
                float vy = acc[i][j][h * 2 + 1] + bv.y;
                if (relu) { vx = fmaxf(vx, 0.f); vy = fmaxf(vy, 0.f); }
                size_t o = (size_t)row * N + cn;
                if (C) *(float2*)(C + o) = make_float2(vx, vy);
                if (Ch) {
                    unsigned hh, ll;
                    bsplit(vx, vy, hh, ll);
                    *(unsigned*)(Ch + o) = hh;
                    *(unsigned*)(Cl + o) = ll;
                }
            }
        }
    }
}

// ---------------- fp32 SGEMM (N=40 head only) ----------------
#define BM 128
#define BN 64
#define BK 16
#define TM 8
#define TN 4
__global__ __launch_bounds__(256) void k_sgemm(
    const float* __restrict__ A, const float* __restrict__ B,
    const float* __restrict__ bias, float* __restrict__ C,
    int M, int N, int K) {
    __shared__ float As[BK][BM];
    __shared__ float Bs[BK][BN];
    const int tid = threadIdx.x;
    const int tx = tid & 15, ty = tid >> 4;
    const int bm = blockIdx.y * BM, bn = blockIdx.x * BN;
    float acc[TM][TN];
#pragma unroll
    for (int i = 0; i < TM; ++i)
#pragma unroll
        for (int j = 0; j < TN; ++j) acc[i][j] = 0.f;
    const int ar = tid >> 2, ac = (tid & 3) << 2;
    const int br = tid >> 4, bc = (tid & 15) << 2;
    for (int k0 = 0; k0 < K; k0 += BK) {
#pragma unroll
        for (int h = 0; h < 2; ++h) {
            int r = ar + h * 64, gr = bm + r;
            float4 v = make_float4(0.f, 0.f, 0.f, 0.f);
            if (gr < M) v = *(const float4*)(A + (size_t)gr * K + k0 + ac);
            As[ac + 0][r] = v.x; As[ac + 1][r] = v.y;
            As[ac + 2][r] = v.z; As[ac + 3][r] = v.w;
        }
        {
            int gc = bn + bc;
            float4 v = make_float4(0.f, 0.f, 0.f, 0.f);
            if (gc < N) v = *(const float4*)(B + (size_t)(k0 + br) * N + gc);
            *(float4*)&Bs[br][bc] = v;
        }
        __syncthreads();
#pragma unroll
        for (int kk = 0; kk < BK; ++kk) {
            float aF[TM], bF[TN];
#pragma unroll
            for (int i = 0; i < TM; ++i) aF[i] = As[kk][ty * TM + i];
#pragma unroll
            for (int j = 0; j < TN; ++j) bF[j] = Bs[kk][tx * TN + j];
#pragma unroll
            for (int i = 0; i < TM; ++i)
#pragma unroll
                for (int j = 0; j < TN; ++j) acc[i][j] = fmaf(aF[i], bF[j], acc[i][j]);
        }
        __syncthreads();
    }
    const int col = bn + tx * TN;
    if (col < N) {
        float4 bv = make_float4(0.f, 0.f, 0.f, 0.f);
        if (bias) bv = *(const float4*)(bias + col);
#pragma unroll
        for (int i = 0; i < TM; ++i) {
            int row = bm + ty * TM + i;
            if (row >= M) continue;
            *(float4*)(C + (size_t)row * N + col) =
                make_float4(acc[i][0] + bv.x, acc[i][1] + bv.y,
                            acc[i][2] + bv.z, acc[i][3] + bv.w);
        }
    }
}

// ---------------- fused relu+residual+LayerNorm + split ----------------
__global__ void k_ln(const float* __restrict__ t, float* __restrict__ h,
                     ushortx* __restrict__ hh, ushortx* __restrict__ hl,
                     const float* __restrict__ g, const float* __restrict__ b, int rows) {
    int w = (blockIdx.x * blockDim.x + threadIdx.x) >> 5;
    int lane = threadIdx.x & 31;
    if (w >= rows) return;
    const float4* t4 = (const float4*)(t + (size_t)w * HD);
    float4* h4 = (float4*)(h + (size_t)w * HD);
    float4 x0 = t4[lane], x1 = t4[lane + 32];
    float4 p0 = h4[lane], p1 = h4[lane + 32];
    float u[8];
    u[0] = fmaxf(x0.x, 0.f) + p0.x; u[1] = fmaxf(x0.y, 0.f) + p0.y;
    u[2] = fmaxf(x0.z, 0.f) + p0.z; u[3] = fmaxf(x0.w, 0.f) + p0.w;
    u[4] = fmaxf(x1.x, 0.f) + p1.x; u[5] = fmaxf(x1.y, 0.f) + p1.y;
    u[6] = fmaxf(x1.z, 0.f) + p1.z; u[7] = fmaxf(x1.w, 0.f) + p1.w;
    float s = 0.f;
#pragma unroll
    for (int i = 0; i < 8; ++i) s += u[i];
    s = warp_sum(s);
    float mu = s * (1.f / HD);
    float v = 0.f;
#pragma unroll
    for (int i = 0; i < 8; ++i) { float d = u[i] - mu; v += d * d; }
    v = warp_sum(v);
    float rstd = rsqrtf(v * (1.f / HD) + 1e-5f);
    const float4* g4 = (const float4*)g;
    const float4* b4 = (const float4*)b;
    float4 ga = g4[lane], gb = g4[lane + 32];
    float4 ba = b4[lane], bb = b4[lane + 32];
    float o[8];
    o[0] = (u[0] - mu) * rstd * ga.x + ba.x; o[1] = (u[1] - mu) * rstd * ga.y + ba.y;
    o[2] = (u[2] - mu) * rstd * ga.z + ba.z; o[3] = (u[3] - mu) * rstd * ga.w + ba.w;
    o[4] = (u[4] - mu) * rstd * gb.x + bb.x; o[5] = (u[5] - mu) * rstd * gb.y + bb.y;
    o[6] = (u[6] - mu) * rstd * gb.z + bb.z; o[7] = (u[7] - mu) * rstd * gb.w + bb.w;
    h4[lane] = make_float4(o[0], o[1], o[2], o[3]);
    h4[lane + 32] = make_float4(o[4], o[5], o[6], o[7]);
    unsigned* hhu = (unsigned*)(hh + (size_t)w * HD);
    unsigned* hlu = (unsigned*)(hl + (size_t)w * HD);
    unsigned hv0, lv0, hv1, lv1;
    bsplit(o[0], o[1], hv0, lv0); bsplit(o[2], o[3], hv1, lv1);
    hhu[lane * 2] = hv0; hhu[lane * 2 + 1] = hv1;
    hlu[lane * 2] = lv0; hlu[lane * 2 + 1] = lv1;
    bsplit(o[4], o[5], hv0, lv0); bsplit(o[6], o[7], hv1, lv1);
    hhu[64 + lane * 2] = hv0; hhu[64 + lane * 2 + 1] = hv1;
    hlu[64 + lane * 2] = lv0; hlu[64 + lane * 2 + 1] = lv1;
}

__global__ void k_lsm(float* __restrict__ x, int rows) {
    int w = (blockIdx.x * blockDim.x + threadIdx.x) >> 5;
    int lane = threadIdx.x & 31;
    if (w >= rows) return;
    float* r = x + (size_t)w * CN;
    float v0 = r[lane];
    bool has1 = (lane + 32) < CN;
    float v1 = has1 ? r[lane + 32] : -3.4e38f;
    float m = warp_max(fmaxf(v0, v1));
    float s = expf(v0 - m) + (has1 ? expf(v1 - m) : 0.f);
    s = warp_sum(s);
    float lse = m + logf(s);
    r[lane] = v0 - lse;
    if (has1) r[lane + 32] = v1 - lse;
}

// ---------------- host ----------------
static inline void bgemm(const ushortx* ah0, const ushortx* al0,
                         const ushortx* ah1, const ushortx* al1,
                         const ushortx* ah2, const ushortx* al2,
                         const ushortx* Bh, const ushortx* Bl,
                         const float* bias, float* C, ushortx* Ch, ushortx* Cl,
                         int M, int N, int Ktot, int Kseg, int relu) {
    dim3 grid(N >> 7, (M + 127) >> 7);
    k_bgemm<<<grid, 256, NSTAGE * STAGE>>>(ah0, al0, ah1, al1, ah2, al2,
                                           Bh, Bl, bias, C, Ch, Cl,
                                           M, N, Ktot, Kseg, relu);
}

extern "C" void kernel_launch(void* const* d_in, const int* in_sizes, int n_in,
                              void* d_out, int out_size) {
    const float* x_author     = (const float*)d_in[0];
    const float* x_paper      = (const float*)d_in[1];
    const int*   e0_src       = (const int*)d_in[2];
    const int*   e0_dst       = (const int*)d_in[3];
    const int*   e1_src       = (const int*)d_in[4];
    const int*   e1_dst       = (const int*)d_in[5];
    const int*   e2_src       = (const int*)d_in[6];
    const int*   e2_dst       = (const int*)d_in[7];
    const float* emb_W_author = (const float*)d_in[8];
    const float* emb_b_author = (const float*)d_in[9];
    const float* emb_W_paper  = (const float*)d_in[10];
    const float* emb_b_paper  = (const float*)d_in[11];
    const float* W_self       = (const float*)d_in[12];
    const float* W_neigh      = (const float*)d_in[13];
    const float* b_conv       = (const float*)d_in[14];
    const float* ln_g_author  = (const float*)d_in[15];
    const float* ln_b_author  = (const float*)d_in[16];
    const float* ln_g_paper   = (const float*)d_in[17];
    const float* ln_b_paper   = (const float*)d_in[18];
    const float* pW1_author   = (const float*)d_in[19];
    const float* pb1_author   = (const float*)d_in[20];
    const float* pW2_author   = (const float*)d_in[21];
    const float* pb2_author   = (const float*)d_in[22];
    const float* pW1_paper    = (const float*)d_in[23];
    const float* pb1_paper    = (const float*)d_in[24];
    const float* pW2_paper    = (const float*)d_in[25];
    const float* pb2_paper    = (const float*)d_in[26];

    cudaFuncSetAttribute(k_bgemm, cudaFuncAttributeMaxDynamicSharedMemorySize, NSTAGE * STAGE);

    float *p_ha, *p_hp, *p_ta, *p_tp, *p_b01;
    ushortx *p_xah, *p_xal, *p_xph, *p_xpl, *p_hah, *p_hal, *p_hph, *p_hpl;
    ushortx *p_ag0h, *p_ag0l, *p_ag1h, *p_ag1l, *p_wh, *p_wl;
    int *p_deg, *p_off, *p_cur, *p_perm, *p_part;
    cudaGetSymbolAddress((void**)&p_ha, g_ha);
    cudaGetSymbolAddress((void**)&p_hp, g_hp);
    cudaGetSymbolAddress((void**)&p_ta, g_ta);
    cudaGetSymbolAddress((void**)&p_tp, g_tp);
    cudaGetSymbolAddress((void**)&p_b01, g_b01);
    cudaGetSymbolAddress((void**)&p_xah, g_xah);
    cudaGetSymbolAddress((void**)&p_xal, g_xal);
    cudaGetSymbolAddress((void**)&p_xph, g_xph);
    cudaGetSymbolAddress((void**)&p_xpl, g_xpl);
    cudaGetSymbolAddress((void**)&p_hah, g_hah);
    cudaGetSymbolAddress((void**)&p_hal, g_hal);
    cudaGetSymbolAddress((void**)&p_hph, g_hph);
    cudaGetSymbolAddress((void**)&p_hpl, g_hpl);
    cudaGetSymbolAddress((void**)&p_ag0h, g_ag0h);
    cudaGetSymbolAddress((void**)&p_ag0l, g_ag0l);
    cudaGetSymbolAddress((void**)&p_ag1h, g_ag1h);
    cudaGetSymbolAddress((void**)&p_ag1l, g_ag1l);
    cudaGetSymbolAddress((void**)&p_wh, g_wh);
    cudaGetSymbolAddress((void**)&p_wl, g_wl);
    cudaGetSymbolAddress((void**)&p_deg, g_deg);
    cudaGetSymbolAddress((void**)&p_off, g_off);
    cudaGetSymbolAddress((void**)&p_cur, g_cur);
    cudaGetSymbolAddress((void**)&p_perm, g_perm);
    cudaGetSymbolAddress((void**)&p_part, g_part);

    // ---- all input/weight/bias splits in ONE launch ----
    k_split_all<<<(NSPLIT_TOT + 255) / 256, 256>>>(
        x_author, x_paper, emb_W_author, emb_W_paper, W_self, W_neigh,
        pW1_author, pW1_paper, pW2_paper, b_conv,
        p_wh, p_wl, p_xah, p_xal, p_xph, p_xpl, p_b01);

    // ---- CSR build: zero, hist, 3-phase scan, fill ----
    k_zero3<<<(3 * PN + 255) / 256, 256>>>(p_deg);
    k_hist3<<<(3 * EN + 255) / 256, 256>>>(e0_dst, e1_dst, e2_dst, p_deg);
    k_scan_sum<<<NBT, 1024>>>(p_deg, p_part);
    k_scan_top<<<1, 32>>>(p_part, p_off);
    k_scan_apply<<<NBT, 1024>>>(p_deg, p_part, p_off, p_cur);
    k_fill3<<<(3 * EN + 255) / 256, 256>>>(e0_src, e0_dst, e1_src, e1_dst,
                                           e2_src, e2_dst, p_cur, p_perm);

    // ---- embeddings (fp32 h + split h) ----
    bgemm(p_xah, p_xal, 0, 0, 0, 0, p_wh + WOFF_EMBA, p_wl + WOFF_EMBA,
          emb_b_author, p_ha, p_hah, p_hal, AN, HD, DIN, DIN, 0);
    bgemm(p_xph, p_xpl, 0, 0, 0, 0, p_wh + WOFF_EMBP, p_wl + WOFF_EMBP,
          emb_b_paper, p_hp, p_hph, p_hpl, PN, HD, DIN, DIN, 0);

    // ---- 2 SAGE layers ----
    const int WPO[2] = {WOFF_WP0, WOFF_WP1};
    const int WAO[2] = {WOFF_WA0, WOFF_WA1};
    const int AGG_BLK = 128;
    for (int l = 0; l < 2; ++l) {
        const float* bc = b_conv + (size_t)l * 3 * HD;
        k_agg<<<(PN * 32 + AGG_BLK - 1) / AGG_BLK, AGG_BLK>>>(
            p_ha, p_off + 0 * (PN + 1), p_perm + 0 * EN, p_ag0h, p_ag0l, PN);
        k_agg<<<(PN * 32 + AGG_BLK - 1) / AGG_BLK, AGG_BLK>>>(
            p_hp, p_off + 1 * (PN + 1), p_perm + 1 * EN, p_ag1h, p_ag1l, PN);
        bgemm(p_hph, p_hpl, p_ag0h, p_ag0l, p_ag1h, p_ag1l,
              p_wh + WPO[l], p_wl + WPO[l], p_b01 + l * HD,
              p_tp, 0, 0, PN, HD, 3 * HD, HD, 0);
        k_agg<<<(AN * 32 + AGG_BLK - 1) / AGG_BLK, AGG_BLK>>>(
            p_hp, p_off + 2 * (PN + 1), p_perm + 2 * EN, p_ag0h, p_ag0l, AN);
        bgemm(p_hah, p_hal, p_ag0h, p_ag0l, 0, 0,
              p_wh + WAO[l], p_wl + WAO[l], bc + 2 * HD,
              p_ta, 0, 0, AN, HD, 2 * HD, HD, 0);
        k_ln<<<(AN * 32 + 127) / 128, 128>>>(p_ta, p_ha, p_hah, p_hal,
                                             ln_g_author, ln_b_author, AN);
        k_ln<<<(PN * 32 + 127) / 128, 128>>>(p_tp, p_hp, p_hph, p_hpl,
                                             ln_g_paper, ln_b_paper, PN);
    }

    // ---- output heads ----
    float* out = (float*)d_out;
    bgemm(p_hah, p_hal, 0, 0, 0, 0, p_wh + WOFF_P1A, p_wl + WOFF_P1A,
          pb1_author, p_ta, 0, 0, AN, HD, HD, HD, 1);
    {
        dim3 grid((CN + BN - 1) / BN, (AN + BM - 1) / BM);
        k_sgemm<<<grid, 256>>>(p_ta, pW2_author, pb2_author, out, AN, CN, HD);
    }
    k_lsm<<<(AN * 32 + 127) / 128, 128>>>(out, AN);
    bgemm(p_hph, p_hpl, 0, 0, 0, 0, p_wh + WOFF_P1P, p_wl + WOFF_P1P,
          pb1_paper, 0, p_ag0h, p_ag0l, PN, HD, HD, HD, 1);
    bgemm(p_ag0h, p_ag0l, 0, 0, 0, 0, p_wh + WOFF_P2P, p_wl + WOFF_P2P,
          pb2_paper, out + (size_t)AN * CN, 0, 0, PN, HD, HD, HD, 0);
}